// round 1
// baseline (speedup 1.0000x reference)
#include <cuda_runtime.h>
#include <cuda_bf16.h>

#define BB   4
#define CC   256
#define NN   4096          // H*W = 64*64
#define GG   8
#define NH   8
#define HD   32
#define MSEQ 512           // N / G
#define OC3  768           // 3*C

// Scratch (allocation-free rule: __device__ globals)
__device__ float g_qkv[(size_t)BB * NN * OC3];   // ~50.3 MB  [b][n][3*C]
__device__ float g_att[(size_t)BB * NN * CC];    // ~16.8 MB  [b][n][C]

// ---------------------------------------------------------------------------
// Kernel 1: QKV projection.  qkv[b,n,oc] = sum_c x[b,c,n] * w_qkv[oc,c]
// x layout [B,C,N] -> reading along n is coalesced. 64x64 tile, 4x4 microtile.
// ---------------------------------------------------------------------------
__global__ __launch_bounds__(256) void qkv_gemm_kernel(const float* __restrict__ x,
                                                       const float* __restrict__ w) {
    __shared__ float As[16][65];   // As[kk][mm] : x tile
    __shared__ float Bs[16][65];   // Bs[kk][jj] : w tile
    const int b  = blockIdx.z;
    const int m0 = blockIdx.x * 64;
    const int j0 = blockIdx.y * 64;
    const float* xb = x + (size_t)b * CC * NN;
    const int t  = threadIdx.x;
    const int tx = t & 15, ty = t >> 4;
    float acc[4][4] = {};

    for (int k0 = 0; k0 < CC; k0 += 16) {
#pragma unroll
        for (int p = 0; p < 4; p++) {
            int i  = t + p * 256;
            int kk = i >> 6, mm = i & 63;
            As[kk][mm] = xb[(size_t)(k0 + kk) * NN + m0 + mm];      // coalesced over mm
            int jj = i >> 4, k2 = i & 15;
            Bs[k2][jj] = w[(size_t)(j0 + jj) * CC + k0 + k2];       // coalesced over k2
        }
        __syncthreads();
#pragma unroll
        for (int kk = 0; kk < 16; kk++) {
            float a[4], bv[4];
#pragma unroll
            for (int i = 0; i < 4; i++) a[i]  = As[kk][tx * 4 + i];
#pragma unroll
            for (int j = 0; j < 4; j++) bv[j] = Bs[kk][ty * 4 + j];
#pragma unroll
            for (int i = 0; i < 4; i++)
#pragma unroll
                for (int j = 0; j < 4; j++)
                    acc[i][j] += a[i] * bv[j];
        }
        __syncthreads();
    }

    float* op = g_qkv + (size_t)b * NN * OC3;
#pragma unroll
    for (int i = 0; i < 4; i++)
#pragma unroll
        for (int j = 0; j < 4; j++)
            op[(size_t)(m0 + tx * 4 + i) * OC3 + j0 + ty * 4 + j] = acc[i][j];
}

// ---------------------------------------------------------------------------
// Kernel 2: grouped MHA. One block = (one head, 128 query rows).
// Each thread owns one query row: q[32], o[32] in registers, online softmax.
// K/V streamed via smem in 128-key tiles.
// qkv layout per (b,n): [3, nh, hd] -> q at +h*32, k at +256+h*32, v at +512+h*32
// n = g*512 + m  (N reshaped [G, M] contiguously)
// ---------------------------------------------------------------------------
__global__ __launch_bounds__(128) void attn_kernel() {
    __shared__ float Ks[128][36];   // 36 keeps float4 stores 16B-aligned
    __shared__ float Vs[128][36];
    const int head = blockIdx.y;                 // 0..255
    const int b = head >> 6;
    const int g = (head >> 3) & 7;
    const int h = head & 7;
    const int m = blockIdx.x * 128 + threadIdx.x;    // query row in [0,512)
    const float* base = g_qkv + ((size_t)b * NN + (size_t)g * MSEQ) * OC3;
    const float scale = 0.17677669529663687f;        // 1/sqrt(32)
    const int t = threadIdx.x;

    float q[HD];
    {
        const float* qp = base + (size_t)m * OC3 + h * HD;
#pragma unroll
        for (int d = 0; d < HD; d += 4) {
            float4 v = *reinterpret_cast<const float4*>(qp + d);
            q[d] = v.x; q[d + 1] = v.y; q[d + 2] = v.z; q[d + 3] = v.w;
        }
    }
    float o[HD];
#pragma unroll
    for (int d = 0; d < HD; d++) o[d] = 0.f;
    float mx = -1e30f, l = 0.f;

    for (int kt = 0; kt < MSEQ; kt += 128) {
        __syncthreads();                          // protect smem reuse
        // load 128x32 K and V tiles, float4, coalesced
#pragma unroll
        for (int p = 0; p < 8; p++) {
            int i   = t + p * 128;
            int row = i >> 3;
            int c4  = (i & 7) * 4;
            const float* kp = base + (size_t)(kt + row) * OC3 + CC + h * HD + c4;
            *reinterpret_cast<float4*>(&Ks[row][c4]) = *reinterpret_cast<const float4*>(kp);
            *reinterpret_cast<float4*>(&Vs[row][c4]) = *reinterpret_cast<const float4*>(kp + CC);
        }
        __syncthreads();

        for (int j = 0; j < 128; j++) {
            float s = 0.f;
#pragma unroll
            for (int d = 0; d < HD; d++) s += q[d] * Ks[j][d];   // broadcast reads
            s *= scale;
            if (s <= mx) {
                float p = __expf(s - mx);
                l += p;
#pragma unroll
                for (int d = 0; d < HD; d++) o[d] += p * Vs[j][d];
            } else {                               // rare: new max -> rescale
                float corr = __expf(mx - s);
                mx = s;
                l = l * corr + 1.f;
#pragma unroll
                for (int d = 0; d < HD; d++) o[d] = o[d] * corr + Vs[j][d];
            }
        }
    }

    const float inv = 1.f / l;
    float* ap = g_att + ((size_t)b * NN + (size_t)g * MSEQ + m) * CC + h * HD;
#pragma unroll
    for (int d = 0; d < HD; d += 4) {
        float4 v;
        v.x = o[d] * inv; v.y = o[d + 1] * inv;
        v.z = o[d + 2] * inv; v.w = o[d + 3] * inv;
        *reinterpret_cast<float4*>(ap + d) = v;
    }
}

// ---------------------------------------------------------------------------
// Kernel 3: output projection + bias + final transpose to [B,C,N].
// out[b,c',n] = sum_c att[b,n,c] * w_proj[c',c] + b_proj[c']
// ---------------------------------------------------------------------------
__global__ __launch_bounds__(256) void proj_gemm_kernel(const float* __restrict__ w,
                                                        const float* __restrict__ bias,
                                                        float* __restrict__ out) {
    __shared__ float As[64][17];   // As[mm][kk] : att tile (k contiguous in gmem)
    __shared__ float Bs[16][65];   // Bs[kk][jj] : w tile
    const int b  = blockIdx.z;
    const int m0 = blockIdx.x * 64;
    const int j0 = blockIdx.y * 64;
    const float* ab = g_att + (size_t)b * NN * CC;
    const int t  = threadIdx.x;
    const int tx = t & 15, ty = t >> 4;
    float acc[4][4] = {};

    for (int k0 = 0; k0 < CC; k0 += 16) {
#pragma unroll
        for (int p = 0; p < 4; p++) {
            int i  = t + p * 256;
            int mm = i >> 4, kk = i & 15;
            As[mm][kk] = ab[(size_t)(m0 + mm) * CC + k0 + kk];     // coalesced over kk
            int jj = i >> 4, k2 = i & 15;
            Bs[k2][jj] = w[(size_t)(j0 + jj) * CC + k0 + k2];
        }
        __syncthreads();
#pragma unroll
        for (int kk = 0; kk < 16; kk++) {
            float a[4], bv[4];
#pragma unroll
            for (int i = 0; i < 4; i++) a[i]  = As[tx * 4 + i][kk];
#pragma unroll
            for (int j = 0; j < 4; j++) bv[j] = Bs[kk][ty * 4 + j];
#pragma unroll
            for (int i = 0; i < 4; i++)
#pragma unroll
                for (int j = 0; j < 4; j++)
                    acc[i][j] += a[i] * bv[j];
        }
        __syncthreads();
    }

#pragma unroll
    for (int j = 0; j < 4; j++) {
        float bj = bias[j0 + ty * 4 + j];
#pragma unroll
        for (int i = 0; i < 4; i++)
            out[((size_t)b * CC + j0 + ty * 4 + j) * NN + m0 + tx * 4 + i] = acc[i][j] + bj;
    }
}

// ---------------------------------------------------------------------------
extern "C" void kernel_launch(void* const* d_in, const int* in_sizes, int n_in,
                              void* d_out, int out_size) {
    const float* x      = (const float*)d_in[0];   // [B,C,H,W] = [B,C,N]
    const float* w_qkv  = (const float*)d_in[1];   // [768,256]
    const float* w_proj = (const float*)d_in[2];   // [256,256]
    const float* b_proj = (const float*)d_in[3];   // [256]
    float* out = (float*)d_out;                    // [B,C,N]

    dim3 g1(NN / 64, OC3 / 64, BB);
    qkv_gemm_kernel<<<g1, 256>>>(x, w_qkv);

    dim3 g2(MSEQ / 128, BB * GG * NH);
    attn_kernel<<<g2, 128>>>();

    dim3 g3(NN / 64, CC / 64, BB);
    proj_gemm_kernel<<<g3, 256>>>(w_proj, b_proj, out);
}

// round 2
// speedup vs baseline: 1.1857x; 1.1857x over previous
#include <cuda_runtime.h>
#include <cuda_bf16.h>

#define BB   4
#define CC   256
#define NN   4096          // H*W
#define GG   8
#define NH   8
#define HD   32
#define MSEQ 512
#define OC3  768

typedef unsigned long long u64;

__device__ __forceinline__ u64 pack2(float lo, float hi) {
    u64 r; asm("mov.b64 %0,{%1,%2};" : "=l"(r) : "f"(lo), "f"(hi)); return r;
}
__device__ __forceinline__ float2 unpk2(u64 v) {
    float2 f; asm("mov.b64 {%0,%1},%2;" : "=f"(f.x), "=f"(f.y) : "l"(v)); return f;
}
__device__ __forceinline__ u64 fma2(u64 a, u64 b, u64 c) {
    u64 d; asm("fma.rn.f32x2 %0,%1,%2,%3;" : "=l"(d) : "l"(a), "l"(b), "l"(c)); return d;
}

// Scratch (allocation-free rule: __device__ globals)
__device__ __align__(128) float g_qkv[(size_t)BB * NN * OC3];   // [b][n][3*C]
__device__ __align__(128) float g_att[(size_t)BB * NN * CC];    // [b][n][C]

// ---------------------------------------------------------------------------
// Kernel 1: qkv[b,n,oc] = sum_c x[b,c,n] * w_qkv[oc,c]
// 128x128 tile, 8x8 microtile, f32x2 packed along M; B duplicated in smem.
// ---------------------------------------------------------------------------
__global__ __launch_bounds__(256) void qkv_gemm_kernel(const float* __restrict__ x,
                                                       const float* __restrict__ w) {
    __shared__ float As[8][132];    // As[kk][mm], rows 528B (16B-mult)
    __shared__ u64   Bsd[8][128];   // Bsd[kk][jj] = (w, w) duplicated

    const int b  = blockIdx.z;
    const int m0 = blockIdx.x * 128;
    const int j0 = blockIdx.y * 128;
    const float* xb = x + (size_t)b * CC * NN;
    const int t  = threadIdx.x;
    const int tx = t & 15;          // M micro: rows tx*8..tx*8+7
    const int ty = t >> 4;          // N micro: cols ty*8..ty*8+7

    u64 acc[4][8];
#pragma unroll
    for (int i = 0; i < 4; i++)
#pragma unroll
        for (int j = 0; j < 8; j++) acc[i][j] = 0ull;

    const int a_kk  = t >> 5;             // 0..7
    const int a_mm4 = (t & 31) * 4;       // 0..124
    const int b_jj  = t >> 1;             // 0..127
    const int b_kk4 = (t & 1) * 4;        // 0 or 4

    for (int k0 = 0; k0 < CC; k0 += 8) {
        // fill As (coalesced along n)
        {
            float4 v = *reinterpret_cast<const float4*>(xb + (size_t)(k0 + a_kk) * NN + m0 + a_mm4);
            *reinterpret_cast<float4*>(&As[a_kk][a_mm4]) = v;
        }
        // fill Bsd (coalesced along k), duplicate each value into a pair
        {
            float4 v = *reinterpret_cast<const float4*>(w + (size_t)(j0 + b_jj) * CC + k0 + b_kk4);
            Bsd[b_kk4 + 0][b_jj] = pack2(v.x, v.x);
            Bsd[b_kk4 + 1][b_jj] = pack2(v.y, v.y);
            Bsd[b_kk4 + 2][b_jj] = pack2(v.z, v.z);
            Bsd[b_kk4 + 3][b_jj] = pack2(v.w, v.w);
        }
        __syncthreads();
#pragma unroll
        for (int kk = 0; kk < 8; kk++) {
            u64 a[4], bv[8];
            const u64* ar = reinterpret_cast<const u64*>(&As[kk][tx * 8]);
#pragma unroll
            for (int i = 0; i < 4; i++) a[i] = ar[i];
            const u64* br = &Bsd[kk][ty * 8];
#pragma unroll
            for (int j = 0; j < 8; j++) bv[j] = br[j];
#pragma unroll
            for (int i = 0; i < 4; i++)
#pragma unroll
                for (int j = 0; j < 8; j++)
                    acc[i][j] = fma2(a[i], bv[j], acc[i][j]);
        }
        __syncthreads();
    }

    float* op = g_qkv + (size_t)b * NN * OC3;
#pragma unroll
    for (int i2 = 0; i2 < 4; i2++) {
        float r0[8], r1[8];
#pragma unroll
        for (int j = 0; j < 8; j++) {
            float2 p = unpk2(acc[i2][j]);
            r0[j] = p.x; r1[j] = p.y;
        }
        size_t base0 = (size_t)(m0 + tx * 8 + 2 * i2) * OC3 + j0 + ty * 8;
        *reinterpret_cast<float4*>(op + base0)           = make_float4(r0[0], r0[1], r0[2], r0[3]);
        *reinterpret_cast<float4*>(op + base0 + 4)       = make_float4(r0[4], r0[5], r0[6], r0[7]);
        *reinterpret_cast<float4*>(op + base0 + OC3)     = make_float4(r1[0], r1[1], r1[2], r1[3]);
        *reinterpret_cast<float4*>(op + base0 + OC3 + 4) = make_float4(r1[4], r1[5], r1[6], r1[7]);
    }
}

// ---------------------------------------------------------------------------
// Kernel 2: grouped MHA, f32x2 packed. One block = (head, 128 query rows);
// thread = one query row (q/o packed in u64 registers, K/V tiles in smem).
// ---------------------------------------------------------------------------
__global__ __launch_bounds__(128) void attn_kernel() {
    __shared__ float Ks[128][36];   // rows 144B: u64/128b aligned
    __shared__ float Vs[128][36];
    const int head = blockIdx.y;
    const int b = head >> 6;
    const int g = (head >> 3) & 7;
    const int h = head & 7;
    const int m = blockIdx.x * 128 + threadIdx.x;
    const float* base = g_qkv + ((size_t)b * NN + (size_t)g * MSEQ) * OC3;
    const float scale = 0.17677669529663687f;   // 1/sqrt(32)
    const int t = threadIdx.x;

    u64 q2[16];
    {
        const u64* qp = reinterpret_cast<const u64*>(base + (size_t)m * OC3 + h * HD);
#pragma unroll
        for (int d = 0; d < 16; d++) q2[d] = qp[d];
    }
    u64 o2[16];
#pragma unroll
    for (int d = 0; d < 16; d++) o2[d] = 0ull;
    float mx = -1e30f, l = 0.f;

    for (int kt = 0; kt < MSEQ; kt += 128) {
        __syncthreads();
#pragma unroll
        for (int p = 0; p < 8; p++) {
            int i   = t + p * 128;
            int row = i >> 3;
            int c4  = (i & 7) * 4;
            const float* kp = base + (size_t)(kt + row) * OC3 + CC + h * HD + c4;
            *reinterpret_cast<float4*>(&Ks[row][c4]) = *reinterpret_cast<const float4*>(kp);
            *reinterpret_cast<float4*>(&Vs[row][c4]) = *reinterpret_cast<const float4*>(kp + CC);
        }
        __syncthreads();

        for (int j = 0; j < 128; j++) {
            const u64* kr = reinterpret_cast<const u64*>(&Ks[j][0]);
            u64 s2 = 0ull;
#pragma unroll
            for (int d = 0; d < 16; d++) s2 = fma2(q2[d], kr[d], s2);
            float2 sf = unpk2(s2);
            float s = (sf.x + sf.y) * scale;

            const u64* vr = reinterpret_cast<const u64*>(&Vs[j][0]);
            if (s <= mx) {
                float p = __expf(s - mx);
                l += p;
                u64 pd = pack2(p, p);
#pragma unroll
                for (int d = 0; d < 16; d++) o2[d] = fma2(pd, vr[d], o2[d]);
            } else {                               // rare: new max
                float corr = __expf(mx - s);
                mx = s;
                l = l * corr + 1.f;
                u64 cd = pack2(corr, corr);
#pragma unroll
                for (int d = 0; d < 16; d++) o2[d] = fma2(o2[d], cd, vr[d]);
            }
        }
    }

    const float inv = 1.f / l;
    float* ap = g_att + ((size_t)b * NN + (size_t)g * MSEQ + m) * CC + h * HD;
#pragma unroll
    for (int d = 0; d < 16; d += 2) {
        float2 p0 = unpk2(o2[d]), p1 = unpk2(o2[d + 1]);
        *reinterpret_cast<float4*>(ap + 2 * d) =
            make_float4(p0.x * inv, p0.y * inv, p1.x * inv, p1.y * inv);
    }
}

// ---------------------------------------------------------------------------
// Kernel 3: out[b,c',n] = sum_c att[b,n,c] * w_proj[c',c] + b_proj[c']
// Same f32x2 structure; A fill is a smem transpose (gmem k-contiguous).
// ---------------------------------------------------------------------------
__global__ __launch_bounds__(256) void proj_gemm_kernel(const float* __restrict__ w,
                                                        const float* __restrict__ bias,
                                                        float* __restrict__ out) {
    __shared__ float As[8][132];
    __shared__ u64   Bsd[8][128];

    const int b  = blockIdx.z;
    const int m0 = blockIdx.x * 128;
    const int j0 = blockIdx.y * 128;
    const float* ab = g_att + (size_t)b * NN * CC;
    const int t  = threadIdx.x;
    const int tx = t & 15;
    const int ty = t >> 4;

    u64 acc[4][8];
#pragma unroll
    for (int i = 0; i < 4; i++)
#pragma unroll
        for (int j = 0; j < 8; j++) acc[i][j] = 0ull;

    const int a_mm  = t >> 1;         // 0..127
    const int a_kk4 = (t & 1) * 4;
    const int b_jj  = t >> 1;
    const int b_kk4 = (t & 1) * 4;

    for (int k0 = 0; k0 < CC; k0 += 8) {
        {
            float4 v = *reinterpret_cast<const float4*>(ab + (size_t)(m0 + a_mm) * CC + k0 + a_kk4);
            As[a_kk4 + 0][a_mm] = v.x;
            As[a_kk4 + 1][a_mm] = v.y;
            As[a_kk4 + 2][a_mm] = v.z;
            As[a_kk4 + 3][a_mm] = v.w;
        }
        {
            float4 v = *reinterpret_cast<const float4*>(w + (size_t)(j0 + b_jj) * CC + k0 + b_kk4);
            Bsd[b_kk4 + 0][b_jj] = pack2(v.x, v.x);
            Bsd[b_kk4 + 1][b_jj] = pack2(v.y, v.y);
            Bsd[b_kk4 + 2][b_jj] = pack2(v.z, v.z);
            Bsd[b_kk4 + 3][b_jj] = pack2(v.w, v.w);
        }
        __syncthreads();
#pragma unroll
        for (int kk = 0; kk < 8; kk++) {
            u64 a[4], bv[8];
            const u64* ar = reinterpret_cast<const u64*>(&As[kk][tx * 8]);
#pragma unroll
            for (int i = 0; i < 4; i++) a[i] = ar[i];
            const u64* br = &Bsd[kk][ty * 8];
#pragma unroll
            for (int j = 0; j < 8; j++) bv[j] = br[j];
#pragma unroll
            for (int i = 0; i < 4; i++)
#pragma unroll
                for (int j = 0; j < 8; j++)
                    acc[i][j] = fma2(a[i], bv[j], acc[i][j]);
        }
        __syncthreads();
    }

    // epilogue: transpose to [C, N] layout + bias
#pragma unroll
    for (int j = 0; j < 8; j++) {
        int col = j0 + ty * 8 + j;
        float bj = bias[col];
        float f[8];
#pragma unroll
        for (int i2 = 0; i2 < 4; i2++) {
            float2 p = unpk2(acc[i2][j]);
            f[2 * i2] = p.x + bj; f[2 * i2 + 1] = p.y + bj;
        }
        size_t base0 = ((size_t)b * CC + col) * NN + m0 + tx * 8;
        *reinterpret_cast<float4*>(out + base0)     = make_float4(f[0], f[1], f[2], f[3]);
        *reinterpret_cast<float4*>(out + base0 + 4) = make_float4(f[4], f[5], f[6], f[7]);
    }
}

// ---------------------------------------------------------------------------
extern "C" void kernel_launch(void* const* d_in, const int* in_sizes, int n_in,
                              void* d_out, int out_size) {
    const float* x      = (const float*)d_in[0];   // [B,C,N]
    const float* w_qkv  = (const float*)d_in[1];   // [768,256]
    const float* w_proj = (const float*)d_in[2];   // [256,256]
    const float* b_proj = (const float*)d_in[3];   // [256]
    float* out = (float*)d_out;                    // [B,C,N]

    dim3 g1(NN / 128, OC3 / 128, BB);
    qkv_gemm_kernel<<<g1, 256>>>(x, w_qkv);

    dim3 g2(MSEQ / 128, BB * GG * NH);
    attn_kernel<<<g2, 128>>>();

    dim3 g3(NN / 128, CC / 128, BB);
    proj_gemm_kernel<<<g3, 256>>>(w_proj, b_proj, out);
}

// round 4
// speedup vs baseline: 1.4394x; 1.2140x over previous
#include <cuda_runtime.h>
#include <cuda_bf16.h>

#define BB   4
#define CC   256
#define NN   4096
#define GG   8
#define NH   8
#define HD   32
#define MSEQ 512
#define OC3  768

typedef unsigned long long u64;
typedef unsigned int u32;

// ---------------------------------------------------------------- helpers
__device__ __forceinline__ u64 pack2(float lo, float hi) {
    u64 r; asm("mov.b64 %0,{%1,%2};" : "=l"(r) : "f"(lo), "f"(hi)); return r;
}
__device__ __forceinline__ float2 unpk2(u64 v) {
    float2 f; asm("mov.b64 {%0,%1},%2;" : "=f"(f.x), "=f"(f.y) : "l"(v)); return f;
}
__device__ __forceinline__ u64 fma2(u64 a, u64 b, u64 c) {
    u64 d; asm("fma.rn.f32x2 %0,%1,%2,%3;" : "=l"(d) : "l"(a), "l"(b), "l"(c)); return d;
}
__device__ __forceinline__ u32 smem_u32(const void* p) {
    u32 a; asm("{.reg .u64 t; cvta.to.shared.u64 t,%1; cvt.u32.u64 %0,t;}" : "=r"(a) : "l"(p));
    return a;
}
__device__ __forceinline__ void ldsm4(u32* r, u32 addr) {
    asm volatile("ldmatrix.sync.aligned.m8n8.x4.shared.b16 {%0,%1,%2,%3},[%4];"
                 : "=r"(r[0]), "=r"(r[1]), "=r"(r[2]), "=r"(r[3]) : "r"(addr));
}
__device__ __forceinline__ void ldsm4t(u32* r, u32 addr) {
    asm volatile("ldmatrix.sync.aligned.m8n8.x4.trans.shared.b16 {%0,%1,%2,%3},[%4];"
                 : "=r"(r[0]), "=r"(r[1]), "=r"(r[2]), "=r"(r[3]) : "r"(addr));
}
__device__ __forceinline__ void mma16816(float* d, const u32* a, const u32* b) {
    asm volatile("mma.sync.aligned.m16n8k16.row.col.f32.bf16.bf16.f32 "
                 "{%0,%1,%2,%3},{%4,%5,%6,%7},{%8,%9},{%0,%1,%2,%3};"
                 : "+f"(d[0]), "+f"(d[1]), "+f"(d[2]), "+f"(d[3])
                 : "r"(a[0]), "r"(a[1]), "r"(a[2]), "r"(a[3]), "r"(b[0]), "r"(b[1]));
}
__device__ __forceinline__ void split_bf16(float x, __nv_bfloat16& h, __nv_bfloat16& l) {
    h = __float2bfloat16(x);
    l = __float2bfloat16(x - __bfloat162float(h));
}

// smem tiles: A (weights) [128 m][64 k] bf16, 128B rows, XOR swizzle on 16B chunks
__device__ __forceinline__ u32 a_off(int m, int k) {
    int chunk = (k >> 3) ^ (m & 7);
    return m * 128 + (chunk << 4) + ((k * 2) & 15);
}
// B (activations) [64 k][128 n] bf16, 256B rows, XOR swizzle
__device__ __forceinline__ u32 b_off(int k, int n) {
    int chunk = (n >> 3) ^ (k & 7);
    return k * 256 + (chunk << 4) + ((n * 2) & 15);
}
__device__ __forceinline__ void st_bf2(char* base, u32 off, __nv_bfloat16 a, __nv_bfloat16 b) {
    __nv_bfloat162 t; t.x = a; t.y = b;
    *reinterpret_cast<__nv_bfloat162*>(base + off) = t;
}

#define AHI 0
#define ALO 16384
#define BHI 32768
#define BLO 49152
#define SMEM_GEMM 65536

// Scratch (allocation-free rule) — channel-major: [b][oc][n]
__device__ __align__(128) float g_qkv[(size_t)BB * OC3 * NN];
__device__ __align__(128) float g_att[(size_t)BB * CC * NN];

// ---------------------------------------------------------------------------
// GEMM core:  out[m][n] = sum_k A[m][k] * B[k][n]   (split-bf16, HMMA)
// A: weights row-major [M][K] in gmem.  B: activations [K][n] (k rows).
// Block tile 128x128, 8 warps (4 m x 2 n), K chunks of 64.
// ---------------------------------------------------------------------------
template<int KDIM, bool ADD_BIAS>
__device__ __forceinline__ void gemm_body(const float* __restrict__ A,
                                          const float* __restrict__ Brow,   // + k*ldb + n0
                                          size_t ldb,
                                          const float* __restrict__ bias,
                                          float* __restrict__ outp,         // + oc*ldo + n0
                                          size_t ldo,
                                          int m0, char* smem) {
    const u32 sb = smem_u32(smem);
    const int t = threadIdx.x;
    const int wid = t >> 5, lane = t & 31;
    const int wm = (wid & 3) * 32;          // warp m offset
    const int wn = (wid >> 2) * 64;         // warp n offset

    float acc[2][8][4];
#pragma unroll
    for (int i = 0; i < 2; i++)
#pragma unroll
        for (int j = 0; j < 8; j++)
#pragma unroll
            for (int c = 0; c < 4; c++) acc[i][j][c] = 0.f;

    for (int c0 = 0; c0 < KDIM; c0 += 64) {
        // ---- fill A chunk: [128 m][64 k]
        {
            int mm = t >> 1, half = t & 1;
            const float* src = A + (size_t)(m0 + mm) * KDIM + c0 + half * 32;
            char* ah = smem + AHI;
            char* al = smem + ALO;
#pragma unroll
            for (int i = 0; i < 8; i++) {
                float4 v = *reinterpret_cast<const float4*>(src + i * 4);
                int k = half * 32 + i * 4;
                __nv_bfloat16 h0, l0, h1, l1, h2, l2, h3, l3;
                split_bf16(v.x, h0, l0); split_bf16(v.y, h1, l1);
                split_bf16(v.z, h2, l2); split_bf16(v.w, h3, l3);
                st_bf2(ah, a_off(mm, k), h0, h1);   st_bf2(ah, a_off(mm, k + 2), h2, h3);
                st_bf2(al, a_off(mm, k), l0, l1);   st_bf2(al, a_off(mm, k + 2), l2, l3);
            }
        }
        // ---- fill B chunk: [64 k][128 n]
        {
            int kk = t >> 2, q = t & 3;
            const float* src = Brow + (size_t)(c0 + kk) * ldb + q * 32;
            char* bh = smem + BHI;
            char* bl = smem + BLO;
#pragma unroll
            for (int i = 0; i < 8; i++) {
                float4 v = *reinterpret_cast<const float4*>(src + i * 4);
                int n = q * 32 + i * 4;
                __nv_bfloat16 h0, l0, h1, l1, h2, l2, h3, l3;
                split_bf16(v.x, h0, l0); split_bf16(v.y, h1, l1);
                split_bf16(v.z, h2, l2); split_bf16(v.w, h3, l3);
                st_bf2(bh, b_off(kk, n), h0, h1);   st_bf2(bh, b_off(kk, n + 2), h2, h3);
                st_bf2(bl, b_off(kk, n), l0, l1);   st_bf2(bl, b_off(kk, n + 2), l2, l3);
            }
        }
        __syncthreads();

#pragma unroll
        for (int ks = 0; ks < 4; ks++) {
            // A fragments for 2 m-tiles, hi+lo
            u32 ah[2][4], al[2][4];
#pragma unroll
            for (int i = 0; i < 2; i++) {
                int row = wm + i * 16 + (lane & 15);
                int kc  = ks * 16 + (lane >> 4) * 8;
                u32 ao = row * 128 + ((((kc >> 3) ^ (row & 7))) << 4);
                ldsm4(ah[i], sb + AHI + ao);
                ldsm4(al[i], sb + ALO + ao);
            }
#pragma unroll
            for (int nh = 0; nh < 2; nh++) {
                u32 bh[2][4], bl[2][4];
#pragma unroll
                for (int pp = 0; pp < 2; pp++) {
                    int k = ks * 16 + ((lane >> 3) & 1) * 8 + (lane & 7);
                    int nb = wn + nh * 32 + pp * 16 + (lane >> 4) * 8;
                    u32 bo = k * 256 + ((((nb >> 3) ^ (k & 7))) << 4);
                    ldsm4t(bh[pp], sb + BHI + bo);
                    ldsm4t(bl[pp], sb + BLO + bo);
                }
#pragma unroll
                for (int i = 0; i < 2; i++)
#pragma unroll
                    for (int pp = 0; pp < 2; pp++)
#pragma unroll
                        for (int s = 0; s < 2; s++) {
                            int nt = nh * 4 + pp * 2 + s;
                            mma16816(acc[i][nt], ah[i], bh[pp] + s * 2);
                            mma16816(acc[i][nt], ah[i], bl[pp] + s * 2);
                            mma16816(acc[i][nt], al[i], bh[pp] + s * 2);
                        }
            }
        }
        __syncthreads();
    }

    // ---- epilogue: direct stores, out[oc][n], float2 per fragment row
#pragma unroll
    for (int i = 0; i < 2; i++) {
        int r0 = wm + i * 16 + (lane >> 2);
        float b0 = 0.f, b8 = 0.f;
        if (ADD_BIAS) { b0 = bias[m0 + r0]; b8 = bias[m0 + r0 + 8]; }
#pragma unroll
        for (int nt = 0; nt < 8; nt++) {
            int n = wn + nt * 8 + (lane & 3) * 2;
            float* d0 = outp + (size_t)r0 * ldo + n;
            *reinterpret_cast<float2*>(d0) =
                make_float2(acc[i][nt][0] + b0, acc[i][nt][1] + b0);
            *reinterpret_cast<float2*>(d0 + 8 * ldo) =
                make_float2(acc[i][nt][2] + b8, acc[i][nt][3] + b8);
        }
    }
}

// Kernel 1: g_qkv[b][oc][n] = sum_c w_qkv[oc][c] * x[b][c][n]
__global__ __launch_bounds__(256) void qkv_gemm_kernel(const float* __restrict__ x,
                                                       const float* __restrict__ w) {
    extern __shared__ char smem[];
    const int b = blockIdx.z;
    const int n0 = blockIdx.x * 128;
    const int m0 = blockIdx.y * 128;
    gemm_body<CC, false>(w, x + (size_t)b * CC * NN + n0, NN, nullptr,
                         g_qkv + ((size_t)b * OC3 + m0) * NN + n0, NN, m0, smem);
}

// Kernel 3: out[b][c'][n] = sum_c w_proj[c'][c] * g_att[b][c][n] + bias[c']
__global__ __launch_bounds__(256) void proj_gemm_kernel(const float* __restrict__ w,
                                                        const float* __restrict__ bias,
                                                        float* __restrict__ out) {
    extern __shared__ char smem[];
    const int b = blockIdx.z;
    const int n0 = blockIdx.x * 128;
    const int m0 = blockIdx.y * 128;
    gemm_body<CC, true>(w, g_att + (size_t)b * CC * NN + n0, NN, bias,
                        out + ((size_t)b * CC + m0) * NN + n0, NN, m0, smem);
}

// ---------------------------------------------------------------------------
// Kernel 2: grouped MHA on channel-major qkv.  g_qkv[b][oc][n], oc:
//   q: h*32+d ; k: 256+h*32+d ; v: 512+h*32+d.   n = g*512 + m.
// One block = (head, 128 query cols); thread = one query.
// K/V tiles staged in smem as packed f32x2 pairs along d.
// ---------------------------------------------------------------------------
__global__ __launch_bounds__(128) void attn_kernel() {
    __shared__ u64 Ksd[16][128];
    __shared__ u64 Vsd[16][128];
    const int head = blockIdx.y;
    const int b = head >> 6;
    const int g = (head >> 3) & 7;
    const int h = head & 7;
    const int t = threadIdx.x;
    const int nq = g * MSEQ + blockIdx.x * 128 + t;
    const float* qrow = g_qkv + ((size_t)b * OC3 + h * HD) * NN;
    const float* krow = qrow + (size_t)CC * NN;
    const float* vrow = qrow + (size_t)(2 * CC) * NN;
    const float scale = 0.17677669529663687f;

    u64 q2[16];
#pragma unroll
    for (int p = 0; p < 16; p++)
        q2[p] = pack2(qrow[(size_t)(2 * p) * NN + nq], qrow[(size_t)(2 * p + 1) * NN + nq]);

    u64 o2[16];
#pragma unroll
    for (int p = 0; p < 16; p++) o2[p] = 0ull;
    float mx = -1e30f, l = 0.f;

    for (int kt = 0; kt < MSEQ; kt += 128) {
        __syncthreads();
        {
            int nk = g * MSEQ + kt + t;
#pragma unroll
            for (int p = 0; p < 16; p++) {
                Ksd[p][t] = pack2(krow[(size_t)(2 * p) * NN + nk],
                                  krow[(size_t)(2 * p + 1) * NN + nk]);
                Vsd[p][t] = pack2(vrow[(size_t)(2 * p) * NN + nk],
                                  vrow[(size_t)(2 * p + 1) * NN + nk]);
            }
        }
        __syncthreads();

        for (int j = 0; j < 128; j++) {
            u64 s2 = 0ull;
#pragma unroll
            for (int p = 0; p < 16; p++) s2 = fma2(q2[p], Ksd[p][j], s2);
            float2 sf = unpk2(s2);
            float s = (sf.x + sf.y) * scale;

            if (s <= mx) {
                float p = __expf(s - mx);
                l += p;
                u64 pd = pack2(p, p);
#pragma unroll
                for (int d = 0; d < 16; d++) o2[d] = fma2(pd, Vsd[d][j], o2[d]);
            } else {
                float corr = __expf(mx - s);
                mx = s;
                l = l * corr + 1.f;
                u64 cd = pack2(corr, corr);
#pragma unroll
                for (int d = 0; d < 16; d++) o2[d] = fma2(o2[d], cd, Vsd[d][j]);
            }
        }
    }

    const float inv = 1.f / l;
    float* ap = g_att + ((size_t)b * CC + h * HD) * NN + nq;
#pragma unroll
    for (int p = 0; p < 16; p++) {
        float2 f = unpk2(o2[p]);
        ap[(size_t)(2 * p) * NN]     = f.x * inv;
        ap[(size_t)(2 * p + 1) * NN] = f.y * inv;
    }
}

// ---------------------------------------------------------------------------
extern "C" void kernel_launch(void* const* d_in, const int* in_sizes, int n_in,
                              void* d_out, int out_size) {
    const float* x      = (const float*)d_in[0];   // [B,C,N]
    const float* w_qkv  = (const float*)d_in[1];   // [768,256]
    const float* w_proj = (const float*)d_in[2];   // [256,256]
    const float* b_proj = (const float*)d_in[3];   // [256]
    float* out = (float*)d_out;                    // [B,C,N]

    cudaFuncSetAttribute(qkv_gemm_kernel, cudaFuncAttributeMaxDynamicSharedMemorySize, SMEM_GEMM);
    cudaFuncSetAttribute(proj_gemm_kernel, cudaFuncAttributeMaxDynamicSharedMemorySize, SMEM_GEMM);

    dim3 g1(NN / 128, OC3 / 128, BB);
    qkv_gemm_kernel<<<g1, 256, SMEM_GEMM>>>(x, w_qkv);

    dim3 g2(MSEQ / 128, BB * GG * NH);
    attn_kernel<<<g2, 128>>>();

    dim3 g3(NN / 128, CC / 128, BB);
    proj_gemm_kernel<<<g3, 256, SMEM_GEMM>>>(w_proj, b_proj, out);
}

// round 5
// speedup vs baseline: 1.6808x; 1.1677x over previous
#include <cuda_runtime.h>
#include <cuda_bf16.h>

#define BB   4
#define CC   256
#define NN   4096
#define GG   8
#define NH   8
#define HD   32
#define MSEQ 512
#define OC3  768

typedef unsigned long long u64;
typedef unsigned int u32;

// ---------------------------------------------------------------- helpers
__device__ __forceinline__ u64 pack2(float lo, float hi) {
    u64 r; asm("mov.b64 %0,{%1,%2};" : "=l"(r) : "f"(lo), "f"(hi)); return r;
}
__device__ __forceinline__ float2 unpk2(u64 v) {
    float2 f; asm("mov.b64 {%0,%1},%2;" : "=f"(f.x), "=f"(f.y) : "l"(v)); return f;
}
__device__ __forceinline__ u64 fma2(u64 a, u64 b, u64 c) {
    u64 d; asm("fma.rn.f32x2 %0,%1,%2,%3;" : "=l"(d) : "l"(a), "l"(b), "l"(c)); return d;
}
__device__ __forceinline__ u64 mul2(u64 a, u64 b) {
    u64 d; asm("mul.rn.f32x2 %0,%1,%2;" : "=l"(d) : "l"(a), "l"(b)); return d;
}
__device__ __forceinline__ u32 smem_u32(const void* p) {
    u32 a; asm("{.reg .u64 t; cvta.to.shared.u64 t,%1; cvt.u32.u64 %0,t;}" : "=r"(a) : "l"(p));
    return a;
}
__device__ __forceinline__ void ldsm4(u32* r, u32 addr) {
    asm volatile("ldmatrix.sync.aligned.m8n8.x4.shared.b16 {%0,%1,%2,%3},[%4];"
                 : "=r"(r[0]), "=r"(r[1]), "=r"(r[2]), "=r"(r[3]) : "r"(addr));
}
__device__ __forceinline__ void ldsm4t(u32* r, u32 addr) {
    asm volatile("ldmatrix.sync.aligned.m8n8.x4.trans.shared.b16 {%0,%1,%2,%3},[%4];"
                 : "=r"(r[0]), "=r"(r[1]), "=r"(r[2]), "=r"(r[3]) : "r"(addr));
}
__device__ __forceinline__ void mma16816(float* d, const u32* a, const u32* b) {
    asm volatile("mma.sync.aligned.m16n8k16.row.col.f32.bf16.bf16.f32 "
                 "{%0,%1,%2,%3},{%4,%5,%6,%7},{%8,%9},{%0,%1,%2,%3};"
                 : "+f"(d[0]), "+f"(d[1]), "+f"(d[2]), "+f"(d[3])
                 : "r"(a[0]), "r"(a[1]), "r"(a[2]), "r"(a[3]), "r"(b[0]), "r"(b[1]));
}
__device__ __forceinline__ void split_bf16(float x, __nv_bfloat16& h, __nv_bfloat16& l) {
    h = __float2bfloat16(x);
    l = __float2bfloat16(x - __bfloat162float(h));
}

// smem tiles: A (weights) [128 m][64 k] bf16, 128B rows, XOR swizzle on 16B chunks
__device__ __forceinline__ u32 a_off(int m, int k) {
    int chunk = (k >> 3) ^ (m & 7);
    return m * 128 + (chunk << 4) + ((k * 2) & 15);
}
// B (activations) [64 k][128 n] bf16, 256B rows, XOR swizzle
__device__ __forceinline__ u32 b_off(int k, int n) {
    int chunk = (n >> 3) ^ (k & 7);
    return k * 256 + (chunk << 4) + ((n * 2) & 15);
}
__device__ __forceinline__ void st_bf2(char* base, u32 off, __nv_bfloat16 a, __nv_bfloat16 b) {
    __nv_bfloat162 t; t.x = a; t.y = b;
    *reinterpret_cast<__nv_bfloat162*>(base + off) = t;
}

#define AHI 0
#define ALO 16384
#define BHI 32768
#define BLO 49152
#define SMEM_GEMM 65536

// Scratch (allocation-free rule) — channel-major: [b][oc][n]
__device__ __align__(128) float g_qkv[(size_t)BB * OC3 * NN];
__device__ __align__(128) float g_att[(size_t)BB * CC * NN];

// ---------------------------------------------------------------------------
// GEMM core:  out[m][n] = sum_k A[m][k] * B[k][n]   (split-bf16, HMMA)
// ---------------------------------------------------------------------------
template<int KDIM, bool ADD_BIAS>
__device__ __forceinline__ void gemm_body(const float* __restrict__ A,
                                          const float* __restrict__ Brow,
                                          size_t ldb,
                                          const float* __restrict__ bias,
                                          float* __restrict__ outp,
                                          size_t ldo,
                                          int m0, char* smem) {
    const u32 sb = smem_u32(smem);
    const int t = threadIdx.x;
    const int wid = t >> 5, lane = t & 31;
    const int wm = (wid & 3) * 32;
    const int wn = (wid >> 2) * 64;

    float acc[2][8][4];
#pragma unroll
    for (int i = 0; i < 2; i++)
#pragma unroll
        for (int j = 0; j < 8; j++)
#pragma unroll
            for (int c = 0; c < 4; c++) acc[i][j][c] = 0.f;

    for (int c0 = 0; c0 < KDIM; c0 += 64) {
        {
            int mm = t >> 1, half = t & 1;
            const float* src = A + (size_t)(m0 + mm) * KDIM + c0 + half * 32;
            char* ah = smem + AHI;
            char* al = smem + ALO;
#pragma unroll
            for (int i = 0; i < 8; i++) {
                float4 v = *reinterpret_cast<const float4*>(src + i * 4);
                int k = half * 32 + i * 4;
                __nv_bfloat16 h0, l0, h1, l1, h2, l2, h3, l3;
                split_bf16(v.x, h0, l0); split_bf16(v.y, h1, l1);
                split_bf16(v.z, h2, l2); split_bf16(v.w, h3, l3);
                st_bf2(ah, a_off(mm, k), h0, h1);   st_bf2(ah, a_off(mm, k + 2), h2, h3);
                st_bf2(al, a_off(mm, k), l0, l1);   st_bf2(al, a_off(mm, k + 2), l2, l3);
            }
        }
        {
            int kk = t >> 2, q = t & 3;
            const float* src = Brow + (size_t)(c0 + kk) * ldb + q * 32;
            char* bh = smem + BHI;
            char* bl = smem + BLO;
#pragma unroll
            for (int i = 0; i < 8; i++) {
                float4 v = *reinterpret_cast<const float4*>(src + i * 4);
                int n = q * 32 + i * 4;
                __nv_bfloat16 h0, l0, h1, l1, h2, l2, h3, l3;
                split_bf16(v.x, h0, l0); split_bf16(v.y, h1, l1);
                split_bf16(v.z, h2, l2); split_bf16(v.w, h3, l3);
                st_bf2(bh, b_off(kk, n), h0, h1);   st_bf2(bh, b_off(kk, n + 2), h2, h3);
                st_bf2(bl, b_off(kk, n), l0, l1);   st_bf2(bl, b_off(kk, n + 2), l2, l3);
            }
        }
        __syncthreads();

#pragma unroll
        for (int ks = 0; ks < 4; ks++) {
            u32 ah[2][4], al[2][4];
#pragma unroll
            for (int i = 0; i < 2; i++) {
                int row = wm + i * 16 + (lane & 15);
                int kc  = ks * 16 + (lane >> 4) * 8;
                u32 ao = row * 128 + ((((kc >> 3) ^ (row & 7))) << 4);
                ldsm4(ah[i], sb + AHI + ao);
                ldsm4(al[i], sb + ALO + ao);
            }
#pragma unroll
            for (int nh = 0; nh < 2; nh++) {
                u32 bh[2][4], bl[2][4];
#pragma unroll
                for (int pp = 0; pp < 2; pp++) {
                    int k = ks * 16 + ((lane >> 3) & 1) * 8 + (lane & 7);
                    int nb = wn + nh * 32 + pp * 16 + (lane >> 4) * 8;
                    u32 bo = k * 256 + ((((nb >> 3) ^ (k & 7))) << 4);
                    ldsm4t(bh[pp], sb + BHI + bo);
                    ldsm4t(bl[pp], sb + BLO + bo);
                }
#pragma unroll
                for (int i = 0; i < 2; i++)
#pragma unroll
                    for (int pp = 0; pp < 2; pp++)
#pragma unroll
                        for (int s = 0; s < 2; s++) {
                            int nt = nh * 4 + pp * 2 + s;
                            mma16816(acc[i][nt], ah[i], bh[pp] + s * 2);
                            mma16816(acc[i][nt], ah[i], bl[pp] + s * 2);
                            mma16816(acc[i][nt], al[i], bh[pp] + s * 2);
                        }
            }
        }
        __syncthreads();
    }

#pragma unroll
    for (int i = 0; i < 2; i++) {
        int r0 = wm + i * 16 + (lane >> 2);
        float b0 = 0.f, b8 = 0.f;
        if (ADD_BIAS) { b0 = bias[m0 + r0]; b8 = bias[m0 + r0 + 8]; }
#pragma unroll
        for (int nt = 0; nt < 8; nt++) {
            int n = wn + nt * 8 + (lane & 3) * 2;
            float* d0 = outp + (size_t)r0 * ldo + n;
            *reinterpret_cast<float2*>(d0) =
                make_float2(acc[i][nt][0] + b0, acc[i][nt][1] + b0);
            *reinterpret_cast<float2*>(d0 + 8 * ldo) =
                make_float2(acc[i][nt][2] + b8, acc[i][nt][3] + b8);
        }
    }
}

__global__ __launch_bounds__(256, 2) void qkv_gemm_kernel(const float* __restrict__ x,
                                                          const float* __restrict__ w) {
    extern __shared__ char smem[];
    const int b = blockIdx.z;
    const int n0 = blockIdx.x * 128;
    const int m0 = blockIdx.y * 128;
    gemm_body<CC, false>(w, x + (size_t)b * CC * NN + n0, NN, nullptr,
                         g_qkv + ((size_t)b * OC3 + m0) * NN + n0, NN, m0, smem);
}

__global__ __launch_bounds__(256, 2) void proj_gemm_kernel(const float* __restrict__ w,
                                                           const float* __restrict__ bias,
                                                           float* __restrict__ out) {
    extern __shared__ char smem[];
    const int b = blockIdx.z;
    const int n0 = blockIdx.x * 128;
    const int m0 = blockIdx.y * 128;
    gemm_body<CC, true>(w, g_att + (size_t)b * CC * NN + n0, NN, bias,
                        out + ((size_t)b * CC + m0) * NN + n0, NN, m0, smem);
}

// ---------------------------------------------------------------------------
// Kernel 2: grouped MHA, two-phase per 64-key tile.
// Phase 1: 4-way-ILP dots -> scores smem + tile max.
// Phase 2: one rescale per tile, then p*V accumulate (no divergent hot path).
// dynamic smem: Ks u64[16][64] (8KB) | Vs u64[16][64] (8KB) | Sc f32[128][65]
// ---------------------------------------------------------------------------
#define ATT_KS 0
#define ATT_VS 8192
#define ATT_SC 16384
#define SMEM_ATT (16384 + 128 * 65 * 4)

__global__ __launch_bounds__(128) void attn_kernel() {
    extern __shared__ char smem[];
    u64 (*Ks)[64] = reinterpret_cast<u64(*)[64]>(smem + ATT_KS);
    u64 (*Vs)[64] = reinterpret_cast<u64(*)[64]>(smem + ATT_VS);
    float (*Sc)[65] = reinterpret_cast<float(*)[65]>(smem + ATT_SC);

    const int head = blockIdx.y;
    const int b = head >> 6;
    const int g = (head >> 3) & 7;
    const int h = head & 7;
    const int t = threadIdx.x;
    const int nq = g * MSEQ + blockIdx.x * 128 + t;
    const float* qrow = g_qkv + ((size_t)b * OC3 + h * HD) * NN;
    const float* krow = qrow + (size_t)CC * NN;
    const float* vrow = qrow + (size_t)(2 * CC) * NN;
    const float scale = 0.17677669529663687f;

    u64 q2[16];
#pragma unroll
    for (int p = 0; p < 16; p++)
        q2[p] = pack2(qrow[(size_t)(2 * p) * NN + nq], qrow[(size_t)(2 * p + 1) * NN + nq]);

    u64 o2[16];
#pragma unroll
    for (int p = 0; p < 16; p++) o2[p] = 0ull;
    float mx = -1e30f, l = 0.f;

    const int fhalf = t >> 6;          // 0: fill K, 1: fill V
    const int fcol  = t & 63;

    for (int kt = 0; kt < MSEQ; kt += 64) {
        __syncthreads();
        {
            const float* src = fhalf ? vrow : krow;
            u64 (*dst)[64] = fhalf ? Vs : Ks;
            int nk = g * MSEQ + kt + fcol;
#pragma unroll
            for (int p = 0; p < 16; p++)
                dst[p][fcol] = pack2(src[(size_t)(2 * p) * NN + nk],
                                     src[(size_t)(2 * p + 1) * NN + nk]);
        }
        __syncthreads();

        // ---- phase 1: scores with 4-way ILP
        float tm0 = -1e30f, tm1 = -1e30f, tm2 = -1e30f, tm3 = -1e30f;
#pragma unroll 2
        for (int j0 = 0; j0 < 64; j0 += 4) {
            u64 s0 = 0ull, s1 = 0ull, s2 = 0ull, s3 = 0ull;
#pragma unroll
            for (int p = 0; p < 16; p++) {
                s0 = fma2(q2[p], Ks[p][j0],     s0);
                s1 = fma2(q2[p], Ks[p][j0 + 1], s1);
                s2 = fma2(q2[p], Ks[p][j0 + 2], s2);
                s3 = fma2(q2[p], Ks[p][j0 + 3], s3);
            }
            float2 f0 = unpk2(s0), f1 = unpk2(s1), f2 = unpk2(s2), f3 = unpk2(s3);
            float v0 = (f0.x + f0.y) * scale;
            float v1 = (f1.x + f1.y) * scale;
            float v2 = (f2.x + f2.y) * scale;
            float v3 = (f3.x + f3.y) * scale;
            Sc[t][j0] = v0; Sc[t][j0 + 1] = v1; Sc[t][j0 + 2] = v2; Sc[t][j0 + 3] = v3;
            tm0 = fmaxf(tm0, v0); tm1 = fmaxf(tm1, v1);
            tm2 = fmaxf(tm2, v2); tm3 = fmaxf(tm3, v3);
        }
        float tmax = fmaxf(fmaxf(tm0, tm1), fmaxf(tm2, tm3));

        // ---- rescale (once per tile)
        if (tmax > mx) {
            float cd = __expf(mx - tmax);
            mx = tmax;
            l *= cd;
            u64 cd2 = pack2(cd, cd);
#pragma unroll
            for (int d = 0; d < 16; d++) o2[d] = mul2(o2[d], cd2);
        }

        // ---- phase 2: exp + p*V
#pragma unroll 2
        for (int j = 0; j < 64; j += 2) {
            float p0 = __expf(Sc[t][j] - mx);
            float p1 = __expf(Sc[t][j + 1] - mx);
            l += p0 + p1;
            u64 pd0 = pack2(p0, p0);
            u64 pd1 = pack2(p1, p1);
#pragma unroll
            for (int d = 0; d < 16; d++) {
                o2[d] = fma2(pd0, Vs[d][j],     o2[d]);
                o2[d] = fma2(pd1, Vs[d][j + 1], o2[d]);
            }
        }
    }

    const float inv = 1.f / l;
    float* ap = g_att + ((size_t)b * CC + h * HD) * NN + nq;
#pragma unroll
    for (int p = 0; p < 16; p++) {
        float2 f = unpk2(o2[p]);
        ap[(size_t)(2 * p) * NN]     = f.x * inv;
        ap[(size_t)(2 * p + 1) * NN] = f.y * inv;
    }
}

// ---------------------------------------------------------------------------
extern "C" void kernel_launch(void* const* d_in, const int* in_sizes, int n_in,
                              void* d_out, int out_size) {
    const float* x      = (const float*)d_in[0];
    const float* w_qkv  = (const float*)d_in[1];
    const float* w_proj = (const float*)d_in[2];
    const float* b_proj = (const float*)d_in[3];
    float* out = (float*)d_out;

    cudaFuncSetAttribute(qkv_gemm_kernel, cudaFuncAttributeMaxDynamicSharedMemorySize, SMEM_GEMM);
    cudaFuncSetAttribute(proj_gemm_kernel, cudaFuncAttributeMaxDynamicSharedMemorySize, SMEM_GEMM);
    cudaFuncSetAttribute(attn_kernel, cudaFuncAttributeMaxDynamicSharedMemorySize, SMEM_ATT);

    dim3 g1(NN / 128, OC3 / 128, BB);
    qkv_gemm_kernel<<<g1, 256, SMEM_GEMM>>>(x, w_qkv);

    dim3 g2(MSEQ / 128, BB * GG * NH);
    attn_kernel<<<g2, 128, SMEM_ATT>>>();

    dim3 g3(NN / 128, CC / 128, BB);
    proj_gemm_kernel<<<g3, 256, SMEM_GEMM>>>(w_proj, b_proj, out);
}

// round 6
// speedup vs baseline: 2.8150x; 1.6748x over previous
#include <cuda_runtime.h>
#include <cuda_bf16.h>

#define BB   4
#define CC   256
#define NN   4096
#define GG   8
#define NH   8
#define HD   32
#define MSEQ 512
#define OC3  768

typedef unsigned long long u64;
typedef unsigned int u32;

// ---------------------------------------------------------------- helpers
__device__ __forceinline__ u32 smem_u32(const void* p) {
    u32 a; asm("{.reg .u64 t; cvta.to.shared.u64 t,%1; cvt.u32.u64 %0,t;}" : "=r"(a) : "l"(p));
    return a;
}
__device__ __forceinline__ void ldsm4(u32* r, u32 addr) {
    asm volatile("ldmatrix.sync.aligned.m8n8.x4.shared.b16 {%0,%1,%2,%3},[%4];"
                 : "=r"(r[0]), "=r"(r[1]), "=r"(r[2]), "=r"(r[3]) : "r"(addr));
}
__device__ __forceinline__ void ldsm4t(u32* r, u32 addr) {
    asm volatile("ldmatrix.sync.aligned.m8n8.x4.trans.shared.b16 {%0,%1,%2,%3},[%4];"
                 : "=r"(r[0]), "=r"(r[1]), "=r"(r[2]), "=r"(r[3]) : "r"(addr));
}
__device__ __forceinline__ void mma16816(float* d, const u32* a, const u32* b) {
    asm volatile("mma.sync.aligned.m16n8k16.row.col.f32.bf16.bf16.f32 "
                 "{%0,%1,%2,%3},{%4,%5,%6,%7},{%8,%9},{%0,%1,%2,%3};"
                 : "+f"(d[0]), "+f"(d[1]), "+f"(d[2]), "+f"(d[3])
                 : "r"(a[0]), "r"(a[1]), "r"(a[2]), "r"(a[3]), "r"(b[0]), "r"(b[1]));
}
__device__ __forceinline__ void split_bf16(float x, __nv_bfloat16& h, __nv_bfloat16& l) {
    h = __float2bfloat16(x);
    l = __float2bfloat16(x - __bfloat162float(h));
}
__device__ __forceinline__ u32 pk_bf(__nv_bfloat16 a, __nv_bfloat16 b) {
    __nv_bfloat162 t; t.x = a; t.y = b;
    return *reinterpret_cast<u32*>(&t);
}
__device__ __forceinline__ void st_bf2(char* base, u32 off, __nv_bfloat16 a, __nv_bfloat16 b) {
    __nv_bfloat162 t; t.x = a; t.y = b;
    *reinterpret_cast<__nv_bfloat162*>(base + off) = t;
}

// GEMM smem swizzles (unchanged from R5)
__device__ __forceinline__ u32 a_off(int m, int k) {
    int chunk = (k >> 3) ^ (m & 7);
    return m * 128 + (chunk << 4) + ((k * 2) & 15);
}
__device__ __forceinline__ u32 b_off(int k, int n) {
    int chunk = (n >> 3) ^ (k & 7);
    return k * 256 + (chunk << 4) + ((n * 2) & 15);
}

#define AHI 0
#define ALO 16384
#define BHI 32768
#define BLO 49152
#define SMEM_GEMM 65536

// Scratch — channel-major: [b][oc][n]
__device__ __align__(128) float g_qkv[(size_t)BB * OC3 * NN];
__device__ __align__(128) float g_att[(size_t)BB * CC * NN];

// ---------------------------------------------------------------------------
// GEMM core (unchanged from R5):  out[m][n] = sum_k A[m][k] * B[k][n]
// ---------------------------------------------------------------------------
template<int KDIM, bool ADD_BIAS>
__device__ __forceinline__ void gemm_body(const float* __restrict__ A,
                                          const float* __restrict__ Brow,
                                          size_t ldb,
                                          const float* __restrict__ bias,
                                          float* __restrict__ outp,
                                          size_t ldo,
                                          int m0, char* smem) {
    const u32 sb = smem_u32(smem);
    const int t = threadIdx.x;
    const int wid = t >> 5, lane = t & 31;
    const int wm = (wid & 3) * 32;
    const int wn = (wid >> 2) * 64;

    float acc[2][8][4];
#pragma unroll
    for (int i = 0; i < 2; i++)
#pragma unroll
        for (int j = 0; j < 8; j++)
#pragma unroll
            for (int c = 0; c < 4; c++) acc[i][j][c] = 0.f;

    for (int c0 = 0; c0 < KDIM; c0 += 64) {
        {
            int mm = t >> 1, half = t & 1;
            const float* src = A + (size_t)(m0 + mm) * KDIM + c0 + half * 32;
            char* ah = smem + AHI;
            char* al = smem + ALO;
#pragma unroll
            for (int i = 0; i < 8; i++) {
                float4 v = *reinterpret_cast<const float4*>(src + i * 4);
                int k = half * 32 + i * 4;
                __nv_bfloat16 h0, l0, h1, l1, h2, l2, h3, l3;
                split_bf16(v.x, h0, l0); split_bf16(v.y, h1, l1);
                split_bf16(v.z, h2, l2); split_bf16(v.w, h3, l3);
                st_bf2(ah, a_off(mm, k), h0, h1);   st_bf2(ah, a_off(mm, k + 2), h2, h3);
                st_bf2(al, a_off(mm, k), l0, l1);   st_bf2(al, a_off(mm, k + 2), l2, l3);
            }
        }
        {
            int kk = t >> 2, q = t & 3;
            const float* src = Brow + (size_t)(c0 + kk) * ldb + q * 32;
            char* bh = smem + BHI;
            char* bl = smem + BLO;
#pragma unroll
            for (int i = 0; i < 8; i++) {
                float4 v = *reinterpret_cast<const float4*>(src + i * 4);
                int n = q * 32 + i * 4;
                __nv_bfloat16 h0, l0, h1, l1, h2, l2, h3, l3;
                split_bf16(v.x, h0, l0); split_bf16(v.y, h1, l1);
                split_bf16(v.z, h2, l2); split_bf16(v.w, h3, l3);
                st_bf2(bh, b_off(kk, n), h0, h1);   st_bf2(bh, b_off(kk, n + 2), h2, h3);
                st_bf2(bl, b_off(kk, n), l0, l1);   st_bf2(bl, b_off(kk, n + 2), l2, l3);
            }
        }
        __syncthreads();

#pragma unroll
        for (int ks = 0; ks < 4; ks++) {
            u32 ah[2][4], al[2][4];
#pragma unroll
            for (int i = 0; i < 2; i++) {
                int row = wm + i * 16 + (lane & 15);
                int kc  = ks * 16 + (lane >> 4) * 8;
                u32 ao = row * 128 + ((((kc >> 3) ^ (row & 7))) << 4);
                ldsm4(ah[i], sb + AHI + ao);
                ldsm4(al[i], sb + ALO + ao);
            }
#pragma unroll
            for (int nh = 0; nh < 2; nh++) {
                u32 bh[2][4], bl[2][4];
#pragma unroll
                for (int pp = 0; pp < 2; pp++) {
                    int k = ks * 16 + ((lane >> 3) & 1) * 8 + (lane & 7);
                    int nb = wn + nh * 32 + pp * 16 + (lane >> 4) * 8;
                    u32 bo = k * 256 + ((((nb >> 3) ^ (k & 7))) << 4);
                    ldsm4t(bh[pp], sb + BHI + bo);
                    ldsm4t(bl[pp], sb + BLO + bo);
                }
#pragma unroll
                for (int i = 0; i < 2; i++)
#pragma unroll
                    for (int pp = 0; pp < 2; pp++)
#pragma unroll
                        for (int s = 0; s < 2; s++) {
                            int nt = nh * 4 + pp * 2 + s;
                            mma16816(acc[i][nt], ah[i], bh[pp] + s * 2);
                            mma16816(acc[i][nt], ah[i], bl[pp] + s * 2);
                            mma16816(acc[i][nt], al[i], bh[pp] + s * 2);
                        }
            }
        }
        __syncthreads();
    }

#pragma unroll
    for (int i = 0; i < 2; i++) {
        int r0 = wm + i * 16 + (lane >> 2);
        float b0 = 0.f, b8 = 0.f;
        if (ADD_BIAS) { b0 = bias[m0 + r0]; b8 = bias[m0 + r0 + 8]; }
#pragma unroll
        for (int nt = 0; nt < 8; nt++) {
            int n = wn + nt * 8 + (lane & 3) * 2;
            float* d0 = outp + (size_t)r0 * ldo + n;
            *reinterpret_cast<float2*>(d0) =
                make_float2(acc[i][nt][0] + b0, acc[i][nt][1] + b0);
            *reinterpret_cast<float2*>(d0 + 8 * ldo) =
                make_float2(acc[i][nt][2] + b8, acc[i][nt][3] + b8);
        }
    }
}

__global__ __launch_bounds__(256, 2) void qkv_gemm_kernel(const float* __restrict__ x,
                                                          const float* __restrict__ w) {
    extern __shared__ char smem[];
    const int b = blockIdx.z;
    const int n0 = blockIdx.x * 128;
    const int m0 = blockIdx.y * 128;
    gemm_body<CC, false>(w, x + (size_t)b * CC * NN + n0, NN, nullptr,
                         g_qkv + ((size_t)b * OC3 + m0) * NN + n0, NN, m0, smem);
}

__global__ __launch_bounds__(256, 2) void proj_gemm_kernel(const float* __restrict__ w,
                                                           const float* __restrict__ bias,
                                                           float* __restrict__ out) {
    extern __shared__ char smem[];
    const int b = blockIdx.z;
    const int n0 = blockIdx.x * 128;
    const int m0 = blockIdx.y * 128;
    gemm_body<CC, true>(w, g_att + (size_t)b * CC * NN + n0, NN, bias,
                        out + ((size_t)b * CC + m0) * NN + n0, NN, m0, smem);
}

// ---------------------------------------------------------------------------
// Kernel 2: grouped MHA on tensor cores (flash-style, split-bf16).
// Block = (head, 64 queries), 4 warps x 16 q-rows. 8 key-tiles of 64.
// smem: Qs[q][hi32|lo32] 8KB | Khs[d][64k] 4KB | Kls 4KB | Vs[key][hi32|lo32] 8KB
// Os (f32 64x34) overlays K/V after the loop.
// ---------------------------------------------------------------------------
__global__ __launch_bounds__(128) void attn_kernel() {
    __shared__ __align__(16) char sm[24576];
    char* Qs  = sm;
    char* Khs = sm + 8192;
    char* Kls = sm + 12288;
    char* Vsm = sm + 16384;
    float* Os = reinterpret_cast<float*>(sm + 8192);

    const int t = threadIdx.x, lane = t & 31, wid = t >> 5;
    const int head = blockIdx.y;
    const int b = head >> 6, g = (head >> 3) & 7, hh = head & 7;
    const int nqbase = g * MSEQ + blockIdx.x * 64;
    const float* qrow = g_qkv + ((size_t)b * OC3 + hh * HD) * NN;
    const float* krow = qrow + (size_t)CC * NN;
    const float* vrow = qrow + (size_t)(2 * CC) * NN;
    const float scale = 0.17677669529663687f;

    // ---- Q fill (pre-scaled, split, transposed [d][n] -> [q][d])
    {
        int q = t & 63, dh = (t >> 6) * 16;
        const float* qp = qrow + nqbase + q;
#pragma unroll
        for (int dd = 0; dd < 16; dd += 2) {
            int d = dh + dd;
            float v0 = qp[(size_t)d * NN] * scale;
            float v1 = qp[(size_t)(d + 1) * NN] * scale;
            __nv_bfloat16 h0, l0, h1, l1;
            split_bf16(v0, h0, l0); split_bf16(v1, h1, l1);
            u32 base = q * 128 + ((d & 7) * 2);
            st_bf2(Qs, base + ((((d >> 3)    ) ^ (q & 7)) << 4), h0, h1);
            st_bf2(Qs, base + ((((d >> 3) + 4) ^ (q & 7)) << 4), l0, l1);
        }
    }
    __syncthreads();

    // ---- per-warp Q fragments (held in registers for the whole kernel)
    u32 qh[2][4], ql[2][4];
    {
        int row = wid * 16 + (lane & 15);
        u32 qsb = smem_u32(Qs) + row * 128;
#pragma unroll
        for (int ks = 0; ks < 2; ks++) {
            int kc = ks * 16 + (lane >> 4) * 8;
            ldsm4(qh[ks], qsb + ((((kc >> 3)    ) ^ (row & 7)) << 4));
            ldsm4(ql[ks], qsb + ((((kc >> 3) + 4) ^ (row & 7)) << 4));
        }
    }

    float oacc[4][4];
#pragma unroll
    for (int i = 0; i < 4; i++)
#pragma unroll
        for (int j = 0; j < 4; j++) oacc[i][j] = 0.f;
    float mx0 = -1e30f, mx1 = -1e30f, l0 = 0.f, l1 = 0.f;

    for (int kt = 0; kt < 8; kt++) {
        const int nkbase = g * MSEQ + kt * 64;
        __syncthreads();
        // ---- K fill: smem [d][key], direct coalesced copy of channel-major K
        {
            int d = t >> 2, kg = (t & 3) * 16;
            const float* kp = krow + (size_t)d * NN + nkbase + kg;
            u32 rbase = d * 128;
#pragma unroll
            for (int kk = 0; kk < 16; kk += 4) {
                float4 v = *reinterpret_cast<const float4*>(kp + kk);
                int key = kg + kk;
                __nv_bfloat16 h0, lo0, h1, lo1, h2, lo2, h3, lo3;
                split_bf16(v.x, h0, lo0); split_bf16(v.y, h1, lo1);
                split_bf16(v.z, h2, lo2); split_bf16(v.w, h3, lo3);
                u32 off = rbase + ((((key >> 3) ^ (d & 7))) << 4) + (key & 7) * 2;
                st_bf2(Khs, off, h0, h1);     st_bf2(Khs, off + 4, h2, h3);
                st_bf2(Kls, off, lo0, lo1);   st_bf2(Kls, off + 4, lo2, lo3);
            }
        }
        // ---- V fill: transpose to smem [key][hi32|lo32]
        {
            int key = t & 63, dh = (t >> 6) * 16;
            const float* vp = vrow + nkbase + key;
#pragma unroll
            for (int dd = 0; dd < 16; dd += 2) {
                int d = dh + dd;
                float v0 = vp[(size_t)d * NN];
                float v1 = vp[(size_t)(d + 1) * NN];
                __nv_bfloat16 h0, lo0, h1, lo1;
                split_bf16(v0, h0, lo0); split_bf16(v1, h1, lo1);
                u32 base = key * 128 + ((d & 7) * 2);
                st_bf2(Vsm, base + ((((d >> 3)    ) ^ (key & 7)) << 4), h0, h1);
                st_bf2(Vsm, base + ((((d >> 3) + 4) ^ (key & 7)) << 4), lo0, lo1);
            }
        }
        __syncthreads();

        // ---- S = Q K^T  (16q x 64k per warp)
        float sacc[8][4];
#pragma unroll
        for (int i = 0; i < 8; i++)
#pragma unroll
            for (int j = 0; j < 4; j++) sacc[i][j] = 0.f;
#pragma unroll
        for (int ks = 0; ks < 2; ks++) {
            int kd = ks * 16 + ((lane >> 3) & 1) * 8 + (lane & 7);
            u32 krb = kd * 128;
#pragma unroll
            for (int pp = 0; pp < 4; pp++) {
                int nb = pp * 16 + (lane >> 4) * 8;
                u32 off = krb + ((((nb >> 3) ^ (kd & 7))) << 4);
                u32 kbh[4], kbl[4];
                ldsm4t(kbh, smem_u32(Khs) + off);
                ldsm4t(kbl, smem_u32(Kls) + off);
#pragma unroll
                for (int s = 0; s < 2; s++) {
                    int f = pp * 2 + s;
                    mma16816(sacc[f], qh[ks], kbh + s * 2);
                    mma16816(sacc[f], qh[ks], kbl + s * 2);
                    mma16816(sacc[f], ql[ks], kbh + s * 2);
                }
            }
        }

        // ---- online softmax on fragments
        float rm0 = -1e30f, rm1 = -1e30f;
#pragma unroll
        for (int j = 0; j < 8; j++) {
            rm0 = fmaxf(rm0, fmaxf(sacc[j][0], sacc[j][1]));
            rm1 = fmaxf(rm1, fmaxf(sacc[j][2], sacc[j][3]));
        }
        rm0 = fmaxf(rm0, __shfl_xor_sync(0xffffffffu, rm0, 1));
        rm0 = fmaxf(rm0, __shfl_xor_sync(0xffffffffu, rm0, 2));
        rm1 = fmaxf(rm1, __shfl_xor_sync(0xffffffffu, rm1, 1));
        rm1 = fmaxf(rm1, __shfl_xor_sync(0xffffffffu, rm1, 2));
        float nm0 = fmaxf(mx0, rm0), nm1 = fmaxf(mx1, rm1);
        float c0 = __expf(mx0 - nm0), c1 = __expf(mx1 - nm1);
        mx0 = nm0; mx1 = nm1;
#pragma unroll
        for (int df = 0; df < 4; df++) {
            oacc[df][0] *= c0; oacc[df][1] *= c0;
            oacc[df][2] *= c1; oacc[df][3] *= c1;
        }

        float rs0 = 0.f, rs1 = 0.f;
        u32 aph[4][4], apl[4][4];
#pragma unroll
        for (int j = 0; j < 8; j++) {
            float p0 = __expf(sacc[j][0] - nm0);
            float p1 = __expf(sacc[j][1] - nm0);
            float p2 = __expf(sacc[j][2] - nm1);
            float p3 = __expf(sacc[j][3] - nm1);
            rs0 += p0 + p1; rs1 += p2 + p3;
            __nv_bfloat16 h0, lo0, h1, lo1, h2, lo2, h3, lo3;
            split_bf16(p0, h0, lo0); split_bf16(p1, h1, lo1);
            split_bf16(p2, h2, lo2); split_bf16(p3, h3, lo3);
            int ks = j >> 1, half = (j & 1) * 2;
            aph[ks][half]     = pk_bf(h0, h1);
            aph[ks][half + 1] = pk_bf(h2, h3);
            apl[ks][half]     = pk_bf(lo0, lo1);
            apl[ks][half + 1] = pk_bf(lo2, lo3);
        }
        rs0 += __shfl_xor_sync(0xffffffffu, rs0, 1);
        rs0 += __shfl_xor_sync(0xffffffffu, rs0, 2);
        rs1 += __shfl_xor_sync(0xffffffffu, rs1, 1);
        rs1 += __shfl_xor_sync(0xffffffffu, rs1, 2);
        l0 = l0 * c0 + rs0;
        l1 = l1 * c1 + rs1;

        // ---- O += P V
#pragma unroll
        for (int ks = 0; ks < 4; ks++) {
            int kk = ks * 16 + ((lane >> 3) & 1) * 8 + (lane & 7);
            u32 vrb = kk * 128;
#pragma unroll
            for (int pp = 0; pp < 2; pp++) {
                int nb = pp * 16 + (lane >> 4) * 8;
                u32 vbh[4], vbl[4];
                ldsm4t(vbh, smem_u32(Vsm) + vrb + ((((nb >> 3)    ) ^ (kk & 7)) << 4));
                ldsm4t(vbl, smem_u32(Vsm) + vrb + ((((nb >> 3) + 4) ^ (kk & 7)) << 4));
#pragma unroll
                for (int s = 0; s < 2; s++) {
                    int df = pp * 2 + s;
                    mma16816(oacc[df], aph[ks], vbh + s * 2);
                    mma16816(oacc[df], aph[ks], vbl + s * 2);
                    mma16816(oacc[df], apl[ks], vbh + s * 2);
                }
            }
        }
    }

    // ---- epilogue: normalize, stage to smem, coalesced store to [c][n]
    float inv0 = 1.f / l0, inv1 = 1.f / l1;
    __syncthreads();
    {
        int r = wid * 16 + (lane >> 2);
#pragma unroll
        for (int df = 0; df < 4; df++) {
            int dc = df * 8 + (lane & 3) * 2;
            *reinterpret_cast<float2*>(&Os[r * 34 + dc]) =
                make_float2(oacc[df][0] * inv0, oacc[df][1] * inv0);
            *reinterpret_cast<float2*>(&Os[(r + 8) * 34 + dc]) =
                make_float2(oacc[df][2] * inv1, oacc[df][3] * inv1);
        }
    }
    __syncthreads();
    {
        int d = t >> 2, qg = (t & 3) * 16;
        float* dst = g_att + ((size_t)b * CC + hh * HD + d) * NN + nqbase + qg;
#pragma unroll
        for (int qq = 0; qq < 16; qq += 4) {
            float4 w;
            w.x = Os[(qg + qq    ) * 34 + d];
            w.y = Os[(qg + qq + 1) * 34 + d];
            w.z = Os[(qg + qq + 2) * 34 + d];
            w.w = Os[(qg + qq + 3) * 34 + d];
            *reinterpret_cast<float4*>(dst + qq) = w;
        }
    }
}

// ---------------------------------------------------------------------------
extern "C" void kernel_launch(void* const* d_in, const int* in_sizes, int n_in,
                              void* d_out, int out_size) {
    const float* x      = (const float*)d_in[0];
    const float* w_qkv  = (const float*)d_in[1];
    const float* w_proj = (const float*)d_in[2];
    const float* b_proj = (const float*)d_in[3];
    float* out = (float*)d_out;

    cudaFuncSetAttribute(qkv_gemm_kernel, cudaFuncAttributeMaxDynamicSharedMemorySize, SMEM_GEMM);
    cudaFuncSetAttribute(proj_gemm_kernel, cudaFuncAttributeMaxDynamicSharedMemorySize, SMEM_GEMM);

    dim3 g1(NN / 128, OC3 / 128, BB);
    qkv_gemm_kernel<<<g1, 256, SMEM_GEMM>>>(x, w_qkv);

    dim3 g2(MSEQ / 64, BB * GG * NH);
    attn_kernel<<<g2, 128>>>();

    dim3 g3(NN / 128, CC / 128, BB);
    proj_gemm_kernel<<<g3, 256, SMEM_GEMM>>>(w_proj, b_proj, out);
}

// round 7
// speedup vs baseline: 3.2655x; 1.1600x over previous
#include <cuda_runtime.h>
#include <cuda_bf16.h>

#define BB   4
#define CC   256
#define NN   4096
#define GG   8
#define NH   8
#define HD   32
#define MSEQ 512
#define OC3  768
#define QSCALE_F 0.17677669529663687f

typedef unsigned long long u64;
typedef unsigned int u32;
typedef __nv_bfloat16 bf16;

// ---------------------------------------------------------------- helpers
__device__ __forceinline__ u32 smem_u32(const void* p) {
    u32 a; asm("{.reg .u64 t; cvta.to.shared.u64 t,%1; cvt.u32.u64 %0,t;}" : "=r"(a) : "l"(p));
    return a;
}
__device__ __forceinline__ void ldsm4(u32* r, u32 addr) {
    asm volatile("ldmatrix.sync.aligned.m8n8.x4.shared.b16 {%0,%1,%2,%3},[%4];"
                 : "=r"(r[0]), "=r"(r[1]), "=r"(r[2]), "=r"(r[3]) : "r"(addr));
}
__device__ __forceinline__ void ldsm4t(u32* r, u32 addr) {
    asm volatile("ldmatrix.sync.aligned.m8n8.x4.trans.shared.b16 {%0,%1,%2,%3},[%4];"
                 : "=r"(r[0]), "=r"(r[1]), "=r"(r[2]), "=r"(r[3]) : "r"(addr));
}
__device__ __forceinline__ void mma16816(float* d, const u32* a, const u32* b) {
    asm volatile("mma.sync.aligned.m16n8k16.row.col.f32.bf16.bf16.f32 "
                 "{%0,%1,%2,%3},{%4,%5,%6,%7},{%8,%9},{%0,%1,%2,%3};"
                 : "+f"(d[0]), "+f"(d[1]), "+f"(d[2]), "+f"(d[3])
                 : "r"(a[0]), "r"(a[1]), "r"(a[2]), "r"(a[3]), "r"(b[0]), "r"(b[1]));
}
__device__ __forceinline__ void split_bf16(float x, bf16& h, bf16& l) {
    h = __float2bfloat16(x);
    l = __float2bfloat16(x - __bfloat162float(h));
}
__device__ __forceinline__ u32 pk_bf(bf16 a, bf16 b) {
    __nv_bfloat162 t; t.x = a; t.y = b;
    return *reinterpret_cast<u32*>(&t);
}
__device__ __forceinline__ void st_bf2(char* base, u32 off, bf16 a, bf16 b) {
    __nv_bfloat162 t; t.x = a; t.y = b;
    *reinterpret_cast<__nv_bfloat162*>(base + off) = t;
}
__device__ __forceinline__ u32 a_off(int m, int k) {           // [128 m][64 k] bf16
    return m * 128 + ((((k >> 3) ^ (m & 7))) << 4) + ((k * 2) & 15);
}
__device__ __forceinline__ u32 b_off(int k, int n) {           // [64 k][128 n] bf16
    return k * 256 + ((((n >> 3) ^ (k & 7))) << 4) + ((n * 2) & 15);
}

#define AHI 0
#define ALO 16384
#define BHI 32768
#define BLO 49152
#define SMEM_GEMM 65536

// ---------------- persistent bf16 hi/lo buffers (split once at producer)
__device__ __align__(128) bf16 gx_hi[(size_t)BB * CC * NN];
__device__ __align__(128) bf16 gx_lo[(size_t)BB * CC * NN];
__device__ __align__(128) bf16 gwq_hi[OC3 * CC];
__device__ __align__(128) bf16 gwq_lo[OC3 * CC];
__device__ __align__(128) bf16 gwp_hi[CC * CC];
__device__ __align__(128) bf16 gwp_lo[CC * CC];
__device__ __align__(128) bf16 gqkv_hi[(size_t)BB * OC3 * NN];   // Q rows pre-scaled
__device__ __align__(128) bf16 gqkv_lo[(size_t)BB * OC3 * NN];
__device__ __align__(128) bf16 gatt_hi[(size_t)BB * CC * NN];
__device__ __align__(128) bf16 gatt_lo[(size_t)BB * CC * NN];

// ---------------------------------------------------------------------------
// Prepass: elementwise f32 -> (hi, lo) bf16 split, vectorized.
// ---------------------------------------------------------------------------
__global__ __launch_bounds__(256) void split_kernel(const float* __restrict__ src,
                                                    bf16* __restrict__ hi,
                                                    bf16* __restrict__ lo, int n4) {
    int i = blockIdx.x * blockDim.x + threadIdx.x;
    if (i >= n4) return;
    float4 v = reinterpret_cast<const float4*>(src)[i];
    bf16 h0, l0, h1, l1, h2, l2, h3, l3;
    split_bf16(v.x, h0, l0); split_bf16(v.y, h1, l1);
    split_bf16(v.z, h2, l2); split_bf16(v.w, h3, l3);
    reinterpret_cast<uint2*>(hi)[i] = make_uint2(pk_bf(h0, h1), pk_bf(h2, h3));
    reinterpret_cast<uint2*>(lo)[i] = make_uint2(pk_bf(l0, l1), pk_bf(l2, l3));
}

// ---------------------------------------------------------------------------
// GEMM mainloop: acc[2][8][4] = sum_k A[m][k]*B[k][n], split-bf16, pure-copy fills.
// ---------------------------------------------------------------------------
template<int KDIM>
__device__ __forceinline__ void gemm_main(const bf16* __restrict__ Ah, const bf16* __restrict__ Al,
                                          const bf16* __restrict__ Bh, const bf16* __restrict__ Bl,
                                          size_t ldb, int m0, char* smem,
                                          float (&acc)[2][8][4]) {
    const u32 sb = smem_u32(smem);
    const int t = threadIdx.x;
    const int wid = t >> 5, lane = t & 31;
    const int wm = (wid & 3) * 32;
    const int wn = (wid >> 2) * 64;

#pragma unroll
    for (int i = 0; i < 2; i++)
#pragma unroll
        for (int j = 0; j < 8; j++)
#pragma unroll
            for (int c = 0; c < 4; c++) acc[i][j][c] = 0.f;

    for (int c0 = 0; c0 < KDIM; c0 += 64) {
        // A fill: 1024 16B-chunks, pure copy
#pragma unroll
        for (int i = 0; i < 4; i++) {
            int cidx = i * 256 + t;
            int mm = cidx >> 3, k8 = (cidx & 7) * 8;
            u32 off = a_off(mm, k8);
            const size_t so = (size_t)(m0 + mm) * KDIM + c0 + k8;
            *reinterpret_cast<float4*>(smem + AHI + off) = *reinterpret_cast<const float4*>(Ah + so);
            *reinterpret_cast<float4*>(smem + ALO + off) = *reinterpret_cast<const float4*>(Al + so);
        }
        // B fill: 1024 16B-chunks, pure copy
#pragma unroll
        for (int i = 0; i < 4; i++) {
            int cidx = i * 256 + t;
            int kk = cidx >> 4, n8 = (cidx & 15) * 8;
            u32 off = b_off(kk, n8);
            const size_t so = (size_t)(c0 + kk) * ldb + n8;
            *reinterpret_cast<float4*>(smem + BHI + off) = *reinterpret_cast<const float4*>(Bh + so);
            *reinterpret_cast<float4*>(smem + BLO + off) = *reinterpret_cast<const float4*>(Bl + so);
        }
        __syncthreads();

#pragma unroll
        for (int ks = 0; ks < 4; ks++) {
            u32 ah[2][4], al[2][4];
#pragma unroll
            for (int i = 0; i < 2; i++) {
                int row = wm + i * 16 + (lane & 15);
                int kc  = ks * 16 + (lane >> 4) * 8;
                u32 ao = row * 128 + ((((kc >> 3) ^ (row & 7))) << 4);
                ldsm4(ah[i], sb + AHI + ao);
                ldsm4(al[i], sb + ALO + ao);
            }
#pragma unroll
            for (int nh = 0; nh < 2; nh++) {
                u32 bh[2][4], bl[2][4];
#pragma unroll
                for (int pp = 0; pp < 2; pp++) {
                    int k = ks * 16 + ((lane >> 3) & 1) * 8 + (lane & 7);
                    int nb = wn + nh * 32 + pp * 16 + (lane >> 4) * 8;
                    u32 bo = k * 256 + ((((nb >> 3) ^ (k & 7))) << 4);
                    ldsm4t(bh[pp], sb + BHI + bo);
                    ldsm4t(bl[pp], sb + BLO + bo);
                }
#pragma unroll
                for (int i = 0; i < 2; i++)
#pragma unroll
                    for (int pp = 0; pp < 2; pp++)
#pragma unroll
                        for (int s = 0; s < 2; s++) {
                            int nt = nh * 4 + pp * 2 + s;
                            mma16816(acc[i][nt], ah[i], bh[pp] + s * 2);
                            mma16816(acc[i][nt], ah[i], bl[pp] + s * 2);
                            mma16816(acc[i][nt], al[i], bh[pp] + s * 2);
                        }
            }
        }
        __syncthreads();
    }
}

// Kernel 1: gqkv_hi/lo[b][oc][n] = split( sum_c w_qkv[oc][c] * x[b][c][n] * (oc<256 ? scale : 1) )
__global__ __launch_bounds__(256, 2) void qkv_gemm_kernel() {
    extern __shared__ char smem[];
    const int b = blockIdx.z;
    const int n0 = blockIdx.x * 128;
    const int m0 = blockIdx.y * 128;
    float acc[2][8][4];
    gemm_main<CC>(gwq_hi, gwq_lo,
                  gx_hi + (size_t)b * CC * NN + n0, gx_lo + (size_t)b * CC * NN + n0,
                  NN, m0, smem, acc);

    const int t = threadIdx.x, wid = t >> 5, lane = t & 31;
    const int wm = (wid & 3) * 32, wn = (wid >> 2) * 64;
    bf16* oh = gqkv_hi + ((size_t)b * OC3 + m0) * NN + n0;
    bf16* ol = gqkv_lo + ((size_t)b * OC3 + m0) * NN + n0;
#pragma unroll
    for (int i = 0; i < 2; i++) {
        int r0 = wm + i * 16 + (lane >> 2);
        float s0 = (m0 + r0 < CC) ? QSCALE_F : 1.f;
        float s8 = (m0 + r0 + 8 < CC) ? QSCALE_F : 1.f;
#pragma unroll
        for (int nt = 0; nt < 8; nt++) {
            int n = wn + nt * 8 + (lane & 3) * 2;
            bf16 h0, l0, h1, l1;
            split_bf16(acc[i][nt][0] * s0, h0, l0);
            split_bf16(acc[i][nt][1] * s0, h1, l1);
            *reinterpret_cast<u32*>(oh + (size_t)r0 * NN + n) = pk_bf(h0, h1);
            *reinterpret_cast<u32*>(ol + (size_t)r0 * NN + n) = pk_bf(l0, l1);
            split_bf16(acc[i][nt][2] * s8, h0, l0);
            split_bf16(acc[i][nt][3] * s8, h1, l1);
            *reinterpret_cast<u32*>(oh + (size_t)(r0 + 8) * NN + n) = pk_bf(h0, h1);
            *reinterpret_cast<u32*>(ol + (size_t)(r0 + 8) * NN + n) = pk_bf(l0, l1);
        }
    }
}

// Kernel 3: out[b][c'][n] = sum_c w_proj[c'][c] * att[b][c][n] + bias[c']
__global__ __launch_bounds__(256, 2) void proj_gemm_kernel(const float* __restrict__ bias,
                                                           float* __restrict__ out) {
    extern __shared__ char smem[];
    const int b = blockIdx.z;
    const int n0 = blockIdx.x * 128;
    const int m0 = blockIdx.y * 128;
    float acc[2][8][4];
    gemm_main<CC>(gwp_hi, gwp_lo,
                  gatt_hi + (size_t)b * CC * NN + n0, gatt_lo + (size_t)b * CC * NN + n0,
                  NN, m0, smem, acc);

    const int t = threadIdx.x, wid = t >> 5, lane = t & 31;
    const int wm = (wid & 3) * 32, wn = (wid >> 2) * 64;
    float* outp = out + ((size_t)b * CC + m0) * NN + n0;
#pragma unroll
    for (int i = 0; i < 2; i++) {
        int r0 = wm + i * 16 + (lane >> 2);
        float b0 = bias[m0 + r0], b8 = bias[m0 + r0 + 8];
#pragma unroll
        for (int nt = 0; nt < 8; nt++) {
            int n = wn + nt * 8 + (lane & 3) * 2;
            float* d0 = outp + (size_t)r0 * NN + n;
            *reinterpret_cast<float2*>(d0) =
                make_float2(acc[i][nt][0] + b0, acc[i][nt][1] + b0);
            *reinterpret_cast<float2*>(d0 + 8 * NN) =
                make_float2(acc[i][nt][2] + b8, acc[i][nt][3] + b8);
        }
    }
}

// ---------------------------------------------------------------------------
// Kernel 2: grouped MHA on tensor cores, bf16 hi/lo inputs (flash-style).
// Block = (head, 64 queries), 4 warps x 16 q-rows. 8 key-tiles of 64.
// ---------------------------------------------------------------------------
__global__ __launch_bounds__(128) void attn_kernel() {
    __shared__ __align__(16) char sm[24576];
    char* Qs  = sm;
    char* Khs = sm + 8192;
    char* Kls = sm + 12288;
    char* Vsm = sm + 16384;
    float* Os = reinterpret_cast<float*>(sm + 8192);

    const int t = threadIdx.x, lane = t & 31, wid = t >> 5;
    const int head = blockIdx.y;
    const int b = head >> 6, g = (head >> 3) & 7, hh = head & 7;
    const int nqbase = g * MSEQ + blockIdx.x * 64;
    const size_t qoff = ((size_t)b * OC3 + hh * HD) * NN;
    const bf16* qph = gqkv_hi + qoff;
    const bf16* qpl = gqkv_lo + qoff;
    const bf16* kph = qph + (size_t)CC * NN;
    const bf16* kpl = qpl + (size_t)CC * NN;
    const bf16* vph = qph + (size_t)(2 * CC) * NN;
    const bf16* vpl = qpl + (size_t)(2 * CC) * NN;

    // ---- Q fill: transpose [d][n] -> smem [q][hi|lo], pure copies of pre-split data
    {
        int q = t & 63, dh = (t >> 6) * 16;
        const bf16* ph = qph + nqbase + q;
        const bf16* pl = qpl + nqbase + q;
#pragma unroll
        for (int dd = 0; dd < 16; dd += 2) {
            int d = dh + dd;
            u32 base = q * 128 + ((d & 7) * 2);
            st_bf2(Qs, base + ((((d >> 3)    ) ^ (q & 7)) << 4),
                   ph[(size_t)d * NN], ph[(size_t)(d + 1) * NN]);
            st_bf2(Qs, base + ((((d >> 3) + 4) ^ (q & 7)) << 4),
                   pl[(size_t)d * NN], pl[(size_t)(d + 1) * NN]);
        }
    }
    __syncthreads();

    u32 qh[2][4], ql[2][4];
    {
        int row = wid * 16 + (lane & 15);
        u32 qsb = smem_u32(Qs) + row * 128;
#pragma unroll
        for (int ks = 0; ks < 2; ks++) {
            int kc = ks * 16 + (lane >> 4) * 8;
            ldsm4(qh[ks], qsb + ((((kc >> 3)    ) ^ (row & 7)) << 4));
            ldsm4(ql[ks], qsb + ((((kc >> 3) + 4) ^ (row & 7)) << 4));
        }
    }

    float oacc[4][4];
#pragma unroll
    for (int i = 0; i < 4; i++)
#pragma unroll
        for (int j = 0; j < 4; j++) oacc[i][j] = 0.f;
    float mx0 = -1e30f, mx1 = -1e30f, l0 = 0.f, l1 = 0.f;

    for (int kt = 0; kt < 8; kt++) {
        const int nkbase = g * MSEQ + kt * 64;
        __syncthreads();
        // ---- K fill: [d][key] swizzled, straight 16B copies
#pragma unroll
        for (int i = 0; i < 2; i++) {
            int cidx = i * 128 + t;
            int d = cidx >> 3, k8 = (cidx & 7) * 8;
            u32 off = d * 128 + ((((k8 >> 3) ^ (d & 7))) << 4);
            const size_t so = (size_t)d * NN + nkbase + k8;
            *reinterpret_cast<float4*>(Khs + off) = *reinterpret_cast<const float4*>(kph + so);
            *reinterpret_cast<float4*>(Kls + off) = *reinterpret_cast<const float4*>(kpl + so);
        }
        // ---- V fill: transpose [d][key] -> [key][hi|lo]
        {
            int key = t & 63, dh = (t >> 6) * 16;
            const bf16* ph = vph + nkbase + key;
            const bf16* pl = vpl + nkbase + key;
#pragma unroll
            for (int dd = 0; dd < 16; dd += 2) {
                int d = dh + dd;
                u32 base = key * 128 + ((d & 7) * 2);
                st_bf2(Vsm, base + ((((d >> 3)    ) ^ (key & 7)) << 4),
                       ph[(size_t)d * NN], ph[(size_t)(d + 1) * NN]);
                st_bf2(Vsm, base + ((((d >> 3) + 4) ^ (key & 7)) << 4),
                       pl[(size_t)d * NN], pl[(size_t)(d + 1) * NN]);
            }
        }
        __syncthreads();

        // ---- S = Q K^T
        float sacc[8][4];
#pragma unroll
        for (int i = 0; i < 8; i++)
#pragma unroll
            for (int j = 0; j < 4; j++) sacc[i][j] = 0.f;
#pragma unroll
        for (int ks = 0; ks < 2; ks++) {
            int kd = ks * 16 + ((lane >> 3) & 1) * 8 + (lane & 7);
            u32 krb = kd * 128;
#pragma unroll
            for (int pp = 0; pp < 4; pp++) {
                int nb = pp * 16 + (lane >> 4) * 8;
                u32 off = krb + ((((nb >> 3) ^ (kd & 7))) << 4);
                u32 kbh[4], kbl[4];
                ldsm4t(kbh, smem_u32(Khs) + off);
                ldsm4t(kbl, smem_u32(Kls) + off);
#pragma unroll
                for (int s = 0; s < 2; s++) {
                    int f = pp * 2 + s;
                    mma16816(sacc[f], qh[ks], kbh + s * 2);
                    mma16816(sacc[f], qh[ks], kbl + s * 2);
                    mma16816(sacc[f], ql[ks], kbh + s * 2);
                }
            }
        }

        // ---- online softmax
        float rm0 = -1e30f, rm1 = -1e30f;
#pragma unroll
        for (int j = 0; j < 8; j++) {
            rm0 = fmaxf(rm0, fmaxf(sacc[j][0], sacc[j][1]));
            rm1 = fmaxf(rm1, fmaxf(sacc[j][2], sacc[j][3]));
        }
        rm0 = fmaxf(rm0, __shfl_xor_sync(0xffffffffu, rm0, 1));
        rm0 = fmaxf(rm0, __shfl_xor_sync(0xffffffffu, rm0, 2));
        rm1 = fmaxf(rm1, __shfl_xor_sync(0xffffffffu, rm1, 1));
        rm1 = fmaxf(rm1, __shfl_xor_sync(0xffffffffu, rm1, 2));
        float nm0 = fmaxf(mx0, rm0), nm1 = fmaxf(mx1, rm1);
        float c0 = __expf(mx0 - nm0), c1 = __expf(mx1 - nm1);
        mx0 = nm0; mx1 = nm1;
#pragma unroll
        for (int df = 0; df < 4; df++) {
            oacc[df][0] *= c0; oacc[df][1] *= c0;
            oacc[df][2] *= c1; oacc[df][3] *= c1;
        }

        float rs0 = 0.f, rs1 = 0.f;
        u32 aph[4][4], apl[4][4];
#pragma unroll
        for (int j = 0; j < 8; j++) {
            float p0 = __expf(sacc[j][0] - nm0);
            float p1 = __expf(sacc[j][1] - nm0);
            float p2 = __expf(sacc[j][2] - nm1);
            float p3 = __expf(sacc[j][3] - nm1);
            rs0 += p0 + p1; rs1 += p2 + p3;
            bf16 h0, lo0, h1, lo1, h2, lo2, h3, lo3;
            split_bf16(p0, h0, lo0); split_bf16(p1, h1, lo1);
            split_bf16(p2, h2, lo2); split_bf16(p3, h3, lo3);
            int ks = j >> 1, half = (j & 1) * 2;
            aph[ks][half]     = pk_bf(h0, h1);
            aph[ks][half + 1] = pk_bf(h2, h3);
            apl[ks][half]     = pk_bf(lo0, lo1);
            apl[ks][half + 1] = pk_bf(lo2, lo3);
        }
        rs0 += __shfl_xor_sync(0xffffffffu, rs0, 1);
        rs0 += __shfl_xor_sync(0xffffffffu, rs0, 2);
        rs1 += __shfl_xor_sync(0xffffffffu, rs1, 1);
        rs1 += __shfl_xor_sync(0xffffffffu, rs1, 2);
        l0 = l0 * c0 + rs0;
        l1 = l1 * c1 + rs1;

        // ---- O += P V
#pragma unroll
        for (int ks = 0; ks < 4; ks++) {
            int kk = ks * 16 + ((lane >> 3) & 1) * 8 + (lane & 7);
            u32 vrb = kk * 128;
#pragma unroll
            for (int pp = 0; pp < 2; pp++) {
                int nb = pp * 16 + (lane >> 4) * 8;
                u32 vbh[4], vbl[4];
                ldsm4t(vbh, smem_u32(Vsm) + vrb + ((((nb >> 3)    ) ^ (kk & 7)) << 4));
                ldsm4t(vbl, smem_u32(Vsm) + vrb + ((((nb >> 3) + 4) ^ (kk & 7)) << 4));
#pragma unroll
                for (int s = 0; s < 2; s++) {
                    int df = pp * 2 + s;
                    mma16816(oacc[df], aph[ks], vbh + s * 2);
                    mma16816(oacc[df], aph[ks], vbl + s * 2);
                    mma16816(oacc[df], apl[ks], vbh + s * 2);
                }
            }
        }
    }

    // ---- epilogue: normalize, stage f32 to smem, split-store to gatt hi/lo
    float inv0 = 1.f / l0, inv1 = 1.f / l1;
    __syncthreads();
    {
        int r = wid * 16 + (lane >> 2);
#pragma unroll
        for (int df = 0; df < 4; df++) {
            int dc = df * 8 + (lane & 3) * 2;
            *reinterpret_cast<float2*>(&Os[r * 34 + dc]) =
                make_float2(oacc[df][0] * inv0, oacc[df][1] * inv0);
            *reinterpret_cast<float2*>(&Os[(r + 8) * 34 + dc]) =
                make_float2(oacc[df][2] * inv1, oacc[df][3] * inv1);
        }
    }
    __syncthreads();
    {
        int d = t >> 2, qg = (t & 3) * 16;
        size_t doff = ((size_t)b * CC + hh * HD + d) * NN + nqbase + qg;
        bf16* dh_ = gatt_hi + doff;
        bf16* dl_ = gatt_lo + doff;
#pragma unroll
        for (int qq = 0; qq < 16; qq += 2) {
            float v0 = Os[(qg + qq) * 34 + d];
            float v1 = Os[(qg + qq + 1) * 34 + d];
            bf16 h0, lo0, h1, lo1;
            split_bf16(v0, h0, lo0); split_bf16(v1, h1, lo1);
            *reinterpret_cast<u32*>(dh_ + qq) = pk_bf(h0, h1);
            *reinterpret_cast<u32*>(dl_ + qq) = pk_bf(lo0, lo1);
        }
    }
}

// ---------------------------------------------------------------------------
extern "C" void kernel_launch(void* const* d_in, const int* in_sizes, int n_in,
                              void* d_out, int out_size) {
    const float* x      = (const float*)d_in[0];
    const float* w_qkv  = (const float*)d_in[1];
    const float* w_proj = (const float*)d_in[2];
    const float* b_proj = (const float*)d_in[3];
    float* out = (float*)d_out;

    cudaFuncSetAttribute(qkv_gemm_kernel, cudaFuncAttributeMaxDynamicSharedMemorySize, SMEM_GEMM);
    cudaFuncSetAttribute(proj_gemm_kernel, cudaFuncAttributeMaxDynamicSharedMemorySize, SMEM_GEMM);

    bf16 *xh, *xl, *wqh, *wql, *wph, *wpl;
    cudaGetSymbolAddress((void**)&xh,  gx_hi);
    cudaGetSymbolAddress((void**)&xl,  gx_lo);
    cudaGetSymbolAddress((void**)&wqh, gwq_hi);
    cudaGetSymbolAddress((void**)&wql, gwq_lo);
    cudaGetSymbolAddress((void**)&wph, gwp_hi);
    cudaGetSymbolAddress((void**)&wpl, gwp_lo);

    split_kernel<<<(BB * CC * NN / 4 + 255) / 256, 256>>>(x, xh, xl, BB * CC * NN / 4);
    split_kernel<<<(OC3 * CC / 4 + 255) / 256, 256>>>(w_qkv, wqh, wql, OC3 * CC / 4);
    split_kernel<<<(CC * CC / 4 + 255) / 256, 256>>>(w_proj, wph, wpl, CC * CC / 4);

    dim3 g1(NN / 128, OC3 / 128, BB);
    qkv_gemm_kernel<<<g1, 256, SMEM_GEMM>>>();

    dim3 g2(MSEQ / 64, BB * GG * NH);
    attn_kernel<<<g2, 128>>>();

    dim3 g3(NN / 128, CC / 128, BB);
    proj_gemm_kernel<<<g3, 256, SMEM_GEMM>>>(b_proj, out);
}

// round 8
// speedup vs baseline: 3.7770x; 1.1567x over previous
#include <cuda_runtime.h>
#include <cuda_bf16.h>

#define BB   4
#define CC   256
#define NN   4096
#define GG   8
#define NH   8
#define HD   32
#define MSEQ 512
#define OC3  768
#define QSCALE_F 0.17677669529663687f

typedef unsigned long long u64;
typedef unsigned int u32;
typedef __nv_bfloat16 bf16;

// ---------------------------------------------------------------- helpers
__device__ __forceinline__ u32 smem_u32(const void* p) {
    u32 a; asm("{.reg .u64 t; cvta.to.shared.u64 t,%1; cvt.u32.u64 %0,t;}" : "=r"(a) : "l"(p));
    return a;
}
__device__ __forceinline__ void cpa16(u32 dst, const void* src) {
    asm volatile("cp.async.cg.shared.global [%0],[%1],16;" :: "r"(dst), "l"(src));
}
#define CPA_COMMIT() asm volatile("cp.async.commit_group;" ::: "memory")
#define CPA_WAIT1()  asm volatile("cp.async.wait_group 1;" ::: "memory")
#define CPA_WAIT0()  asm volatile("cp.async.wait_group 0;" ::: "memory")
__device__ __forceinline__ void ldsm4(u32* r, u32 addr) {
    asm volatile("ldmatrix.sync.aligned.m8n8.x4.shared.b16 {%0,%1,%2,%3},[%4];"
                 : "=r"(r[0]), "=r"(r[1]), "=r"(r[2]), "=r"(r[3]) : "r"(addr));
}
__device__ __forceinline__ void ldsm4t(u32* r, u32 addr) {
    asm volatile("ldmatrix.sync.aligned.m8n8.x4.trans.shared.b16 {%0,%1,%2,%3},[%4];"
                 : "=r"(r[0]), "=r"(r[1]), "=r"(r[2]), "=r"(r[3]) : "r"(addr));
}
__device__ __forceinline__ void mma16816(float* d, const u32* a, const u32* b) {
    asm volatile("mma.sync.aligned.m16n8k16.row.col.f32.bf16.bf16.f32 "
                 "{%0,%1,%2,%3},{%4,%5,%6,%7},{%8,%9},{%0,%1,%2,%3};"
                 : "+f"(d[0]), "+f"(d[1]), "+f"(d[2]), "+f"(d[3])
                 : "r"(a[0]), "r"(a[1]), "r"(a[2]), "r"(a[3]), "r"(b[0]), "r"(b[1]));
}
__device__ __forceinline__ void split_bf16(float x, bf16& h, bf16& l) {
    h = __float2bfloat16(x);
    l = __float2bfloat16(x - __bfloat162float(h));
}
__device__ __forceinline__ u32 pk_bf(bf16 a, bf16 b) {
    __nv_bfloat162 t; t.x = a; t.y = b;
    return *reinterpret_cast<u32*>(&t);
}
__device__ __forceinline__ void st_bf2(char* base, u32 off, bf16 a, bf16 b) {
    __nv_bfloat162 t; t.x = a; t.y = b;
    *reinterpret_cast<__nv_bfloat162*>(base + off) = t;
}

// A tile [128 m][32 k] bf16: 64B rows, 4-chunk swizzle
__device__ __forceinline__ u32 a32_off(int m, int k8) {
    return m * 64 + ((((k8 >> 3) ^ ((m >> 1) & 3)) & 3) << 4);
}
// B tile [32 k][128 n] bf16: 256B rows, 8-chunk swizzle
__device__ __forceinline__ u32 b32_off(int k, int n8) {
    return k * 256 + ((((n8 >> 3) ^ (k & 7))) << 4);
}

#define ST_A_HI 0
#define ST_A_LO 8192
#define ST_B_HI 16384
#define ST_B_LO 24576
#define STAGE_SZ 32768
#define SMEM_GEMM 65536

// ---------------- persistent bf16 hi/lo buffers
__device__ __align__(128) bf16 gx_hi[(size_t)BB * CC * NN];
__device__ __align__(128) bf16 gx_lo[(size_t)BB * CC * NN];
__device__ __align__(128) bf16 gwq_hi[OC3 * CC];
__device__ __align__(128) bf16 gwq_lo[OC3 * CC];
__device__ __align__(128) bf16 gwp_hi[CC * CC];
__device__ __align__(128) bf16 gwp_lo[CC * CC];
__device__ __align__(128) bf16 gqkv_hi[(size_t)BB * OC3 * NN];   // Q pre-scaled
__device__ __align__(128) bf16 gqkv_lo[(size_t)BB * OC3 * NN];
__device__ __align__(128) bf16 gatt_hi[(size_t)BB * CC * NN];
__device__ __align__(128) bf16 gatt_lo[(size_t)BB * CC * NN];

// ---------------------------------------------------------------------------
__global__ __launch_bounds__(256) void split_kernel(const float* __restrict__ src,
                                                    bf16* __restrict__ hi,
                                                    bf16* __restrict__ lo, int n4) {
    int i = blockIdx.x * blockDim.x + threadIdx.x;
    if (i >= n4) return;
    float4 v = reinterpret_cast<const float4*>(src)[i];
    bf16 h0, l0, h1, l1, h2, l2, h3, l3;
    split_bf16(v.x, h0, l0); split_bf16(v.y, h1, l1);
    split_bf16(v.z, h2, l2); split_bf16(v.w, h3, l3);
    reinterpret_cast<uint2*>(hi)[i] = make_uint2(pk_bf(h0, h1), pk_bf(h2, h3));
    reinterpret_cast<uint2*>(lo)[i] = make_uint2(pk_bf(l0, l1), pk_bf(l2, l3));
}

// ---------------------------------------------------------------------------
// GEMM mainloop: 2-stage cp.async pipeline, K-chunks of 32.
// ---------------------------------------------------------------------------
template<int KDIM>
__device__ __forceinline__ void gemm_main(const bf16* __restrict__ Ah, const bf16* __restrict__ Al,
                                          const bf16* __restrict__ Bh, const bf16* __restrict__ Bl,
                                          size_t ldb, int m0, char* smem,
                                          float (&acc)[2][8][4]) {
    const u32 sb = smem_u32(smem);
    const int t = threadIdx.x;
    const int wid = t >> 5, lane = t & 31;
    const int wm = (wid & 3) * 32;
    const int wn = (wid >> 2) * 64;
    constexpr int NCH = KDIM / 32;

#pragma unroll
    for (int i = 0; i < 2; i++)
#pragma unroll
        for (int j = 0; j < 8; j++)
#pragma unroll
            for (int c = 0; c < 4; c++) acc[i][j][c] = 0.f;

    // per-thread fill coordinates (fixed)
    const int am0 = t >> 2,        ak8 = (t & 3) * 8;          // A chunks 0,1
    const int am1 = (256 + t) >> 2, bk0 = t >> 4;
    const int bn8 = (t & 15) * 8,  bk1 = (256 + t) >> 4;

    auto fill = [&](int c0, int buf) {
        u32 base = sb + buf * STAGE_SZ;
        {   // A: 2 chunks hi + 2 lo
            u32 o0 = base + a32_off(am0, ak8), o1 = base + a32_off(am1, ak8);
            size_t s0 = (size_t)(m0 + am0) * KDIM + c0 + ak8;
            size_t s1 = (size_t)(m0 + am1) * KDIM + c0 + ak8;
            cpa16(o0 + ST_A_HI, Ah + s0);  cpa16(o1 + ST_A_HI, Ah + s1);
            cpa16(o0 + ST_A_LO, Al + s0);  cpa16(o1 + ST_A_LO, Al + s1);
        }
        {   // B: 2 chunks hi + 2 lo
            u32 o0 = base + b32_off(bk0, bn8), o1 = base + b32_off(bk1, bn8);
            size_t s0 = (size_t)(c0 + bk0) * ldb + bn8;
            size_t s1 = (size_t)(c0 + bk1) * ldb + bn8;
            cpa16(o0 + ST_B_HI, Bh + s0);  cpa16(o1 + ST_B_HI, Bh + s1);
            cpa16(o0 + ST_B_LO, Bl + s0);  cpa16(o1 + ST_B_LO, Bl + s1);
        }
    };

    fill(0, 0); CPA_COMMIT();

    for (int ch = 0; ch < NCH; ch++) {
        if (ch + 1 < NCH) { fill((ch + 1) * 32, (ch + 1) & 1); CPA_COMMIT(); CPA_WAIT1(); }
        else              { CPA_WAIT0(); }
        __syncthreads();
        u32 base = sb + (ch & 1) * STAGE_SZ;

#pragma unroll
        for (int ks = 0; ks < 2; ks++) {
            u32 ah[2][4], al[2][4];
#pragma unroll
            for (int i = 0; i < 2; i++) {
                int row = wm + i * 16 + (lane & 15);
                int kc  = ks * 16 + (lane >> 4) * 8;
                u32 ao = row * 64 + ((((kc >> 3) ^ ((row >> 1) & 3)) & 3) << 4);
                ldsm4(ah[i], base + ST_A_HI + ao);
                ldsm4(al[i], base + ST_A_LO + ao);
            }
#pragma unroll
            for (int nh = 0; nh < 2; nh++) {
                u32 bh[2][4], bl[2][4];
#pragma unroll
                for (int pp = 0; pp < 2; pp++) {
                    int k = ks * 16 + ((lane >> 3) & 1) * 8 + (lane & 7);
                    int nb = wn + nh * 32 + pp * 16 + (lane >> 4) * 8;
                    u32 bo = k * 256 + ((((nb >> 3) ^ (k & 7))) << 4);
                    ldsm4t(bh[pp], base + ST_B_HI + bo);
                    ldsm4t(bl[pp], base + ST_B_LO + bo);
                }
#pragma unroll
                for (int i = 0; i < 2; i++)
#pragma unroll
                    for (int pp = 0; pp < 2; pp++)
#pragma unroll
                        for (int s = 0; s < 2; s++) {
                            int nt = nh * 4 + pp * 2 + s;
                            mma16816(acc[i][nt], ah[i], bh[pp] + s * 2);
                            mma16816(acc[i][nt], ah[i], bl[pp] + s * 2);
                            mma16816(acc[i][nt], al[i], bh[pp] + s * 2);
                        }
            }
        }
        __syncthreads();
    }
}

// Kernel 1: qkv GEMM -> bf16 hi/lo, Q rows pre-scaled
__global__ __launch_bounds__(256, 2) void qkv_gemm_kernel() {
    extern __shared__ char smem[];
    const int b = blockIdx.z;
    const int n0 = blockIdx.x * 128;
    const int m0 = blockIdx.y * 128;
    float acc[2][8][4];
    gemm_main<CC>(gwq_hi, gwq_lo,
                  gx_hi + (size_t)b * CC * NN + n0, gx_lo + (size_t)b * CC * NN + n0,
                  NN, m0, smem, acc);

    const int t = threadIdx.x, wid = t >> 5, lane = t & 31;
    const int wm = (wid & 3) * 32, wn = (wid >> 2) * 64;
    bf16* oh = gqkv_hi + ((size_t)b * OC3 + m0) * NN + n0;
    bf16* ol = gqkv_lo + ((size_t)b * OC3 + m0) * NN + n0;
#pragma unroll
    for (int i = 0; i < 2; i++) {
        int r0 = wm + i * 16 + (lane >> 2);
        float s0 = (m0 + r0 < CC) ? QSCALE_F : 1.f;
        float s8 = (m0 + r0 + 8 < CC) ? QSCALE_F : 1.f;
#pragma unroll
        for (int nt = 0; nt < 8; nt++) {
            int n = wn + nt * 8 + (lane & 3) * 2;
            bf16 h0, l0, h1, l1;
            split_bf16(acc[i][nt][0] * s0, h0, l0);
            split_bf16(acc[i][nt][1] * s0, h1, l1);
            *reinterpret_cast<u32*>(oh + (size_t)r0 * NN + n) = pk_bf(h0, h1);
            *reinterpret_cast<u32*>(ol + (size_t)r0 * NN + n) = pk_bf(l0, l1);
            split_bf16(acc[i][nt][2] * s8, h0, l0);
            split_bf16(acc[i][nt][3] * s8, h1, l1);
            *reinterpret_cast<u32*>(oh + (size_t)(r0 + 8) * NN + n) = pk_bf(h0, h1);
            *reinterpret_cast<u32*>(ol + (size_t)(r0 + 8) * NN + n) = pk_bf(l0, l1);
        }
    }
}

// Kernel 3: proj GEMM + bias -> f32 out
__global__ __launch_bounds__(256, 2) void proj_gemm_kernel(const float* __restrict__ bias,
                                                           float* __restrict__ out) {
    extern __shared__ char smem[];
    const int b = blockIdx.z;
    const int n0 = blockIdx.x * 128;
    const int m0 = blockIdx.y * 128;
    float acc[2][8][4];
    gemm_main<CC>(gwp_hi, gwp_lo,
                  gatt_hi + (size_t)b * CC * NN + n0, gatt_lo + (size_t)b * CC * NN + n0,
                  NN, m0, smem, acc);

    const int t = threadIdx.x, wid = t >> 5, lane = t & 31;
    const int wm = (wid & 3) * 32, wn = (wid >> 2) * 64;
    float* outp = out + ((size_t)b * CC + m0) * NN + n0;
#pragma unroll
    for (int i = 0; i < 2; i++) {
        int r0 = wm + i * 16 + (lane >> 2);
        float b0 = bias[m0 + r0], b8 = bias[m0 + r0 + 8];
#pragma unroll
        for (int nt = 0; nt < 8; nt++) {
            int n = wn + nt * 8 + (lane & 3) * 2;
            float* d0 = outp + (size_t)r0 * NN + n;
            *reinterpret_cast<float2*>(d0) =
                make_float2(acc[i][nt][0] + b0, acc[i][nt][1] + b0);
            *reinterpret_cast<float2*>(d0 + 8 * NN) =
                make_float2(acc[i][nt][2] + b8, acc[i][nt][3] + b8);
        }
    }
}

// ---------------------------------------------------------------------------
// Kernel 2: grouped MHA, cp.async double-buffered K/V, V in [d][key] layout.
// smem: Qs 8KB @0 | stages @8192 + s*16384: Kh,Kl,Vh,Vl (4KB each). Os overlays.
// ---------------------------------------------------------------------------
#define AKH 0
#define AKL 4096
#define AVH 8192
#define AVL 12288

__global__ __launch_bounds__(128) void attn_kernel() {
    __shared__ __align__(16) char sm[8192 + 2 * 16384];
    char* Qs = sm;
    float* Os = reinterpret_cast<float*>(sm + 8192);
    const u32 sb = smem_u32(sm);

    const int t = threadIdx.x, lane = t & 31, wid = t >> 5;
    const int head = blockIdx.y;
    const int b = head >> 6, g = (head >> 3) & 7, hh = head & 7;
    const int nqbase = g * MSEQ + blockIdx.x * 64;
    const size_t qoff = ((size_t)b * OC3 + hh * HD) * NN;
    const bf16* qph = gqkv_hi + qoff;
    const bf16* qpl = gqkv_lo + qoff;
    const bf16* kph = qph + (size_t)CC * NN;
    const bf16* kpl = qpl + (size_t)CC * NN;
    const bf16* vph = qph + (size_t)(2 * CC) * NN;
    const bf16* vpl = qpl + (size_t)(2 * CC) * NN;

    // K/V fill coordinates (fixed per thread): 2 chunk sets
    const int fd0 = t >> 3,          fk8 = (t & 7) * 8;
    const int fd1 = (128 + t) >> 3;
    const u32 fo0 = fd0 * 128 + ((((fk8 >> 3) ^ (fd0 & 7))) << 4);
    const u32 fo1 = fd1 * 128 + ((((fk8 >> 3) ^ (fd1 & 7))) << 4);

    auto fill_kv = [&](int kt, int buf) {
        const int nk = g * MSEQ + kt * 64;
        u32 base = sb + 8192 + buf * 16384;
        size_t s0 = (size_t)fd0 * NN + nk + fk8;
        size_t s1 = (size_t)fd1 * NN + nk + fk8;
        cpa16(base + AKH + fo0, kph + s0);  cpa16(base + AKH + fo1, kph + s1);
        cpa16(base + AKL + fo0, kpl + s0);  cpa16(base + AKL + fo1, kpl + s1);
        cpa16(base + AVH + fo0, vph + s0);  cpa16(base + AVH + fo1, vph + s1);
        cpa16(base + AVL + fo0, vpl + s0);  cpa16(base + AVL + fo1, vpl + s1);
    };

    fill_kv(0, 0); CPA_COMMIT();

    // ---- Q fill: transpose [d][n] -> smem [q][hi|lo]
    {
        int q = t & 63, dh = (t >> 6) * 16;
        const bf16* ph = qph + nqbase + q;
        const bf16* pl = qpl + nqbase + q;
#pragma unroll
        for (int dd = 0; dd < 16; dd += 2) {
            int d = dh + dd;
            u32 base = q * 128 + ((d & 7) * 2);
            st_bf2(Qs, base + ((((d >> 3)    ) ^ (q & 7)) << 4),
                   ph[(size_t)d * NN], ph[(size_t)(d + 1) * NN]);
            st_bf2(Qs, base + ((((d >> 3) + 4) ^ (q & 7)) << 4),
                   pl[(size_t)d * NN], pl[(size_t)(d + 1) * NN]);
        }
    }
    __syncthreads();

    u32 qh[2][4], ql[2][4];
    {
        int row = wid * 16 + (lane & 15);
        u32 qsb = sb + row * 128;
#pragma unroll
        for (int ks = 0; ks < 2; ks++) {
            int kc = ks * 16 + (lane >> 4) * 8;
            ldsm4(qh[ks], qsb + ((((kc >> 3)    ) ^ (row & 7)) << 4));
            ldsm4(ql[ks], qsb + ((((kc >> 3) + 4) ^ (row & 7)) << 4));
        }
    }

    float oacc[4][4];
#pragma unroll
    for (int i = 0; i < 4; i++)
#pragma unroll
        for (int j = 0; j < 4; j++) oacc[i][j] = 0.f;
    float mx0 = -1e30f, mx1 = -1e30f, l0 = 0.f, l1 = 0.f;

    for (int kt = 0; kt < 8; kt++) {
        if (kt + 1 < 8) { fill_kv(kt + 1, (kt + 1) & 1); CPA_COMMIT(); CPA_WAIT1(); }
        else            { CPA_WAIT0(); }
        __syncthreads();
        u32 base = sb + 8192 + (kt & 1) * 16384;

        // ---- S = Q K^T  (K: [d][key] = [k][n] row-major, trans ldsm)
        float sacc[8][4];
#pragma unroll
        for (int i = 0; i < 8; i++)
#pragma unroll
            for (int j = 0; j < 4; j++) sacc[i][j] = 0.f;
#pragma unroll
        for (int ks = 0; ks < 2; ks++) {
            int kd = ks * 16 + ((lane >> 3) & 1) * 8 + (lane & 7);
            u32 krb = kd * 128;
#pragma unroll
            for (int pp = 0; pp < 4; pp++) {
                int nb = pp * 16 + (lane >> 4) * 8;
                u32 off = krb + ((((nb >> 3) ^ (kd & 7))) << 4);
                u32 kbh[4], kbl[4];
                ldsm4t(kbh, base + AKH + off);
                ldsm4t(kbl, base + AKL + off);
#pragma unroll
                for (int s = 0; s < 2; s++) {
                    int f = pp * 2 + s;
                    mma16816(sacc[f], qh[ks], kbh + s * 2);
                    mma16816(sacc[f], qh[ks], kbl + s * 2);
                    mma16816(sacc[f], ql[ks], kbh + s * 2);
                }
            }
        }

        // ---- online softmax
        float rm0 = -1e30f, rm1 = -1e30f;
#pragma unroll
        for (int j = 0; j < 8; j++) {
            rm0 = fmaxf(rm0, fmaxf(sacc[j][0], sacc[j][1]));
            rm1 = fmaxf(rm1, fmaxf(sacc[j][2], sacc[j][3]));
        }
        rm0 = fmaxf(rm0, __shfl_xor_sync(0xffffffffu, rm0, 1));
        rm0 = fmaxf(rm0, __shfl_xor_sync(0xffffffffu, rm0, 2));
        rm1 = fmaxf(rm1, __shfl_xor_sync(0xffffffffu, rm1, 1));
        rm1 = fmaxf(rm1, __shfl_xor_sync(0xffffffffu, rm1, 2));
        float nm0 = fmaxf(mx0, rm0), nm1 = fmaxf(mx1, rm1);
        float c0 = __expf(mx0 - nm0), c1 = __expf(mx1 - nm1);
        mx0 = nm0; mx1 = nm1;
#pragma unroll
        for (int df = 0; df < 4; df++) {
            oacc[df][0] *= c0; oacc[df][1] *= c0;
            oacc[df][2] *= c1; oacc[df][3] *= c1;
        }

        float rs0 = 0.f, rs1 = 0.f;
        u32 aph[4][4], apl[4][4];
#pragma unroll
        for (int j = 0; j < 8; j++) {
            float p0 = __expf(sacc[j][0] - nm0);
            float p1 = __expf(sacc[j][1] - nm0);
            float p2 = __expf(sacc[j][2] - nm1);
            float p3 = __expf(sacc[j][3] - nm1);
            rs0 += p0 + p1; rs1 += p2 + p3;
            bf16 h0, lo0, h1, lo1, h2, lo2, h3, lo3;
            split_bf16(p0, h0, lo0); split_bf16(p1, h1, lo1);
            split_bf16(p2, h2, lo2); split_bf16(p3, h3, lo3);
            int ks = j >> 1, half = (j & 1) * 2;
            aph[ks][half]     = pk_bf(h0, h1);
            aph[ks][half + 1] = pk_bf(h2, h3);
            apl[ks][half]     = pk_bf(lo0, lo1);
            apl[ks][half + 1] = pk_bf(lo2, lo3);
        }
        rs0 += __shfl_xor_sync(0xffffffffu, rs0, 1);
        rs0 += __shfl_xor_sync(0xffffffffu, rs0, 2);
        rs1 += __shfl_xor_sync(0xffffffffu, rs1, 1);
        rs1 += __shfl_xor_sync(0xffffffffu, rs1, 2);
        l0 = l0 * c0 + rs0;
        l1 = l1 * c1 + rs1;

        // ---- O += P V  (V: [d][key] = [n][k] row-major, NON-trans ldsm)
#pragma unroll
        for (int ks = 0; ks < 4; ks++) {
            int kk = ks * 16 + ((lane >> 3) & 1) * 8;
#pragma unroll
            for (int dg = 0; dg < 2; dg++) {
                int dn = dg * 16 + (lane >> 4) * 8 + (lane & 7);
                u32 off = dn * 128 + ((((kk >> 3) ^ (dn & 7))) << 4);
                u32 vbh[4], vbl[4];
                ldsm4(vbh, base + AVH + off);
                ldsm4(vbl, base + AVL + off);
#pragma unroll
                for (int s = 0; s < 2; s++) {
                    int df = dg * 2 + s;
                    mma16816(oacc[df], aph[ks], vbh + s * 2);
                    mma16816(oacc[df], aph[ks], vbl + s * 2);
                    mma16816(oacc[df], apl[ks], vbh + s * 2);
                }
            }
        }
        __syncthreads();
    }

    // ---- epilogue: normalize, stage f32 to smem, split-store to gatt hi/lo
    float inv0 = 1.f / l0, inv1 = 1.f / l1;
    __syncthreads();
    {
        int r = wid * 16 + (lane >> 2);
#pragma unroll
        for (int df = 0; df < 4; df++) {
            int dc = df * 8 + (lane & 3) * 2;
            *reinterpret_cast<float2*>(&Os[r * 34 + dc]) =
                make_float2(oacc[df][0] * inv0, oacc[df][1] * inv0);
            *reinterpret_cast<float2*>(&Os[(r + 8) * 34 + dc]) =
                make_float2(oacc[df][2] * inv1, oacc[df][3] * inv1);
        }
    }
    __syncthreads();
    {
        int d = t >> 2, qg = (t & 3) * 16;
        size_t doff = ((size_t)b * CC + hh * HD + d) * NN + nqbase + qg;
        bf16* dh_ = gatt_hi + doff;
        bf16* dl_ = gatt_lo + doff;
#pragma unroll
        for (int qq = 0; qq < 16; qq += 2) {
            float v0 = Os[(qg + qq) * 34 + d];
            float v1 = Os[(qg + qq + 1) * 34 + d];
            bf16 h0, lo0, h1, lo1;
            split_bf16(v0, h0, lo0); split_bf16(v1, h1, lo1);
            *reinterpret_cast<u32*>(dh_ + qq) = pk_bf(h0, h1);
            *reinterpret_cast<u32*>(dl_ + qq) = pk_bf(lo0, lo1);
        }
    }
}

// ---------------------------------------------------------------------------
extern "C" void kernel_launch(void* const* d_in, const int* in_sizes, int n_in,
                              void* d_out, int out_size) {
    const float* x      = (const float*)d_in[0];
    const float* w_qkv  = (const float*)d_in[1];
    const float* w_proj = (const float*)d_in[2];
    const float* b_proj = (const float*)d_in[3];
    float* out = (float*)d_out;

    cudaFuncSetAttribute(qkv_gemm_kernel, cudaFuncAttributeMaxDynamicSharedMemorySize, SMEM_GEMM);
    cudaFuncSetAttribute(proj_gemm_kernel, cudaFuncAttributeMaxDynamicSharedMemorySize, SMEM_GEMM);

    bf16 *xh, *xl, *wqh, *wql, *wph, *wpl;
    cudaGetSymbolAddress((void**)&xh,  gx_hi);
    cudaGetSymbolAddress((void**)&xl,  gx_lo);
    cudaGetSymbolAddress((void**)&wqh, gwq_hi);
    cudaGetSymbolAddress((void**)&wql, gwq_lo);
    cudaGetSymbolAddress((void**)&wph, gwp_hi);
    cudaGetSymbolAddress((void**)&wpl, gwp_lo);

    split_kernel<<<(BB * CC * NN / 4 + 255) / 256, 256>>>(x, xh, xl, BB * CC * NN / 4);
    split_kernel<<<(OC3 * CC / 4 + 255) / 256, 256>>>(w_qkv, wqh, wql, OC3 * CC / 4);
    split_kernel<<<(CC * CC / 4 + 255) / 256, 256>>>(w_proj, wph, wpl, CC * CC / 4);

    dim3 g1(NN / 128, OC3 / 128, BB);
    qkv_gemm_kernel<<<g1, 256, SMEM_GEMM>>>();

    dim3 g2(MSEQ / 64, BB * GG * NH);
    attn_kernel<<<g2, 128>>>();

    dim3 g3(NN / 128, CC / 128, BB);
    proj_gemm_kernel<<<g3, 256, SMEM_GEMM>>>(b_proj, out);
}

// round 9
// speedup vs baseline: 3.8570x; 1.0212x over previous
#include <cuda_runtime.h>
#include <cuda_bf16.h>

#define BB   4
#define CC   256
#define NN   4096
#define GG   8
#define NH   8
#define HD   32
#define MSEQ 512
#define OC3  768
// 1/sqrt(32) * log2(e): Q pre-scale so softmax runs in log2 domain (ex2)
#define Q2SCALE (0.17677669529663687f * 1.4426950408889634f)

typedef unsigned long long u64;
typedef unsigned int u32;
typedef __nv_bfloat16 bf16;

// ---------------------------------------------------------------- helpers
__device__ __forceinline__ u32 smem_u32(const void* p) {
    u32 a; asm("{.reg .u64 t; cvta.to.shared.u64 t,%1; cvt.u32.u64 %0,t;}" : "=r"(a) : "l"(p));
    return a;
}
__device__ __forceinline__ void cpa16(u32 dst, const void* src) {
    asm volatile("cp.async.cg.shared.global [%0],[%1],16;" :: "r"(dst), "l"(src));
}
#define CPA_COMMIT() asm volatile("cp.async.commit_group;" ::: "memory")
#define CPA_WAIT1()  asm volatile("cp.async.wait_group 1;" ::: "memory")
#define CPA_WAIT0()  asm volatile("cp.async.wait_group 0;" ::: "memory")
__device__ __forceinline__ float ex2f(float x) {
    float r; asm("ex2.approx.f32 %0,%1;" : "=f"(r) : "f"(x)); return r;
}
__device__ __forceinline__ void ldsm4(u32* r, u32 addr) {
    asm volatile("ldmatrix.sync.aligned.m8n8.x4.shared.b16 {%0,%1,%2,%3},[%4];"
                 : "=r"(r[0]), "=r"(r[1]), "=r"(r[2]), "=r"(r[3]) : "r"(addr));
}
__device__ __forceinline__ void ldsm4t(u32* r, u32 addr) {
    asm volatile("ldmatrix.sync.aligned.m8n8.x4.trans.shared.b16 {%0,%1,%2,%3},[%4];"
                 : "=r"(r[0]), "=r"(r[1]), "=r"(r[2]), "=r"(r[3]) : "r"(addr));
}
__device__ __forceinline__ void mma16816(float* d, const u32* a, const u32* b) {
    asm volatile("mma.sync.aligned.m16n8k16.row.col.f32.bf16.bf16.f32 "
                 "{%0,%1,%2,%3},{%4,%5,%6,%7},{%8,%9},{%0,%1,%2,%3};"
                 : "+f"(d[0]), "+f"(d[1]), "+f"(d[2]), "+f"(d[3])
                 : "r"(a[0]), "r"(a[1]), "r"(a[2]), "r"(a[3]), "r"(b[0]), "r"(b[1]));
}
__device__ __forceinline__ void split_bf16(float x, bf16& h, bf16& l) {
    h = __float2bfloat16(x);
    l = __float2bfloat16(x - __bfloat162float(h));
}
__device__ __forceinline__ u32 pk_bf(bf16 a, bf16 b) {
    __nv_bfloat162 t; t.x = a; t.y = b;
    return *reinterpret_cast<u32*>(&t);
}
__device__ __forceinline__ void st_bf2(char* base, u32 off, bf16 a, bf16 b) {
    __nv_bfloat162 t; t.x = a; t.y = b;
    *reinterpret_cast<__nv_bfloat162*>(base + off) = t;
}

// A tile [128 m][32 k] bf16: 64B rows, 4-chunk swizzle
__device__ __forceinline__ u32 a32_off(int m, int k8) {
    return m * 64 + ((((k8 >> 3) ^ ((m >> 1) & 3)) & 3) << 4);
}
// B tile [32 k][128 n] bf16: 256B rows, 8-chunk swizzle
__device__ __forceinline__ u32 b32_off(int k, int n8) {
    return k * 256 + ((((n8 >> 3) ^ (k & 7))) << 4);
}

#define ST_A_HI 0
#define ST_A_LO 8192
#define ST_B_HI 16384
#define ST_B_LO 24576
#define STAGE_SZ 32768
#define SMEM_GEMM (3 * STAGE_SZ)        // 98304, 3-stage

// ---------------- persistent bf16 hi/lo buffers
__device__ __align__(128) bf16 gx_hi[(size_t)BB * CC * NN];
__device__ __align__(128) bf16 gx_lo[(size_t)BB * CC * NN];
__device__ __align__(128) bf16 gwq_hi[OC3 * CC];
__device__ __align__(128) bf16 gwq_lo[OC3 * CC];
__device__ __align__(128) bf16 gwp_hi[CC * CC];
__device__ __align__(128) bf16 gwp_lo[CC * CC];
__device__ __align__(128) bf16 gqkv_hi[(size_t)BB * OC3 * NN];   // Q pre-scaled by Q2SCALE
__device__ __align__(128) bf16 gqkv_lo[(size_t)BB * OC3 * NN];
__device__ __align__(128) bf16 gatt_hi[(size_t)BB * CC * NN];
__device__ __align__(128) bf16 gatt_lo[(size_t)BB * CC * NN];

// ---------------------------------------------------------------------------
__global__ __launch_bounds__(256) void split_kernel(const float* __restrict__ src,
                                                    bf16* __restrict__ hi,
                                                    bf16* __restrict__ lo, int n4) {
    int i = blockIdx.x * blockDim.x + threadIdx.x;
    if (i >= n4) return;
    float4 v = reinterpret_cast<const float4*>(src)[i];
    bf16 h0, l0, h1, l1, h2, l2, h3, l3;
    split_bf16(v.x, h0, l0); split_bf16(v.y, h1, l1);
    split_bf16(v.z, h2, l2); split_bf16(v.w, h3, l3);
    reinterpret_cast<uint2*>(hi)[i] = make_uint2(pk_bf(h0, h1), pk_bf(h2, h3));
    reinterpret_cast<uint2*>(lo)[i] = make_uint2(pk_bf(l0, l1), pk_bf(l2, l3));
}

// ---------------------------------------------------------------------------
// GEMM mainloop: 3-stage cp.async pipeline, K-chunks of 32, 1 barrier/chunk.
// ---------------------------------------------------------------------------
template<int KDIM>
__device__ __forceinline__ void gemm_main(const bf16* __restrict__ Ah, const bf16* __restrict__ Al,
                                          const bf16* __restrict__ Bh, const bf16* __restrict__ Bl,
                                          size_t ldb, int m0, char* smem,
                                          float (&acc)[2][8][4]) {
    const u32 sb = smem_u32(smem);
    const int t = threadIdx.x;
    const int wid = t >> 5, lane = t & 31;
    const int wm = (wid & 3) * 32;
    const int wn = (wid >> 2) * 64;
    constexpr int NCH = KDIM / 32;

#pragma unroll
    for (int i = 0; i < 2; i++)
#pragma unroll
        for (int j = 0; j < 8; j++)
#pragma unroll
            for (int c = 0; c < 4; c++) acc[i][j][c] = 0.f;

    const int am0 = t >> 2,         ak8 = (t & 3) * 8;
    const int am1 = (256 + t) >> 2, bk0 = t >> 4;
    const int bn8 = (t & 15) * 8,   bk1 = (256 + t) >> 4;

    auto fill = [&](int c0, int buf) {
        u32 base = sb + buf * STAGE_SZ;
        {
            u32 o0 = base + a32_off(am0, ak8), o1 = base + a32_off(am1, ak8);
            size_t s0 = (size_t)(m0 + am0) * KDIM + c0 + ak8;
            size_t s1 = (size_t)(m0 + am1) * KDIM + c0 + ak8;
            cpa16(o0 + ST_A_HI, Ah + s0);  cpa16(o1 + ST_A_HI, Ah + s1);
            cpa16(o0 + ST_A_LO, Al + s0);  cpa16(o1 + ST_A_LO, Al + s1);
        }
        {
            u32 o0 = base + b32_off(bk0, bn8), o1 = base + b32_off(bk1, bn8);
            size_t s0 = (size_t)(c0 + bk0) * ldb + bn8;
            size_t s1 = (size_t)(c0 + bk1) * ldb + bn8;
            cpa16(o0 + ST_B_HI, Bh + s0);  cpa16(o1 + ST_B_HI, Bh + s1);
            cpa16(o0 + ST_B_LO, Bl + s0);  cpa16(o1 + ST_B_LO, Bl + s1);
        }
    };

    fill(0, 0);  CPA_COMMIT();
    fill(32, 1); CPA_COMMIT();

    for (int ch = 0; ch < NCH; ch++) {
        if (ch == NCH - 1) { CPA_WAIT0(); } else { CPA_WAIT1(); }
        __syncthreads();
        if (ch + 2 < NCH) { fill((ch + 2) * 32, (ch + 2) % 3); CPA_COMMIT(); }
        u32 base = sb + (ch % 3) * STAGE_SZ;

#pragma unroll
        for (int ks = 0; ks < 2; ks++) {
            u32 ah[2][4], al[2][4];
#pragma unroll
            for (int i = 0; i < 2; i++) {
                int row = wm + i * 16 + (lane & 15);
                int kc  = ks * 16 + (lane >> 4) * 8;
                u32 ao = row * 64 + ((((kc >> 3) ^ ((row >> 1) & 3)) & 3) << 4);
                ldsm4(ah[i], base + ST_A_HI + ao);
                ldsm4(al[i], base + ST_A_LO + ao);
            }
#pragma unroll
            for (int nh = 0; nh < 2; nh++) {
                u32 bh[2][4], bl[2][4];
#pragma unroll
                for (int pp = 0; pp < 2; pp++) {
                    int k = ks * 16 + ((lane >> 3) & 1) * 8 + (lane & 7);
                    int nb = wn + nh * 32 + pp * 16 + (lane >> 4) * 8;
                    u32 bo = k * 256 + ((((nb >> 3) ^ (k & 7))) << 4);
                    ldsm4t(bh[pp], base + ST_B_HI + bo);
                    ldsm4t(bl[pp], base + ST_B_LO + bo);
                }
#pragma unroll
                for (int i = 0; i < 2; i++)
#pragma unroll
                    for (int pp = 0; pp < 2; pp++)
#pragma unroll
                        for (int s = 0; s < 2; s++) {
                            int nt = nh * 4 + pp * 2 + s;
                            mma16816(acc[i][nt], ah[i], bh[pp] + s * 2);
                            mma16816(acc[i][nt], ah[i], bl[pp] + s * 2);
                            mma16816(acc[i][nt], al[i], bh[pp] + s * 2);
                        }
            }
        }
    }
}

// Kernel 1: qkv GEMM -> bf16 hi/lo, Q rows pre-scaled by Q2SCALE (log2-domain softmax)
__global__ __launch_bounds__(256, 2) void qkv_gemm_kernel() {
    extern __shared__ char smem[];
    const int b = blockIdx.z;
    const int n0 = blockIdx.x * 128;
    const int m0 = blockIdx.y * 128;
    float acc[2][8][4];
    gemm_main<CC>(gwq_hi, gwq_lo,
                  gx_hi + (size_t)b * CC * NN + n0, gx_lo + (size_t)b * CC * NN + n0,
                  NN, m0, smem, acc);

    const int t = threadIdx.x, wid = t >> 5, lane = t & 31;
    const int wm = (wid & 3) * 32, wn = (wid >> 2) * 64;
    bf16* oh = gqkv_hi + ((size_t)b * OC3 + m0) * NN + n0;
    bf16* ol = gqkv_lo + ((size_t)b * OC3 + m0) * NN + n0;
#pragma unroll
    for (int i = 0; i < 2; i++) {
        int r0 = wm + i * 16 + (lane >> 2);
        float s0 = (m0 + r0 < CC) ? Q2SCALE : 1.f;
        float s8 = (m0 + r0 + 8 < CC) ? Q2SCALE : 1.f;
#pragma unroll
        for (int nt = 0; nt < 8; nt++) {
            int n = wn + nt * 8 + (lane & 3) * 2;
            bf16 h0, l0, h1, l1;
            split_bf16(acc[i][nt][0] * s0, h0, l0);
            split_bf16(acc[i][nt][1] * s0, h1, l1);
            *reinterpret_cast<u32*>(oh + (size_t)r0 * NN + n) = pk_bf(h0, h1);
            *reinterpret_cast<u32*>(ol + (size_t)r0 * NN + n) = pk_bf(l0, l1);
            split_bf16(acc[i][nt][2] * s8, h0, l0);
            split_bf16(acc[i][nt][3] * s8, h1, l1);
            *reinterpret_cast<u32*>(oh + (size_t)(r0 + 8) * NN + n) = pk_bf(h0, h1);
            *reinterpret_cast<u32*>(ol + (size_t)(r0 + 8) * NN + n) = pk_bf(l0, l1);
        }
    }
}

// Kernel 3: proj GEMM + bias -> f32 out
__global__ __launch_bounds__(256, 2) void proj_gemm_kernel(const float* __restrict__ bias,
                                                           float* __restrict__ out) {
    extern __shared__ char smem[];
    const int b = blockIdx.z;
    const int n0 = blockIdx.x * 128;
    const int m0 = blockIdx.y * 128;
    float acc[2][8][4];
    gemm_main<CC>(gwp_hi, gwp_lo,
                  gatt_hi + (size_t)b * CC * NN + n0, gatt_lo + (size_t)b * CC * NN + n0,
                  NN, m0, smem, acc);

    const int t = threadIdx.x, wid = t >> 5, lane = t & 31;
    const int wm = (wid & 3) * 32, wn = (wid >> 2) * 64;
    float* outp = out + ((size_t)b * CC + m0) * NN + n0;
#pragma unroll
    for (int i = 0; i < 2; i++) {
        int r0 = wm + i * 16 + (lane >> 2);
        float b0 = bias[m0 + r0], b8 = bias[m0 + r0 + 8];
#pragma unroll
        for (int nt = 0; nt < 8; nt++) {
            int n = wn + nt * 8 + (lane & 3) * 2;
            float* d0 = outp + (size_t)r0 * NN + n;
            *reinterpret_cast<float2*>(d0) =
                make_float2(acc[i][nt][0] + b0, acc[i][nt][1] + b0);
            *reinterpret_cast<float2*>(d0 + 8 * NN) =
                make_float2(acc[i][nt][2] + b8, acc[i][nt][3] + b8);
        }
    }
}

// ---------------------------------------------------------------------------
// Kernel 2: grouped MHA, 3-stage cp.async K/V, log2-domain softmax (ex2).
// dyn smem: Qs 8KB @0 | stages @8192 + s*16384 (Kh,Kl,Vh,Vl 4KB each). Os overlays.
// ---------------------------------------------------------------------------
#define AKH 0
#define AKL 4096
#define AVH 8192
#define AVL 12288
#define SMEM_ATT (8192 + 3 * 16384)     // 57344

__global__ __launch_bounds__(128) void attn_kernel() {
    extern __shared__ char sm[];
    char* Qs = sm;
    float* Os = reinterpret_cast<float*>(sm + 8192);
    const u32 sb = smem_u32(sm);

    const int t = threadIdx.x, lane = t & 31, wid = t >> 5;
    const int head = blockIdx.y;
    const int b = head >> 6, g = (head >> 3) & 7, hh = head & 7;
    const int nqbase = g * MSEQ + blockIdx.x * 64;
    const size_t qoff = ((size_t)b * OC3 + hh * HD) * NN;
    const bf16* qph = gqkv_hi + qoff;
    const bf16* qpl = gqkv_lo + qoff;
    const bf16* kph = qph + (size_t)CC * NN;
    const bf16* kpl = qpl + (size_t)CC * NN;
    const bf16* vph = qph + (size_t)(2 * CC) * NN;
    const bf16* vpl = qpl + (size_t)(2 * CC) * NN;

    const int fd0 = t >> 3,          fk8 = (t & 7) * 8;
    const int fd1 = (128 + t) >> 3;
    const u32 fo0 = fd0 * 128 + ((((fk8 >> 3) ^ (fd0 & 7))) << 4);
    const u32 fo1 = fd1 * 128 + ((((fk8 >> 3) ^ (fd1 & 7))) << 4);

    auto fill_kv = [&](int kt, int buf) {
        const int nk = g * MSEQ + kt * 64;
        u32 base = sb + 8192 + buf * 16384;
        size_t s0 = (size_t)fd0 * NN + nk + fk8;
        size_t s1 = (size_t)fd1 * NN + nk + fk8;
        cpa16(base + AKH + fo0, kph + s0);  cpa16(base + AKH + fo1, kph + s1);
        cpa16(base + AKL + fo0, kpl + s0);  cpa16(base + AKL + fo1, kpl + s1);
        cpa16(base + AVH + fo0, vph + s0);  cpa16(base + AVH + fo1, vph + s1);
        cpa16(base + AVL + fo0, vpl + s0);  cpa16(base + AVL + fo1, vpl + s1);
    };

    fill_kv(0, 0); CPA_COMMIT();
    fill_kv(1, 1); CPA_COMMIT();

    // ---- Q fill: transpose [d][n] -> smem [q][hi|lo]
    {
        int q = t & 63, dh = (t >> 6) * 16;
        const bf16* ph = qph + nqbase + q;
        const bf16* pl = qpl + nqbase + q;
#pragma unroll
        for (int dd = 0; dd < 16; dd += 2) {
            int d = dh + dd;
            u32 base = q * 128 + ((d & 7) * 2);
            st_bf2(Qs, base + ((((d >> 3)    ) ^ (q & 7)) << 4),
                   ph[(size_t)d * NN], ph[(size_t)(d + 1) * NN]);
            st_bf2(Qs, base + ((((d >> 3) + 4) ^ (q & 7)) << 4),
                   pl[(size_t)d * NN], pl[(size_t)(d + 1) * NN]);
        }
    }
    __syncthreads();

    u32 qh[2][4], ql[2][4];
    {
        int row = wid * 16 + (lane & 15);
        u32 qsb = sb + row * 128;
#pragma unroll
        for (int ks = 0; ks < 2; ks++) {
            int kc = ks * 16 + (lane >> 4) * 8;
            ldsm4(qh[ks], qsb + ((((kc >> 3)    ) ^ (row & 7)) << 4));
            ldsm4(ql[ks], qsb + ((((kc >> 3) + 4) ^ (row & 7)) << 4));
        }
    }

    float oacc[4][4];
#pragma unroll
    for (int i = 0; i < 4; i++)
#pragma unroll
        for (int j = 0; j < 4; j++) oacc[i][j] = 0.f;
    float mx0 = -1e30f, mx1 = -1e30f, l0 = 0.f, l1 = 0.f;

    for (int kt = 0; kt < 8; kt++) {
        if (kt == 7) { CPA_WAIT0(); } else { CPA_WAIT1(); }
        __syncthreads();
        if (kt + 2 < 8) { fill_kv(kt + 2, (kt + 2) % 3); CPA_COMMIT(); }
        u32 base = sb + 8192 + (kt % 3) * 16384;

        // ---- S = Q K^T (log2-domain scores; Q pre-scaled by Q2SCALE)
        float sacc[8][4];
#pragma unroll
        for (int i = 0; i < 8; i++)
#pragma unroll
            for (int j = 0; j < 4; j++) sacc[i][j] = 0.f;
#pragma unroll
        for (int ks = 0; ks < 2; ks++) {
            int kd = ks * 16 + ((lane >> 3) & 1) * 8 + (lane & 7);
            u32 krb = kd * 128;
#pragma unroll
            for (int pp = 0; pp < 4; pp++) {
                int nb = pp * 16 + (lane >> 4) * 8;
                u32 off = krb + ((((nb >> 3) ^ (kd & 7))) << 4);
                u32 kbh[4], kbl[4];
                ldsm4t(kbh, base + AKH + off);
                ldsm4t(kbl, base + AKL + off);
#pragma unroll
                for (int s = 0; s < 2; s++) {
                    int f = pp * 2 + s;
                    mma16816(sacc[f], qh[ks], kbh + s * 2);
                    mma16816(sacc[f], qh[ks], kbl + s * 2);
                    mma16816(sacc[f], ql[ks], kbh + s * 2);
                }
            }
        }

        // ---- online softmax (base-2)
        float rm0 = -1e30f, rm1 = -1e30f;
#pragma unroll
        for (int j = 0; j < 8; j++) {
            rm0 = fmaxf(rm0, fmaxf(sacc[j][0], sacc[j][1]));
            rm1 = fmaxf(rm1, fmaxf(sacc[j][2], sacc[j][3]));
        }
        rm0 = fmaxf(rm0, __shfl_xor_sync(0xffffffffu, rm0, 1));
        rm0 = fmaxf(rm0, __shfl_xor_sync(0xffffffffu, rm0, 2));
        rm1 = fmaxf(rm1, __shfl_xor_sync(0xffffffffu, rm1, 1));
        rm1 = fmaxf(rm1, __shfl_xor_sync(0xffffffffu, rm1, 2));
        float nm0 = fmaxf(mx0, rm0), nm1 = fmaxf(mx1, rm1);
        float c0 = ex2f(mx0 - nm0), c1 = ex2f(mx1 - nm1);
        mx0 = nm0; mx1 = nm1;
#pragma unroll
        for (int df = 0; df < 4; df++) {
            oacc[df][0] *= c0; oacc[df][1] *= c0;
            oacc[df][2] *= c1; oacc[df][3] *= c1;
        }

        float rs0 = 0.f, rs1 = 0.f;
        u32 aph[4][4], apl[4][4];
#pragma unroll
        for (int j = 0; j < 8; j++) {
            float p0 = ex2f(sacc[j][0] - nm0);
            float p1 = ex2f(sacc[j][1] - nm0);
            float p2 = ex2f(sacc[j][2] - nm1);
            float p3 = ex2f(sacc[j][3] - nm1);
            rs0 += p0 + p1; rs1 += p2 + p3;
            bf16 h0, lo0, h1, lo1, h2, lo2, h3, lo3;
            split_bf16(p0, h0, lo0); split_bf16(p1, h1, lo1);
            split_bf16(p2, h2, lo2); split_bf16(p3, h3, lo3);
            int ks = j >> 1, half = (j & 1) * 2;
            aph[ks][half]     = pk_bf(h0, h1);
            aph[ks][half + 1] = pk_bf(h2, h3);
            apl[ks][half]     = pk_bf(lo0, lo1);
            apl[ks][half + 1] = pk_bf(lo2, lo3);
        }
        rs0 += __shfl_xor_sync(0xffffffffu, rs0, 1);
        rs0 += __shfl_xor_sync(0xffffffffu, rs0, 2);
        rs1 += __shfl_xor_sync(0xffffffffu, rs1, 1);
        rs1 += __shfl_xor_sync(0xffffffffu, rs1, 2);
        l0 = l0 * c0 + rs0;
        l1 = l1 * c1 + rs1;

        // ---- O += P V  (V in [d][key], NON-trans ldsm)
#pragma unroll
        for (int ks = 0; ks < 4; ks++) {
            int kk = ks * 16 + ((lane >> 3) & 1) * 8;
#pragma unroll
            for (int dg = 0; dg < 2; dg++) {
                int dn = dg * 16 + (lane >> 4) * 8 + (lane & 7);
                u32 off = dn * 128 + ((((kk >> 3) ^ (dn & 7))) << 4);
                u32 vbh[4], vbl[4];
                ldsm4(vbh, base + AVH + off);
                ldsm4(vbl, base + AVL + off);
#pragma unroll
                for (int s = 0; s < 2; s++) {
                    int df = dg * 2 + s;
                    mma16816(oacc[df], aph[ks], vbh + s * 2);
                    mma16816(oacc[df], aph[ks], vbl + s * 2);
                    mma16816(oacc[df], apl[ks], vbh + s * 2);
                }
            }
        }
    }

    // ---- epilogue: normalize, stage f32 to smem, split-store to gatt hi/lo
    float inv0 = 1.f / l0, inv1 = 1.f / l1;
    __syncthreads();
    {
        int r = wid * 16 + (lane >> 2);
#pragma unroll
        for (int df = 0; df < 4; df++) {
            int dc = df * 8 + (lane & 3) * 2;
            *reinterpret_cast<float2*>(&Os[r * 34 + dc]) =
                make_float2(oacc[df][0] * inv0, oacc[df][1] * inv0);
            *reinterpret_cast<float2*>(&Os[(r + 8) * 34 + dc]) =
                make_float2(oacc[df][2] * inv1, oacc[df][3] * inv1);
        }
    }
    __syncthreads();
    {
        int d = t >> 2, qg = (t & 3) * 16;
        size_t doff = ((size_t)b * CC + hh * HD + d) * NN + nqbase + qg;
        bf16* dh_ = gatt_hi + doff;
        bf16* dl_ = gatt_lo + doff;
#pragma unroll
        for (int qq = 0; qq < 16; qq += 2) {
            float v0 = Os[(qg + qq) * 34 + d];
            float v1 = Os[(qg + qq + 1) * 34 + d];
            bf16 h0, lo0, h1, lo1;
            split_bf16(v0, h0, lo0); split_bf16(v1, h1, lo1);
            *reinterpret_cast<u32*>(dh_ + qq) = pk_bf(h0, h1);
            *reinterpret_cast<u32*>(dl_ + qq) = pk_bf(lo0, lo1);
        }
    }
}

// ---------------------------------------------------------------------------
extern "C" void kernel_launch(void* const* d_in, const int* in_sizes, int n_in,
                              void* d_out, int out_size) {
    const float* x      = (const float*)d_in[0];
    const float* w_qkv  = (const float*)d_in[1];
    const float* w_proj = (const float*)d_in[2];
    const float* b_proj = (const float*)d_in[3];
    float* out = (float*)d_out;

    cudaFuncSetAttribute(qkv_gemm_kernel, cudaFuncAttributeMaxDynamicSharedMemorySize, SMEM_GEMM);
    cudaFuncSetAttribute(proj_gemm_kernel, cudaFuncAttributeMaxDynamicSharedMemorySize, SMEM_GEMM);
    cudaFuncSetAttribute(attn_kernel, cudaFuncAttributeMaxDynamicSharedMemorySize, SMEM_ATT);

    bf16 *xh, *xl, *wqh, *wql, *wph, *wpl;
    cudaGetSymbolAddress((void**)&xh,  gx_hi);
    cudaGetSymbolAddress((void**)&xl,  gx_lo);
    cudaGetSymbolAddress((void**)&wqh, gwq_hi);
    cudaGetSymbolAddress((void**)&wql, gwq_lo);
    cudaGetSymbolAddress((void**)&wph, gwp_hi);
    cudaGetSymbolAddress((void**)&wpl, gwp_lo);

    split_kernel<<<(BB * CC * NN / 4 + 255) / 256, 256>>>(x, xh, xl, BB * CC * NN / 4);
    split_kernel<<<(OC3 * CC / 4 + 255) / 256, 256>>>(w_qkv, wqh, wql, OC3 * CC / 4);
    split_kernel<<<(CC * CC / 4 + 255) / 256, 256>>>(w_proj, wph, wpl, CC * CC / 4);

    dim3 g1(NN / 128, OC3 / 128, BB);
    qkv_gemm_kernel<<<g1, 256, SMEM_GEMM>>>();

    dim3 g2(MSEQ / 64, BB * GG * NH);
    attn_kernel<<<g2, 128, SMEM_ATT>>>();

    dim3 g3(NN / 128, CC / 128, BB);
    proj_gemm_kernel<<<g3, 256, SMEM_GEMM>>>(b_proj, out);
}

// round 10
// speedup vs baseline: 4.9732x; 1.2894x over previous
#include <cuda_runtime.h>
#include <cuda_fp16.h>

#define BB   4
#define CC   256
#define NN   4096
#define GG   8
#define NH   8
#define HD   32
#define MSEQ 512
#define OC3  768
// 1/sqrt(32) * log2(e): Q pre-scale so softmax runs in log2 domain (ex2)
#define Q2SCALE (0.17677669529663687f * 1.4426950408889634f)

typedef unsigned long long u64;
typedef unsigned int u32;
typedef __half f16;

// ---------------------------------------------------------------- helpers
__device__ __forceinline__ u32 smem_u32(const void* p) {
    u32 a; asm("{.reg .u64 t; cvta.to.shared.u64 t,%1; cvt.u32.u64 %0,t;}" : "=r"(a) : "l"(p));
    return a;
}
__device__ __forceinline__ void cpa16(u32 dst, const void* src) {
    asm volatile("cp.async.cg.shared.global [%0],[%1],16;" :: "r"(dst), "l"(src));
}
#define CPA_COMMIT() asm volatile("cp.async.commit_group;" ::: "memory")
#define CPA_WAIT1()  asm volatile("cp.async.wait_group 1;" ::: "memory")
#define CPA_WAIT0()  asm volatile("cp.async.wait_group 0;" ::: "memory")
__device__ __forceinline__ float ex2f(float x) {
    float r; asm("ex2.approx.f32 %0,%1;" : "=f"(r) : "f"(x)); return r;
}
__device__ __forceinline__ void ldsm4(u32* r, u32 addr) {
    asm volatile("ldmatrix.sync.aligned.m8n8.x4.shared.b16 {%0,%1,%2,%3},[%4];"
                 : "=r"(r[0]), "=r"(r[1]), "=r"(r[2]), "=r"(r[3]) : "r"(addr));
}
__device__ __forceinline__ void ldsm4t(u32* r, u32 addr) {
    asm volatile("ldmatrix.sync.aligned.m8n8.x4.trans.shared.b16 {%0,%1,%2,%3},[%4];"
                 : "=r"(r[0]), "=r"(r[1]), "=r"(r[2]), "=r"(r[3]) : "r"(addr));
}
__device__ __forceinline__ void mma16816(float* d, const u32* a, const u32* b) {
    asm volatile("mma.sync.aligned.m16n8k16.row.col.f32.f16.f16.f32 "
                 "{%0,%1,%2,%3},{%4,%5,%6,%7},{%8,%9},{%0,%1,%2,%3};"
                 : "+f"(d[0]), "+f"(d[1]), "+f"(d[2]), "+f"(d[3])
                 : "r"(a[0]), "r"(a[1]), "r"(a[2]), "r"(a[3]), "r"(b[0]), "r"(b[1]));
}
__device__ __forceinline__ void split_f16(float x, f16& h, f16& l) {
    h = __float2half(x);
    l = __float2half(x - __half2float(h));
}
__device__ __forceinline__ u32 pk_h(f16 a, f16 b) {
    __half2 t; t.x = a; t.y = b;
    return *reinterpret_cast<u32*>(&t);
}
__device__ __forceinline__ void st_h2(char* base, u32 off, f16 a, f16 b) {
    __half2 t; t.x = a; t.y = b;
    *reinterpret_cast<__half2*>(base + off) = t;
}

// A tile [128 m][32 k] f16: 64B rows, 4-chunk swizzle
__device__ __forceinline__ u32 a32_off(int m, int k8) {
    return m * 64 + ((((k8 >> 3) ^ ((m >> 1) & 3)) & 3) << 4);
}
// B tile [32 k][128 n] f16: 256B rows, 8-chunk swizzle
__device__ __forceinline__ u32 b32_off(int k, int n8) {
    return k * 256 + ((((n8 >> 3) ^ (k & 7))) << 4);
}

#define ST_A    0
#define ST_B_HI 8192
#define ST_B_LO 16384
#define STAGE_SZ 24576
#define SMEM_GEMM (3 * STAGE_SZ)        // 73728, 3-stage

// ---------------- persistent f16 hi/lo buffers
__device__ __align__(128) f16 gx_hi[(size_t)BB * CC * NN];
__device__ __align__(128) f16 gx_lo[(size_t)BB * CC * NN];
__device__ __align__(128) f16 gwq_hi[OC3 * CC];          // weights: hi used as mma-A
__device__ __align__(128) f16 gwp_hi[CC * CC];
__device__ __align__(128) f16 gqkv_hi[(size_t)BB * OC3 * NN];   // Q pre-scaled by Q2SCALE
__device__ __align__(128) f16 gqkv_lo[(size_t)BB * OC3 * NN];
__device__ __align__(128) f16 gatt_hi[(size_t)BB * CC * NN];
__device__ __align__(128) f16 gatt_lo[(size_t)BB * CC * NN];

// ---------------------------------------------------------------------------
// Prepass: f32 -> (hi, lo) f16 split (lo may be null: hi-only, for weights)
// ---------------------------------------------------------------------------
__global__ __launch_bounds__(256) void split_kernel(const float* __restrict__ src,
                                                    f16* __restrict__ hi,
                                                    f16* __restrict__ lo, int n4) {
    int i = blockIdx.x * blockDim.x + threadIdx.x;
    if (i >= n4) return;
    float4 v = reinterpret_cast<const float4*>(src)[i];
    f16 h0, l0, h1, l1, h2, l2, h3, l3;
    split_f16(v.x, h0, l0); split_f16(v.y, h1, l1);
    split_f16(v.z, h2, l2); split_f16(v.w, h3, l3);
    reinterpret_cast<uint2*>(hi)[i] = make_uint2(pk_h(h0, h1), pk_h(h2, h3));
    if (lo)
        reinterpret_cast<uint2*>(lo)[i] = make_uint2(pk_h(l0, l1), pk_h(l2, l3));
}

// ---------------------------------------------------------------------------
// GEMM mainloop: 3-stage cp.async, K-chunks of 32.
// A (weights) hi-only; B hi+lo. D = Ah*Bh + Ah*Bl (2-product fp16).
// ---------------------------------------------------------------------------
template<int KDIM>
__device__ __forceinline__ void gemm_main(const f16* __restrict__ Ah,
                                          const f16* __restrict__ Bh, const f16* __restrict__ Bl,
                                          size_t ldb, int m0, char* smem,
                                          float (&acc)[2][8][4]) {
    const u32 sb = smem_u32(smem);
    const int t = threadIdx.x;
    const int wid = t >> 5, lane = t & 31;
    const int wm = (wid & 3) * 32;
    const int wn = (wid >> 2) * 64;
    constexpr int NCH = KDIM / 32;

#pragma unroll
    for (int i = 0; i < 2; i++)
#pragma unroll
        for (int j = 0; j < 8; j++)
#pragma unroll
            for (int c = 0; c < 4; c++) acc[i][j][c] = 0.f;

    const int am0 = t >> 2,         ak8 = (t & 3) * 8;
    const int am1 = (256 + t) >> 2, bk0 = t >> 4;
    const int bn8 = (t & 15) * 8,   bk1 = (256 + t) >> 4;

    auto fill = [&](int c0, int buf) {
        u32 base = sb + buf * STAGE_SZ;
        {
            u32 o0 = base + a32_off(am0, ak8), o1 = base + a32_off(am1, ak8);
            cpa16(o0 + ST_A, Ah + (size_t)(m0 + am0) * KDIM + c0 + ak8);
            cpa16(o1 + ST_A, Ah + (size_t)(m0 + am1) * KDIM + c0 + ak8);
        }
        {
            u32 o0 = base + b32_off(bk0, bn8), o1 = base + b32_off(bk1, bn8);
            size_t s0 = (size_t)(c0 + bk0) * ldb + bn8;
            size_t s1 = (size_t)(c0 + bk1) * ldb + bn8;
            cpa16(o0 + ST_B_HI, Bh + s0);  cpa16(o1 + ST_B_HI, Bh + s1);
            cpa16(o0 + ST_B_LO, Bl + s0);  cpa16(o1 + ST_B_LO, Bl + s1);
        }
    };

    fill(0, 0);  CPA_COMMIT();
    fill(32, 1); CPA_COMMIT();

    for (int ch = 0; ch < NCH; ch++) {
        if (ch == NCH - 1) { CPA_WAIT0(); } else { CPA_WAIT1(); }
        __syncthreads();
        if (ch + 2 < NCH) { fill((ch + 2) * 32, (ch + 2) % 3); CPA_COMMIT(); }
        u32 base = sb + (ch % 3) * STAGE_SZ;

#pragma unroll
        for (int ks = 0; ks < 2; ks++) {
            u32 ah[2][4];
#pragma unroll
            for (int i = 0; i < 2; i++) {
                int row = wm + i * 16 + (lane & 15);
                int kc  = ks * 16 + (lane >> 4) * 8;
                u32 ao = row * 64 + ((((kc >> 3) ^ ((row >> 1) & 3)) & 3) << 4);
                ldsm4(ah[i], base + ST_A + ao);
            }
#pragma unroll
            for (int nh = 0; nh < 2; nh++) {
                u32 bh[2][4], bl[2][4];
#pragma unroll
                for (int pp = 0; pp < 2; pp++) {
                    int k = ks * 16 + ((lane >> 3) & 1) * 8 + (lane & 7);
                    int nb = wn + nh * 32 + pp * 16 + (lane >> 4) * 8;
                    u32 bo = k * 256 + ((((nb >> 3) ^ (k & 7))) << 4);
                    ldsm4t(bh[pp], base + ST_B_HI + bo);
                    ldsm4t(bl[pp], base + ST_B_LO + bo);
                }
#pragma unroll
                for (int i = 0; i < 2; i++)
#pragma unroll
                    for (int pp = 0; pp < 2; pp++)
#pragma unroll
                        for (int s = 0; s < 2; s++) {
                            int nt = nh * 4 + pp * 2 + s;
                            mma16816(acc[i][nt], ah[i], bh[pp] + s * 2);
                            mma16816(acc[i][nt], ah[i], bl[pp] + s * 2);
                        }
            }
        }
    }
}

// Kernel 1: qkv GEMM -> f16 hi/lo, Q rows pre-scaled by Q2SCALE
__global__ __launch_bounds__(256, 2) void qkv_gemm_kernel() {
    extern __shared__ char smem[];
    const int b = blockIdx.z;
    const int n0 = blockIdx.x * 128;
    const int m0 = blockIdx.y * 128;
    float acc[2][8][4];
    gemm_main<CC>(gwq_hi,
                  gx_hi + (size_t)b * CC * NN + n0, gx_lo + (size_t)b * CC * NN + n0,
                  NN, m0, smem, acc);

    const int t = threadIdx.x, wid = t >> 5, lane = t & 31;
    const int wm = (wid & 3) * 32, wn = (wid >> 2) * 64;
    f16* oh = gqkv_hi + ((size_t)b * OC3 + m0) * NN + n0;
    f16* ol = gqkv_lo + ((size_t)b * OC3 + m0) * NN + n0;
#pragma unroll
    for (int i = 0; i < 2; i++) {
        int r0 = wm + i * 16 + (lane >> 2);
        float s0 = (m0 + r0 < CC) ? Q2SCALE : 1.f;
        float s8 = (m0 + r0 + 8 < CC) ? Q2SCALE : 1.f;
#pragma unroll
        for (int nt = 0; nt < 8; nt++) {
            int n = wn + nt * 8 + (lane & 3) * 2;
            f16 h0, l0, h1, l1;
            split_f16(acc[i][nt][0] * s0, h0, l0);
            split_f16(acc[i][nt][1] * s0, h1, l1);
            *reinterpret_cast<u32*>(oh + (size_t)r0 * NN + n) = pk_h(h0, h1);
            *reinterpret_cast<u32*>(ol + (size_t)r0 * NN + n) = pk_h(l0, l1);
            split_f16(acc[i][nt][2] * s8, h0, l0);
            split_f16(acc[i][nt][3] * s8, h1, l1);
            *reinterpret_cast<u32*>(oh + (size_t)(r0 + 8) * NN + n) = pk_h(h0, h1);
            *reinterpret_cast<u32*>(ol + (size_t)(r0 + 8) * NN + n) = pk_h(l0, l1);
        }
    }
}

// Kernel 3: proj GEMM + bias -> f32 out
__global__ __launch_bounds__(256, 2) void proj_gemm_kernel(const float* __restrict__ bias,
                                                           float* __restrict__ out) {
    extern __shared__ char smem[];
    const int b = blockIdx.z;
    const int n0 = blockIdx.x * 128;
    const int m0 = blockIdx.y * 128;
    float acc[2][8][4];
    gemm_main<CC>(gwp_hi,
                  gatt_hi + (size_t)b * CC * NN + n0, gatt_lo + (size_t)b * CC * NN + n0,
                  NN, m0, smem, acc);

    const int t = threadIdx.x, wid = t >> 5, lane = t & 31;
    const int wm = (wid & 3) * 32, wn = (wid >> 2) * 64;
    float* outp = out + ((size_t)b * CC + m0) * NN + n0;
#pragma unroll
    for (int i = 0; i < 2; i++) {
        int r0 = wm + i * 16 + (lane >> 2);
        float b0 = bias[m0 + r0], b8 = bias[m0 + r0 + 8];
#pragma unroll
        for (int nt = 0; nt < 8; nt++) {
            int n = wn + nt * 8 + (lane & 3) * 2;
            float* d0 = outp + (size_t)r0 * NN + n;
            *reinterpret_cast<float2*>(d0) =
                make_float2(acc[i][nt][0] + b0, acc[i][nt][1] + b0);
            *reinterpret_cast<float2*>(d0 + 8 * NN) =
                make_float2(acc[i][nt][2] + b8, acc[i][nt][3] + b8);
        }
    }
}

// ---------------------------------------------------------------------------
// Kernel 2: grouped MHA. Q hi-only (mma-A); K,V hi+lo (mma-B). P hi-only.
// dyn smem: Qs 4KB @0 | stages @4096 + s*16384 (Kh,Kl,Vh,Vl 4KB each). Os overlays.
// ---------------------------------------------------------------------------
#define AKH 0
#define AKL 4096
#define AVH 8192
#define AVL 12288
#define SMEM_ATT (4096 + 3 * 16384)     // 53248

__global__ __launch_bounds__(128) void attn_kernel() {
    extern __shared__ char sm[];
    char* Qs = sm;
    float* Os = reinterpret_cast<float*>(sm + 4096);
    const u32 sb = smem_u32(sm);

    const int t = threadIdx.x, lane = t & 31, wid = t >> 5;
    const int head = blockIdx.y;
    const int b = head >> 6, g = (head >> 3) & 7, hh = head & 7;
    const int nqbase = g * MSEQ + blockIdx.x * 64;
    const size_t qoff = ((size_t)b * OC3 + hh * HD) * NN;
    const f16* qph = gqkv_hi + qoff;
    const f16* kph = qph + (size_t)CC * NN;
    const f16* kpl = gqkv_lo + qoff + (size_t)CC * NN;
    const f16* vph = qph + (size_t)(2 * CC) * NN;
    const f16* vpl = gqkv_lo + qoff + (size_t)(2 * CC) * NN;

    const int fd0 = t >> 3,          fk8 = (t & 7) * 8;
    const int fd1 = (128 + t) >> 3;
    const u32 fo0 = fd0 * 128 + ((((fk8 >> 3) ^ (fd0 & 7))) << 4);
    const u32 fo1 = fd1 * 128 + ((((fk8 >> 3) ^ (fd1 & 7))) << 4);

    auto fill_kv = [&](int kt, int buf) {
        const int nk = g * MSEQ + kt * 64;
        u32 base = sb + 4096 + buf * 16384;
        size_t s0 = (size_t)fd0 * NN + nk + fk8;
        size_t s1 = (size_t)fd1 * NN + nk + fk8;
        cpa16(base + AKH + fo0, kph + s0);  cpa16(base + AKH + fo1, kph + s1);
        cpa16(base + AKL + fo0, kpl + s0);  cpa16(base + AKL + fo1, kpl + s1);
        cpa16(base + AVH + fo0, vph + s0);  cpa16(base + AVH + fo1, vph + s1);
        cpa16(base + AVL + fo0, vpl + s0);  cpa16(base + AVL + fo1, vpl + s1);
    };

    fill_kv(0, 0); CPA_COMMIT();
    fill_kv(1, 1); CPA_COMMIT();

    // ---- Q fill: transpose [d][n] -> smem [q][d] hi-only (64B rows, 4-chunk swizzle)
    {
        int q = t & 63, dh = (t >> 6) * 16;
        const f16* ph = qph + nqbase + q;
#pragma unroll
        for (int dd = 0; dd < 16; dd += 2) {
            int d = dh + dd;
            u32 off = q * 64 + ((((d >> 3) ^ ((q >> 1) & 3)) & 3) << 4) + (d & 7) * 2;
            st_h2(Qs, off, ph[(size_t)d * NN], ph[(size_t)(d + 1) * NN]);
        }
    }
    __syncthreads();

    u32 qh[2][4];
    {
        int row = wid * 16 + (lane & 15);
#pragma unroll
        for (int ks = 0; ks < 2; ks++) {
            int kc = ks * 16 + (lane >> 4) * 8;
            u32 ao = row * 64 + ((((kc >> 3) ^ ((row >> 1) & 3)) & 3) << 4);
            ldsm4(qh[ks], sb + ao);
        }
    }

    float oacc[4][4];
#pragma unroll
    for (int i = 0; i < 4; i++)
#pragma unroll
        for (int j = 0; j < 4; j++) oacc[i][j] = 0.f;
    float mx0 = -1e30f, mx1 = -1e30f, l0 = 0.f, l1 = 0.f;

    for (int kt = 0; kt < 8; kt++) {
        if (kt == 7) { CPA_WAIT0(); } else { CPA_WAIT1(); }
        __syncthreads();
        if (kt + 2 < 8) { fill_kv(kt + 2, (kt + 2) % 3); CPA_COMMIT(); }
        u32 base = sb + 4096 + (kt % 3) * 16384;

        // ---- S = Q K^T (log2-domain; Q pre-scaled)
        float sacc[8][4];
#pragma unroll
        for (int i = 0; i < 8; i++)
#pragma unroll
            for (int j = 0; j < 4; j++) sacc[i][j] = 0.f;
#pragma unroll
        for (int ks = 0; ks < 2; ks++) {
            int kd = ks * 16 + ((lane >> 3) & 1) * 8 + (lane & 7);
            u32 krb = kd * 128;
#pragma unroll
            for (int pp = 0; pp < 4; pp++) {
                int nb = pp * 16 + (lane >> 4) * 8;
                u32 off = krb + ((((nb >> 3) ^ (kd & 7))) << 4);
                u32 kbh[4], kbl[4];
                ldsm4t(kbh, base + AKH + off);
                ldsm4t(kbl, base + AKL + off);
#pragma unroll
                for (int s = 0; s < 2; s++) {
                    int f = pp * 2 + s;
                    mma16816(sacc[f], qh[ks], kbh + s * 2);
                    mma16816(sacc[f], qh[ks], kbl + s * 2);
                }
            }
        }

        // ---- online softmax (base-2)
        float rm0 = -1e30f, rm1 = -1e30f;
#pragma unroll
        for (int j = 0; j < 8; j++) {
            rm0 = fmaxf(rm0, fmaxf(sacc[j][0], sacc[j][1]));
            rm1 = fmaxf(rm1, fmaxf(sacc[j][2], sacc[j][3]));
        }
        rm0 = fmaxf(rm0, __shfl_xor_sync(0xffffffffu, rm0, 1));
        rm0 = fmaxf(rm0, __shfl_xor_sync(0xffffffffu, rm0, 2));
        rm1 = fmaxf(rm1, __shfl_xor_sync(0xffffffffu, rm1, 1));
        rm1 = fmaxf(rm1, __shfl_xor_sync(0xffffffffu, rm1, 2));
        float nm0 = fmaxf(mx0, rm0), nm1 = fmaxf(mx1, rm1);
        float c0 = ex2f(mx0 - nm0), c1 = ex2f(mx1 - nm1);
        mx0 = nm0; mx1 = nm1;
#pragma unroll
        for (int df = 0; df < 4; df++) {
            oacc[df][0] *= c0; oacc[df][1] *= c0;
            oacc[df][2] *= c1; oacc[df][3] *= c1;
        }

        float rs0 = 0.f, rs1 = 0.f;
        u32 aph[4][4];
#pragma unroll
        for (int j = 0; j < 8; j++) {
            float p0 = ex2f(sacc[j][0] - nm0);
            float p1 = ex2f(sacc[j][1] - nm0);
            float p2 = ex2f(sacc[j][2] - nm1);
            float p3 = ex2f(sacc[j][3] - nm1);
            rs0 += p0 + p1; rs1 += p2 + p3;
            int ks = j >> 1, half = (j & 1) * 2;
            aph[ks][half]     = pk_h(__float2half(p0), __float2half(p1));
            aph[ks][half + 1] = pk_h(__float2half(p2), __float2half(p3));
        }
        rs0 += __shfl_xor_sync(0xffffffffu, rs0, 1);
        rs0 += __shfl_xor_sync(0xffffffffu, rs0, 2);
        rs1 += __shfl_xor_sync(0xffffffffu, rs1, 1);
        rs1 += __shfl_xor_sync(0xffffffffu, rs1, 2);
        l0 = l0 * c0 + rs0;
        l1 = l1 * c1 + rs1;

        // ---- O += P V  (V in [d][key], NON-trans ldsm; P hi-only)
#pragma unroll
        for (int ks = 0; ks < 4; ks++) {
            int kk = ks * 16 + ((lane >> 3) & 1) * 8;
#pragma unroll
            for (int dg = 0; dg < 2; dg++) {
                int dn = dg * 16 + (lane >> 4) * 8 + (lane & 7);
                u32 off = dn * 128 + ((((kk >> 3) ^ (dn & 7))) << 4);
                u32 vbh[4], vbl[4];
                ldsm4(vbh, base + AVH + off);
                ldsm4(vbl, base + AVL + off);
#pragma unroll
                for (int s = 0; s < 2; s++) {
                    int df = dg * 2 + s;
                    mma16816(oacc[df], aph[ks], vbh + s * 2);
                    mma16816(oacc[df], aph[ks], vbl + s * 2);
                }
            }
        }
    }

    // ---- epilogue: normalize, stage f32 to smem, split-store to gatt hi/lo
    float inv0 = 1.f / l0, inv1 = 1.f / l1;
    __syncthreads();
    {
        int r = wid * 16 + (lane >> 2);
#pragma unroll
        for (int df = 0; df < 4; df++) {
            int dc = df * 8 + (lane & 3) * 2;
            *reinterpret_cast<float2*>(&Os[r * 34 + dc]) =
                make_float2(oacc[df][0] * inv0, oacc[df][1] * inv0);
            *reinterpret_cast<float2*>(&Os[(r + 8) * 34 + dc]) =
                make_float2(oacc[df][2] * inv1, oacc[df][3] * inv1);
        }
    }
    __syncthreads();
    {
        int d = t >> 2, qg = (t & 3) * 16;
        size_t doff = ((size_t)b * CC + hh * HD + d) * NN + nqbase + qg;
        f16* dh_ = gatt_hi + doff;
        f16* dl_ = gatt_lo + doff;
#pragma unroll
        for (int qq = 0; qq < 16; qq += 2) {
            float v0 = Os[(qg + qq) * 34 + d];
            float v1 = Os[(qg + qq + 1) * 34 + d];
            f16 h0, lo0, h1, lo1;
            split_f16(v0, h0, lo0); split_f16(v1, h1, lo1);
            *reinterpret_cast<u32*>(dh_ + qq) = pk_h(h0, h1);
            *reinterpret_cast<u32*>(dl_ + qq) = pk_h(lo0, lo1);
        }
    }
}

// ---------------------------------------------------------------------------
extern "C" void kernel_launch(void* const* d_in, const int* in_sizes, int n_in,
                              void* d_out, int out_size) {
    const float* x      = (const float*)d_in[0];
    const float* w_qkv  = (const float*)d_in[1];
    const float* w_proj = (const float*)d_in[2];
    const float* b_proj = (const float*)d_in[3];
    float* out = (float*)d_out;

    cudaFuncSetAttribute(qkv_gemm_kernel, cudaFuncAttributeMaxDynamicSharedMemorySize, SMEM_GEMM);
    cudaFuncSetAttribute(proj_gemm_kernel, cudaFuncAttributeMaxDynamicSharedMemorySize, SMEM_GEMM);
    cudaFuncSetAttribute(attn_kernel, cudaFuncAttributeMaxDynamicSharedMemorySize, SMEM_ATT);

    f16 *xh, *xl, *wqh, *wph;
    cudaGetSymbolAddress((void**)&xh,  gx_hi);
    cudaGetSymbolAddress((void**)&xl,  gx_lo);
    cudaGetSymbolAddress((void**)&wqh, gwq_hi);
    cudaGetSymbolAddress((void**)&wph, gwp_hi);

    split_kernel<<<(BB * CC * NN / 4 + 255) / 256, 256>>>(x, xh, xl, BB * CC * NN / 4);
    split_kernel<<<(OC3 * CC / 4 + 255) / 256, 256>>>(w_qkv, wqh, nullptr, OC3 * CC / 4);
    split_kernel<<<(CC * CC / 4 + 255) / 256, 256>>>(w_proj, wph, nullptr, CC * CC / 4);

    dim3 g1(NN / 128, OC3 / 128, BB);
    qkv_gemm_kernel<<<g1, 256, SMEM_GEMM>>>();

    dim3 g2(MSEQ / 64, BB * GG * NH);
    attn_kernel<<<g2, 128, SMEM_ATT>>>();

    dim3 g3(NN / 128, CC / 128, BB);
    proj_gemm_kernel<<<g3, 256, SMEM_GEMM>>>(b_proj, out);
}

// round 11
// speedup vs baseline: 5.1552x; 1.0366x over previous
#include <cuda_runtime.h>
#include <cuda_fp16.h>

#define BB   4
#define CC   256
#define NN   4096
#define GG   8
#define NH   8
#define HD   32
#define MSEQ 512
#define OC3  768
// 1/sqrt(32) * log2(e): Q pre-scale so softmax runs in log2 domain (ex2)
#define Q2SCALE (0.17677669529663687f * 1.4426950408889634f)

typedef unsigned long long u64;
typedef unsigned int u32;
typedef __half f16;

// ---------------------------------------------------------------- helpers
__device__ __forceinline__ u32 smem_u32(const void* p) {
    u32 a; asm("{.reg .u64 t; cvta.to.shared.u64 t,%1; cvt.u32.u64 %0,t;}" : "=r"(a) : "l"(p));
    return a;
}
__device__ __forceinline__ void cpa16(u32 dst, const void* src) {
    asm volatile("cp.async.cg.shared.global [%0],[%1],16;" :: "r"(dst), "l"(src));
}
#define CPA_COMMIT() asm volatile("cp.async.commit_group;" ::: "memory")
#define CPA_WAIT1()  asm volatile("cp.async.wait_group 1;" ::: "memory")
#define CPA_WAIT0()  asm volatile("cp.async.wait_group 0;" ::: "memory")
__device__ __forceinline__ float ex2f(float x) {
    float r; asm("ex2.approx.f32 %0,%1;" : "=f"(r) : "f"(x)); return r;
}
__device__ __forceinline__ void ldsm4(u32* r, u32 addr) {
    asm volatile("ldmatrix.sync.aligned.m8n8.x4.shared.b16 {%0,%1,%2,%3},[%4];"
                 : "=r"(r[0]), "=r"(r[1]), "=r"(r[2]), "=r"(r[3]) : "r"(addr));
}
__device__ __forceinline__ void ldsm4t(u32* r, u32 addr) {
    asm volatile("ldmatrix.sync.aligned.m8n8.x4.trans.shared.b16 {%0,%1,%2,%3},[%4];"
                 : "=r"(r[0]), "=r"(r[1]), "=r"(r[2]), "=r"(r[3]) : "r"(addr));
}
__device__ __forceinline__ void mma16816(float* d, const u32* a, const u32* b) {
    asm volatile("mma.sync.aligned.m16n8k16.row.col.f32.f16.f16.f32 "
                 "{%0,%1,%2,%3},{%4,%5,%6,%7},{%8,%9},{%0,%1,%2,%3};"
                 : "+f"(d[0]), "+f"(d[1]), "+f"(d[2]), "+f"(d[3])
                 : "r"(a[0]), "r"(a[1]), "r"(a[2]), "r"(a[3]), "r"(b[0]), "r"(b[1]));
}
__device__ __forceinline__ void split_f16(float x, f16& h, f16& l) {
    h = __float2half(x);
    l = __float2half(x - __half2float(h));
}
__device__ __forceinline__ u32 pk_h(f16 a, f16 b) {
    __half2 t; t.x = a; t.y = b;
    return *reinterpret_cast<u32*>(&t);
}
__device__ __forceinline__ void st_h2(char* base, u32 off, f16 a, f16 b) {
    __half2 t; t.x = a; t.y = b;
    *reinterpret_cast<__half2*>(base + off) = t;
}

// A tile [m][32 k] f16: 64B rows, 4-chunk swizzle
__device__ __forceinline__ u32 a32_off(int m, int k8) {
    return m * 64 + ((((k8 >> 3) ^ ((m >> 1) & 3)) & 3) << 4);
}
// B tile [32 k][128 n] f16: 256B rows, 8-chunk swizzle
__device__ __forceinline__ u32 b32_off(int k, int n8) {
    return k * 256 + ((((n8 >> 3) ^ (k & 7))) << 4);
}

#define ST_A    0
#define ST_B_HI 8192
#define ST_B_LO 16384
#define STAGE_SZ 24576
#define SMEM_GEMM (3 * STAGE_SZ)        // 73728, 3-stage

// ---------------- persistent f16 hi/lo buffers
__device__ __align__(128) f16 gx_hi[(size_t)BB * CC * NN];
__device__ __align__(128) f16 gx_lo[(size_t)BB * CC * NN];
__device__ __align__(128) f16 gwq_hi[OC3 * CC];          // weights: hi used as mma-A
__device__ __align__(128) f16 gwp_hi[CC * CC];
__device__ __align__(128) f16 gqkv_hi[(size_t)BB * OC3 * NN];   // Q pre-scaled by Q2SCALE
__device__ __align__(128) f16 gqkv_lo[(size_t)BB * OC3 * NN];
__device__ __align__(128) f16 gatt_hi[(size_t)BB * CC * NN];
__device__ __align__(128) f16 gatt_lo[(size_t)BB * CC * NN];

// ---------------------------------------------------------------------------
// Fused prepass: splits x (hi+lo), w_qkv (hi), w_proj (hi) in one launch.
// ---------------------------------------------------------------------------
#define N4X (BB * CC * NN / 4)
#define N4Q (OC3 * CC / 4)
#define N4P (CC * CC / 4)

__global__ __launch_bounds__(256) void split_all_kernel(const float* __restrict__ x,
                                                        const float* __restrict__ wq,
                                                        const float* __restrict__ wp) {
    int i = blockIdx.x * blockDim.x + threadIdx.x;
    const float* src;
    f16 *hi, *lo = nullptr;
    int j;
    if (i < N4X)              { src = x;  hi = gx_hi;  lo = gx_lo; j = i; }
    else if (i < N4X + N4Q)   { src = wq; hi = gwq_hi; j = i - N4X; }
    else if (i < N4X + N4Q + N4P) { src = wp; hi = gwp_hi; j = i - N4X - N4Q; }
    else return;
    float4 v = reinterpret_cast<const float4*>(src)[j];
    f16 h0, l0, h1, l1, h2, l2, h3, l3;
    split_f16(v.x, h0, l0); split_f16(v.y, h1, l1);
    split_f16(v.z, h2, l2); split_f16(v.w, h3, l3);
    reinterpret_cast<uint2*>(hi)[j] = make_uint2(pk_h(h0, h1), pk_h(h2, h3));
    if (lo)
        reinterpret_cast<uint2*>(lo)[j] = make_uint2(pk_h(l0, l1), pk_h(l2, l3));
}

// ---------------------------------------------------------------------------
// GEMM mainloop: 3-stage cp.async, K-chunks of 32. A hi-only; B hi+lo.
// ---------------------------------------------------------------------------
template<int KDIM>
__device__ __forceinline__ void gemm_main(const f16* __restrict__ Ah,
                                          const f16* __restrict__ Bh, const f16* __restrict__ Bl,
                                          size_t ldb, int m0, char* smem,
                                          float (&acc)[2][8][4]) {
    const u32 sb = smem_u32(smem);
    const int t = threadIdx.x;
    const int wid = t >> 5, lane = t & 31;
    const int wm = (wid & 3) * 32;
    const int wn = (wid >> 2) * 64;
    constexpr int NCH = KDIM / 32;

#pragma unroll
    for (int i = 0; i < 2; i++)
#pragma unroll
        for (int j = 0; j < 8; j++)
#pragma unroll
            for (int c = 0; c < 4; c++) acc[i][j][c] = 0.f;

    const int am0 = t >> 2,         ak8 = (t & 3) * 8;
    const int am1 = (256 + t) >> 2, bk0 = t >> 4;
    const int bn8 = (t & 15) * 8,   bk1 = (256 + t) >> 4;

    auto fill = [&](int c0, int buf) {
        u32 base = sb + buf * STAGE_SZ;
        {
            u32 o0 = base + a32_off(am0, ak8), o1 = base + a32_off(am1, ak8);
            cpa16(o0 + ST_A, Ah + (size_t)(m0 + am0) * KDIM + c0 + ak8);
            cpa16(o1 + ST_A, Ah + (size_t)(m0 + am1) * KDIM + c0 + ak8);
        }
        {
            u32 o0 = base + b32_off(bk0, bn8), o1 = base + b32_off(bk1, bn8);
            size_t s0 = (size_t)(c0 + bk0) * ldb + bn8;
            size_t s1 = (size_t)(c0 + bk1) * ldb + bn8;
            cpa16(o0 + ST_B_HI, Bh + s0);  cpa16(o1 + ST_B_HI, Bh + s1);
            cpa16(o0 + ST_B_LO, Bl + s0);  cpa16(o1 + ST_B_LO, Bl + s1);
        }
    };

    fill(0, 0);  CPA_COMMIT();
    fill(32, 1); CPA_COMMIT();

    for (int ch = 0; ch < NCH; ch++) {
        if (ch == NCH - 1) { CPA_WAIT0(); } else { CPA_WAIT1(); }
        __syncthreads();
        if (ch + 2 < NCH) { fill((ch + 2) * 32, (ch + 2) % 3); CPA_COMMIT(); }
        u32 base = sb + (ch % 3) * STAGE_SZ;

#pragma unroll
        for (int ks = 0; ks < 2; ks++) {
            u32 ah[2][4];
#pragma unroll
            for (int i = 0; i < 2; i++) {
                int row = wm + i * 16 + (lane & 15);
                int kc  = ks * 16 + (lane >> 4) * 8;
                u32 ao = row * 64 + ((((kc >> 3) ^ ((row >> 1) & 3)) & 3) << 4);
                ldsm4(ah[i], base + ST_A + ao);
            }
#pragma unroll
            for (int nh = 0; nh < 2; nh++) {
                u32 bh[2][4], bl[2][4];
#pragma unroll
                for (int pp = 0; pp < 2; pp++) {
                    int k = ks * 16 + ((lane >> 3) & 1) * 8 + (lane & 7);
                    int nb = wn + nh * 32 + pp * 16 + (lane >> 4) * 8;
                    u32 bo = k * 256 + ((((nb >> 3) ^ (k & 7))) << 4);
                    ldsm4t(bh[pp], base + ST_B_HI + bo);
                    ldsm4t(bl[pp], base + ST_B_LO + bo);
                }
#pragma unroll
                for (int i = 0; i < 2; i++)
#pragma unroll
                    for (int pp = 0; pp < 2; pp++)
#pragma unroll
                        for (int s = 0; s < 2; s++) {
                            int nt = nh * 4 + pp * 2 + s;
                            mma16816(acc[i][nt], ah[i], bh[pp] + s * 2);
                            mma16816(acc[i][nt], ah[i], bl[pp] + s * 2);
                        }
            }
        }
    }
}

// Kernel 1: qkv GEMM -> f16 hi/lo, Q rows pre-scaled by Q2SCALE
__global__ __launch_bounds__(256, 2) void qkv_gemm_kernel() {
    extern __shared__ char smem[];
    const int b = blockIdx.z;
    const int n0 = blockIdx.x * 128;
    const int m0 = blockIdx.y * 128;
    float acc[2][8][4];
    gemm_main<CC>(gwq_hi,
                  gx_hi + (size_t)b * CC * NN + n0, gx_lo + (size_t)b * CC * NN + n0,
                  NN, m0, smem, acc);

    const int t = threadIdx.x, wid = t >> 5, lane = t & 31;
    const int wm = (wid & 3) * 32, wn = (wid >> 2) * 64;
    f16* oh = gqkv_hi + ((size_t)b * OC3 + m0) * NN + n0;
    f16* ol = gqkv_lo + ((size_t)b * OC3 + m0) * NN + n0;
#pragma unroll
    for (int i = 0; i < 2; i++) {
        int r0 = wm + i * 16 + (lane >> 2);
        float s0 = (m0 + r0 < CC) ? Q2SCALE : 1.f;
        float s8 = (m0 + r0 + 8 < CC) ? Q2SCALE : 1.f;
#pragma unroll
        for (int nt = 0; nt < 8; nt++) {
            int n = wn + nt * 8 + (lane & 3) * 2;
            f16 h0, l0, h1, l1;
            split_f16(acc[i][nt][0] * s0, h0, l0);
            split_f16(acc[i][nt][1] * s0, h1, l1);
            *reinterpret_cast<u32*>(oh + (size_t)r0 * NN + n) = pk_h(h0, h1);
            *reinterpret_cast<u32*>(ol + (size_t)r0 * NN + n) = pk_h(l0, l1);
            split_f16(acc[i][nt][2] * s8, h0, l0);
            split_f16(acc[i][nt][3] * s8, h1, l1);
            *reinterpret_cast<u32*>(oh + (size_t)(r0 + 8) * NN + n) = pk_h(h0, h1);
            *reinterpret_cast<u32*>(ol + (size_t)(r0 + 8) * NN + n) = pk_h(l0, l1);
        }
    }
}

// Kernel 3: proj GEMM + bias -> f32 out
__global__ __launch_bounds__(256, 2) void proj_gemm_kernel(const float* __restrict__ bias,
                                                           float* __restrict__ out) {
    extern __shared__ char smem[];
    const int b = blockIdx.z;
    const int n0 = blockIdx.x * 128;
    const int m0 = blockIdx.y * 128;
    float acc[2][8][4];
    gemm_main<CC>(gwp_hi,
                  gatt_hi + (size_t)b * CC * NN + n0, gatt_lo + (size_t)b * CC * NN + n0,
                  NN, m0, smem, acc);

    const int t = threadIdx.x, wid = t >> 5, lane = t & 31;
    const int wm = (wid & 3) * 32, wn = (wid >> 2) * 64;
    float* outp = out + ((size_t)b * CC + m0) * NN + n0;
#pragma unroll
    for (int i = 0; i < 2; i++) {
        int r0 = wm + i * 16 + (lane >> 2);
        float b0 = bias[m0 + r0], b8 = bias[m0 + r0 + 8];
#pragma unroll
        for (int nt = 0; nt < 8; nt++) {
            int n = wn + nt * 8 + (lane & 3) * 2;
            float* d0 = outp + (size_t)r0 * NN + n;
            *reinterpret_cast<float2*>(d0) =
                make_float2(acc[i][nt][0] + b0, acc[i][nt][1] + b0);
            *reinterpret_cast<float2*>(d0 + 8 * NN) =
                make_float2(acc[i][nt][2] + b8, acc[i][nt][3] + b8);
        }
    }
}

// ---------------------------------------------------------------------------
// Kernel 2: grouped MHA. 128 queries/block, 8 warps. Q/P hi-only; K,V hi+lo.
// dyn smem: Qs 8KB @0 | stages @8192 + s*16384 (Kh,Kl,Vh,Vl 4KB each). Os overlays.
// ---------------------------------------------------------------------------
#define AKH 0
#define AKL 4096
#define AVH 8192
#define AVL 12288
#define SMEM_ATT (8192 + 3 * 16384)     // 57344

__global__ __launch_bounds__(256) void attn_kernel() {
    extern __shared__ char sm[];
    char* Qs = sm;
    float* Os = reinterpret_cast<float*>(sm + 8192);
    const u32 sb = smem_u32(sm);

    const int t = threadIdx.x, lane = t & 31, wid = t >> 5;
    const int head = blockIdx.y;
    const int b = head >> 6, g = (head >> 3) & 7, hh = head & 7;
    const int nqbase = g * MSEQ + blockIdx.x * 128;
    const size_t qoff = ((size_t)b * OC3 + hh * HD) * NN;
    const f16* qph = gqkv_hi + qoff;
    const f16* kph = qph + (size_t)CC * NN;
    const f16* kpl = gqkv_lo + qoff + (size_t)CC * NN;
    const f16* vph = qph + (size_t)(2 * CC) * NN;
    const f16* vpl = gqkv_lo + qoff + (size_t)(2 * CC) * NN;

    // K/V fill: 256 threads, 1 16B chunk per tile per thread
    const int fd = t >> 3, fk8 = (t & 7) * 8;
    const u32 fo = fd * 128 + ((((fk8 >> 3) ^ (fd & 7))) << 4);

    auto fill_kv = [&](int kt, int buf) {
        const int nk = g * MSEQ + kt * 64;
        u32 base = sb + 8192 + buf * 16384;
        size_t s = (size_t)fd * NN + nk + fk8;
        cpa16(base + AKH + fo, kph + s);
        cpa16(base + AKL + fo, kpl + s);
        cpa16(base + AVH + fo, vph + s);
        cpa16(base + AVL + fo, vpl + s);
    };

    fill_kv(0, 0); CPA_COMMIT();
    fill_kv(1, 1); CPA_COMMIT();

    // ---- Q fill: transpose [d][n] -> smem [q][d] hi-only (64B rows, 4-chunk swizzle)
    {
        int q = t & 127, dh = (t >> 7) * 16;
        const f16* ph = qph + nqbase + q;
#pragma unroll
        for (int dd = 0; dd < 16; dd += 2) {
            int d = dh + dd;
            u32 off = q * 64 + ((((d >> 3) ^ ((q >> 1) & 3)) & 3) << 4) + (d & 7) * 2;
            st_h2(Qs, off, ph[(size_t)d * NN], ph[(size_t)(d + 1) * NN]);
        }
    }
    __syncthreads();

    u32 qh[2][4];
    {
        int row = wid * 16 + (lane & 15);
#pragma unroll
        for (int ks = 0; ks < 2; ks++) {
            int kc = ks * 16 + (lane >> 4) * 8;
            u32 ao = row * 64 + ((((kc >> 3) ^ ((row >> 1) & 3)) & 3) << 4);
            ldsm4(qh[ks], sb + ao);
        }
    }

    float oacc[4][4];
#pragma unroll
    for (int i = 0; i < 4; i++)
#pragma unroll
        for (int j = 0; j < 4; j++) oacc[i][j] = 0.f;
    float mx0 = -1e30f, mx1 = -1e30f, l0 = 0.f, l1 = 0.f;

    for (int kt = 0; kt < 8; kt++) {
        if (kt == 7) { CPA_WAIT0(); } else { CPA_WAIT1(); }
        __syncthreads();
        if (kt + 2 < 8) { fill_kv(kt + 2, (kt + 2) % 3); CPA_COMMIT(); }
        u32 base = sb + 8192 + (kt % 3) * 16384;

        // ---- S = Q K^T (log2-domain; Q pre-scaled)
        float sacc[8][4];
#pragma unroll
        for (int i = 0; i < 8; i++)
#pragma unroll
            for (int j = 0; j < 4; j++) sacc[i][j] = 0.f;
#pragma unroll
        for (int ks = 0; ks < 2; ks++) {
            int kd = ks * 16 + ((lane >> 3) & 1) * 8 + (lane & 7);
            u32 krb = kd * 128;
#pragma unroll
            for (int pp = 0; pp < 4; pp++) {
                int nb = pp * 16 + (lane >> 4) * 8;
                u32 off = krb + ((((nb >> 3) ^ (kd & 7))) << 4);
                u32 kbh[4], kbl[4];
                ldsm4t(kbh, base + AKH + off);
                ldsm4t(kbl, base + AKL + off);
#pragma unroll
                for (int s = 0; s < 2; s++) {
                    int f = pp * 2 + s;
                    mma16816(sacc[f], qh[ks], kbh + s * 2);
                    mma16816(sacc[f], qh[ks], kbl + s * 2);
                }
            }
        }

        // ---- online softmax (base-2)
        float rm0 = -1e30f, rm1 = -1e30f;
#pragma unroll
        for (int j = 0; j < 8; j++) {
            rm0 = fmaxf(rm0, fmaxf(sacc[j][0], sacc[j][1]));
            rm1 = fmaxf(rm1, fmaxf(sacc[j][2], sacc[j][3]));
        }
        rm0 = fmaxf(rm0, __shfl_xor_sync(0xffffffffu, rm0, 1));
        rm0 = fmaxf(rm0, __shfl_xor_sync(0xffffffffu, rm0, 2));
        rm1 = fmaxf(rm1, __shfl_xor_sync(0xffffffffu, rm1, 1));
        rm1 = fmaxf(rm1, __shfl_xor_sync(0xffffffffu, rm1, 2));
        float nm0 = fmaxf(mx0, rm0), nm1 = fmaxf(mx1, rm1);
        float c0 = ex2f(mx0 - nm0), c1 = ex2f(mx1 - nm1);
        mx0 = nm0; mx1 = nm1;
#pragma unroll
        for (int df = 0; df < 4; df++) {
            oacc[df][0] *= c0; oacc[df][1] *= c0;
            oacc[df][2] *= c1; oacc[df][3] *= c1;
        }

        float rs0 = 0.f, rs1 = 0.f;
        u32 aph[4][4];
#pragma unroll
        for (int j = 0; j < 8; j++) {
            float p0 = ex2f(sacc[j][0] - nm0);
            float p1 = ex2f(sacc[j][1] - nm0);
            float p2 = ex2f(sacc[j][2] - nm1);
            float p3 = ex2f(sacc[j][3] - nm1);
            rs0 += p0 + p1; rs1 += p2 + p3;
            int ks = j >> 1, half = (j & 1) * 2;
            aph[ks][half]     = pk_h(__float2half(p0), __float2half(p1));
            aph[ks][half + 1] = pk_h(__float2half(p2), __float2half(p3));
        }
        rs0 += __shfl_xor_sync(0xffffffffu, rs0, 1);
        rs0 += __shfl_xor_sync(0xffffffffu, rs0, 2);
        rs1 += __shfl_xor_sync(0xffffffffu, rs1, 1);
        rs1 += __shfl_xor_sync(0xffffffffu, rs1, 2);
        l0 = l0 * c0 + rs0;
        l1 = l1 * c1 + rs1;

        // ---- O += P V  (V in [d][key], NON-trans ldsm; P hi-only)
#pragma unroll
        for (int ks = 0; ks < 4; ks++) {
            int kk = ks * 16 + ((lane >> 3) & 1) * 8;
#pragma unroll
            for (int dg = 0; dg < 2; dg++) {
                int dn = dg * 16 + (lane >> 4) * 8 + (lane & 7);
                u32 off = dn * 128 + ((((kk >> 3) ^ (dn & 7))) << 4);
                u32 vbh[4], vbl[4];
                ldsm4(vbh, base + AVH + off);
                ldsm4(vbl, base + AVL + off);
#pragma unroll
                for (int s = 0; s < 2; s++) {
                    int df = dg * 2 + s;
                    mma16816(oacc[df], aph[ks], vbh + s * 2);
                    mma16816(oacc[df], aph[ks], vbl + s * 2);
                }
            }
        }
    }

    // ---- epilogue: normalize, stage f32 to smem [128][34], split-store hi/lo
    float inv0 = 1.f / l0, inv1 = 1.f / l1;
    __syncthreads();
    {
        int r = wid * 16 + (lane >> 2);
#pragma unroll
        for (int df = 0; df < 4; df++) {
            int dc = df * 8 + (lane & 3) * 2;
            *reinterpret_cast<float2*>(&Os[r * 34 + dc]) =
                make_float2(oacc[df][0] * inv0, oacc[df][1] * inv0);
            *reinterpret_cast<float2*>(&Os[(r + 8) * 34 + dc]) =
                make_float2(oacc[df][2] * inv1, oacc[df][3] * inv1);
        }
    }
    __syncthreads();
    {
        int d = t >> 3, qg = (t & 7) * 16;
        size_t doff = ((size_t)b * CC + hh * HD + d) * NN + nqbase + qg;
        f16* dh_ = gatt_hi + doff;
        f16* dl_ = gatt_lo + doff;
#pragma unroll
        for (int qq = 0; qq < 16; qq += 2) {
            float v0 = Os[(qg + qq) * 34 + d];
            float v1 = Os[(qg + qq + 1) * 34 + d];
            f16 h0, lo0, h1, lo1;
            split_f16(v0, h0, lo0); split_f16(v1, h1, lo1);
            *reinterpret_cast<u32*>(dh_ + qq) = pk_h(h0, h1);
            *reinterpret_cast<u32*>(dl_ + qq) = pk_h(lo0, lo1);
        }
    }
}

// ---------------------------------------------------------------------------
extern "C" void kernel_launch(void* const* d_in, const int* in_sizes, int n_in,
                              void* d_out, int out_size) {
    const float* x      = (const float*)d_in[0];
    const float* w_qkv  = (const float*)d_in[1];
    const float* w_proj = (const float*)d_in[2];
    const float* b_proj = (const float*)d_in[3];
    float* out = (float*)d_out;

    cudaFuncSetAttribute(qkv_gemm_kernel, cudaFuncAttributeMaxDynamicSharedMemorySize, SMEM_GEMM);
    cudaFuncSetAttribute(proj_gemm_kernel, cudaFuncAttributeMaxDynamicSharedMemorySize, SMEM_GEMM);
    cudaFuncSetAttribute(attn_kernel, cudaFuncAttributeMaxDynamicSharedMemorySize, SMEM_ATT);

    split_all_kernel<<<(N4X + N4Q + N4P + 255) / 256, 256>>>(x, w_qkv, w_proj);

    dim3 g1(NN / 128, OC3 / 128, BB);
    qkv_gemm_kernel<<<g1, 256, SMEM_GEMM>>>();

    dim3 g2(MSEQ / 128, BB * GG * NH);
    attn_kernel<<<g2, 256, SMEM_ATT>>>();

    dim3 g3(NN / 128, CC / 128, BB);
    proj_gemm_kernel<<<g3, 256, SMEM_GEMM>>>(b_proj, out);
}

// round 12
// speedup vs baseline: 8.2247x; 1.5954x over previous
#include <cuda_runtime.h>
#include <cuda_fp16.h>

#define BB   4
#define CC   256
#define NN   4096
#define GG   8
#define NH   8
#define HD   32
#define MSEQ 512
#define OC3  768
// 1/sqrt(32) * log2(e): Q pre-scale so softmax runs in log2 domain (ex2)
#define Q2SCALE (0.17677669529663687f * 1.4426950408889634f)

typedef unsigned long long u64;
typedef unsigned int u32;
typedef __half f16;

// ---------------------------------------------------------------- helpers
__device__ __forceinline__ u32 smem_u32(const void* p) {
    u32 a; asm("{.reg .u64 t; cvta.to.shared.u64 t,%1; cvt.u32.u64 %0,t;}" : "=r"(a) : "l"(p));
    return a;
}
__device__ __forceinline__ void cpa16(u32 dst, const void* src) {
    asm volatile("cp.async.cg.shared.global [%0],[%1],16;" :: "r"(dst), "l"(src));
}
#define CPA_COMMIT() asm volatile("cp.async.commit_group;" ::: "memory")
#define CPA_WAIT1()  asm volatile("cp.async.wait_group 1;" ::: "memory")
#define CPA_WAIT0()  asm volatile("cp.async.wait_group 0;" ::: "memory")
__device__ __forceinline__ float ex2f(float x) {
    float r; asm("ex2.approx.f32 %0,%1;" : "=f"(r) : "f"(x)); return r;
}
__device__ __forceinline__ void ldsm4(u32* r, u32 addr) {
    asm volatile("ldmatrix.sync.aligned.m8n8.x4.shared.b16 {%0,%1,%2,%3},[%4];"
                 : "=r"(r[0]), "=r"(r[1]), "=r"(r[2]), "=r"(r[3]) : "r"(addr));
}
__device__ __forceinline__ void ldsm4t(u32* r, u32 addr) {
    asm volatile("ldmatrix.sync.aligned.m8n8.x4.trans.shared.b16 {%0,%1,%2,%3},[%4];"
                 : "=r"(r[0]), "=r"(r[1]), "=r"(r[2]), "=r"(r[3]) : "r"(addr));
}
__device__ __forceinline__ void mma16816(float* d, const u32* a, const u32* b) {
    asm volatile("mma.sync.aligned.m16n8k16.row.col.f32.f16.f16.f32 "
                 "{%0,%1,%2,%3},{%4,%5,%6,%7},{%8,%9},{%0,%1,%2,%3};"
                 : "+f"(d[0]), "+f"(d[1]), "+f"(d[2]), "+f"(d[3])
                 : "r"(a[0]), "r"(a[1]), "r"(a[2]), "r"(a[3]), "r"(b[0]), "r"(b[1]));
}
__device__ __forceinline__ u32 pk_h(f16 a, f16 b) {
    __half2 t; t.x = a; t.y = b;
    return *reinterpret_cast<u32*>(&t);
}
__device__ __forceinline__ void st_h2(char* base, u32 off, f16 a, f16 b) {
    __half2 t; t.x = a; t.y = b;
    *reinterpret_cast<__half2*>(base + off) = t;
}

// A tile [m][32 k] f16: 64B rows, 4-chunk swizzle
__device__ __forceinline__ u32 a32_off(int m, int k8) {
    return m * 64 + ((((k8 >> 3) ^ ((m >> 1) & 3)) & 3) << 4);
}
// B tile [32 k][128 n] f16: 256B rows, 8-chunk swizzle
__device__ __forceinline__ u32 b32_off(int k, int n8) {
    return k * 256 + ((((n8 >> 3) ^ (k & 7))) << 4);
}

#define ST_A    0
#define ST_B    8192
#define STAGE_SZ 16384
#define SMEM_GEMM (3 * STAGE_SZ)        // 49152, 3-stage

// ---------------- persistent f16 buffers (plain fp16, fp32 accum in mma)
__device__ __align__(128) f16 gx[(size_t)BB * CC * NN];
__device__ __align__(128) f16 gwq[OC3 * CC];
__device__ __align__(128) f16 gwp[CC * CC];
__device__ __align__(128) f16 gqkv[(size_t)BB * OC3 * NN];   // Q rows pre-scaled by Q2SCALE
__device__ __align__(128) f16 gatt[(size_t)BB * CC * NN];

// ---------------------------------------------------------------------------
// Fused prepass: f32 -> f16 for x, w_qkv, w_proj in one launch.
// ---------------------------------------------------------------------------
#define N4X (BB * CC * NN / 4)
#define N4Q (OC3 * CC / 4)
#define N4P (CC * CC / 4)

__global__ __launch_bounds__(256) void split_all_kernel(const float* __restrict__ x,
                                                        const float* __restrict__ wq,
                                                        const float* __restrict__ wp) {
    int i = blockIdx.x * blockDim.x + threadIdx.x;
    const float* src;
    f16* hi;
    int j;
    if (i < N4X)                  { src = x;  hi = gx;  j = i; }
    else if (i < N4X + N4Q)       { src = wq; hi = gwq; j = i - N4X; }
    else if (i < N4X + N4Q + N4P) { src = wp; hi = gwp; j = i - N4X - N4Q; }
    else return;
    float4 v = reinterpret_cast<const float4*>(src)[j];
    reinterpret_cast<uint2*>(hi)[j] =
        make_uint2(pk_h(__float2half(v.x), __float2half(v.y)),
                   pk_h(__float2half(v.z), __float2half(v.w)));
}

// ---------------------------------------------------------------------------
// GEMM mainloop: 3-stage cp.async, K-chunks of 32, plain fp16 operands.
// ---------------------------------------------------------------------------
template<int KDIM>
__device__ __forceinline__ void gemm_main(const f16* __restrict__ Ah,
                                          const f16* __restrict__ Bh,
                                          size_t ldb, int m0, char* smem,
                                          float (&acc)[2][8][4]) {
    const u32 sb = smem_u32(smem);
    const int t = threadIdx.x;
    const int wid = t >> 5, lane = t & 31;
    const int wm = (wid & 3) * 32;
    const int wn = (wid >> 2) * 64;
    constexpr int NCH = KDIM / 32;

#pragma unroll
    for (int i = 0; i < 2; i++)
#pragma unroll
        for (int j = 0; j < 8; j++)
#pragma unroll
            for (int c = 0; c < 4; c++) acc[i][j][c] = 0.f;

    const int am0 = t >> 2,         ak8 = (t & 3) * 8;
    const int am1 = (256 + t) >> 2, bk0 = t >> 4;
    const int bn8 = (t & 15) * 8,   bk1 = (256 + t) >> 4;

    auto fill = [&](int c0, int buf) {
        u32 base = sb + buf * STAGE_SZ;
        cpa16(base + ST_A + a32_off(am0, ak8), Ah + (size_t)(m0 + am0) * KDIM + c0 + ak8);
        cpa16(base + ST_A + a32_off(am1, ak8), Ah + (size_t)(m0 + am1) * KDIM + c0 + ak8);
        cpa16(base + ST_B + b32_off(bk0, bn8), Bh + (size_t)(c0 + bk0) * ldb + bn8);
        cpa16(base + ST_B + b32_off(bk1, bn8), Bh + (size_t)(c0 + bk1) * ldb + bn8);
    };

    fill(0, 0);  CPA_COMMIT();
    fill(32, 1); CPA_COMMIT();

    for (int ch = 0; ch < NCH; ch++) {
        if (ch == NCH - 1) { CPA_WAIT0(); } else { CPA_WAIT1(); }
        __syncthreads();
        if (ch + 2 < NCH) { fill((ch + 2) * 32, (ch + 2) % 3); CPA_COMMIT(); }
        u32 base = sb + (ch % 3) * STAGE_SZ;

#pragma unroll
        for (int ks = 0; ks < 2; ks++) {
            u32 ah[2][4];
#pragma unroll
            for (int i = 0; i < 2; i++) {
                int row = wm + i * 16 + (lane & 15);
                int kc  = ks * 16 + (lane >> 4) * 8;
                u32 ao = row * 64 + ((((kc >> 3) ^ ((row >> 1) & 3)) & 3) << 4);
                ldsm4(ah[i], base + ST_A + ao);
            }
#pragma unroll
            for (int nh = 0; nh < 2; nh++) {
                u32 bh[2][4];
#pragma unroll
                for (int pp = 0; pp < 2; pp++) {
                    int k = ks * 16 + ((lane >> 3) & 1) * 8 + (lane & 7);
                    int nb = wn + nh * 32 + pp * 16 + (lane >> 4) * 8;
                    u32 bo = k * 256 + ((((nb >> 3) ^ (k & 7))) << 4);
                    ldsm4t(bh[pp], base + ST_B + bo);
                }
#pragma unroll
                for (int i = 0; i < 2; i++)
#pragma unroll
                    for (int pp = 0; pp < 2; pp++)
#pragma unroll
                        for (int s = 0; s < 2; s++)
                            mma16816(acc[i][nh * 4 + pp * 2 + s], ah[i], bh[pp] + s * 2);
            }
        }
    }
}

// Kernel 1: qkv GEMM -> f16, Q rows pre-scaled by Q2SCALE
__global__ __launch_bounds__(256, 2) void qkv_gemm_kernel() {
    extern __shared__ char smem[];
    const int b = blockIdx.z;
    const int n0 = blockIdx.x * 128;
    const int m0 = blockIdx.y * 128;
    float acc[2][8][4];
    gemm_main<CC>(gwq, gx + (size_t)b * CC * NN + n0, NN, m0, smem, acc);

    const int t = threadIdx.x, wid = t >> 5, lane = t & 31;
    const int wm = (wid & 3) * 32, wn = (wid >> 2) * 64;
    f16* oh = gqkv + ((size_t)b * OC3 + m0) * NN + n0;
#pragma unroll
    for (int i = 0; i < 2; i++) {
        int r0 = wm + i * 16 + (lane >> 2);
        float s0 = (m0 + r0 < CC) ? Q2SCALE : 1.f;
        float s8 = (m0 + r0 + 8 < CC) ? Q2SCALE : 1.f;
#pragma unroll
        for (int nt = 0; nt < 8; nt++) {
            int n = wn + nt * 8 + (lane & 3) * 2;
            *reinterpret_cast<u32*>(oh + (size_t)r0 * NN + n) =
                pk_h(__float2half(acc[i][nt][0] * s0), __float2half(acc[i][nt][1] * s0));
            *reinterpret_cast<u32*>(oh + (size_t)(r0 + 8) * NN + n) =
                pk_h(__float2half(acc[i][nt][2] * s8), __float2half(acc[i][nt][3] * s8));
        }
    }
}

// Kernel 3: proj GEMM + bias -> f32 out
__global__ __launch_bounds__(256, 2) void proj_gemm_kernel(const float* __restrict__ bias,
                                                           float* __restrict__ out) {
    extern __shared__ char smem[];
    const int b = blockIdx.z;
    const int n0 = blockIdx.x * 128;
    const int m0 = blockIdx.y * 128;
    float acc[2][8][4];
    gemm_main<CC>(gwp, gatt + (size_t)b * CC * NN + n0, NN, m0, smem, acc);

    const int t = threadIdx.x, wid = t >> 5, lane = t & 31;
    const int wm = (wid & 3) * 32, wn = (wid >> 2) * 64;
    float* outp = out + ((size_t)b * CC + m0) * NN + n0;
#pragma unroll
    for (int i = 0; i < 2; i++) {
        int r0 = wm + i * 16 + (lane >> 2);
        float b0 = bias[m0 + r0], b8 = bias[m0 + r0 + 8];
#pragma unroll
        for (int nt = 0; nt < 8; nt++) {
            int n = wn + nt * 8 + (lane & 3) * 2;
            float* d0 = outp + (size_t)r0 * NN + n;
            *reinterpret_cast<float2*>(d0) =
                make_float2(acc[i][nt][0] + b0, acc[i][nt][1] + b0);
            *reinterpret_cast<float2*>(d0 + 8 * NN) =
                make_float2(acc[i][nt][2] + b8, acc[i][nt][3] + b8);
        }
    }
}

// ---------------------------------------------------------------------------
// Kernel 2: grouped MHA, plain fp16. 128 queries/block, 8 warps.
// dyn smem: Qs 8KB @0 | stages @8192 + s*8192 (K 4KB, V 4KB). Os overlays.
// ---------------------------------------------------------------------------
#define AK 0
#define AV 4096
#define ASTG 8192
#define SMEM_ATT (8192 + 3 * ASTG)      // 32768

__global__ __launch_bounds__(256) void attn_kernel() {
    extern __shared__ char sm[];
    char* Qs = sm;
    float* Os = reinterpret_cast<float*>(sm + 8192);
    const u32 sb = smem_u32(sm);

    const int t = threadIdx.x, lane = t & 31, wid = t >> 5;
    const int head = blockIdx.y;
    const int b = head >> 6, g = (head >> 3) & 7, hh = head & 7;
    const int nqbase = g * MSEQ + blockIdx.x * 128;
    const size_t qoff = ((size_t)b * OC3 + hh * HD) * NN;
    const f16* qp = gqkv + qoff;
    const f16* kp = qp + (size_t)CC * NN;
    const f16* vp = qp + (size_t)(2 * CC) * NN;

    // K/V fill: 256 threads, 1 16B chunk per tile per thread
    const int fd = t >> 3, fk8 = (t & 7) * 8;
    const u32 fo = fd * 128 + ((((fk8 >> 3) ^ (fd & 7))) << 4);

    auto fill_kv = [&](int kt, int buf) {
        const int nk = g * MSEQ + kt * 64;
        u32 base = sb + 8192 + buf * ASTG;
        size_t s = (size_t)fd * NN + nk + fk8;
        cpa16(base + AK + fo, kp + s);
        cpa16(base + AV + fo, vp + s);
    };

    fill_kv(0, 0); CPA_COMMIT();
    fill_kv(1, 1); CPA_COMMIT();

    // ---- Q fill: transpose [d][n] -> smem [q][d] (64B rows, 4-chunk swizzle)
    {
        int q = t & 127, dh = (t >> 7) * 16;
        const f16* ph = qp + nqbase + q;
#pragma unroll
        for (int dd = 0; dd < 16; dd += 2) {
            int d = dh + dd;
            u32 off = q * 64 + ((((d >> 3) ^ ((q >> 1) & 3)) & 3) << 4) + (d & 7) * 2;
            st_h2(Qs, off, ph[(size_t)d * NN], ph[(size_t)(d + 1) * NN]);
        }
    }
    __syncthreads();

    u32 qh[2][4];
    {
        int row = wid * 16 + (lane & 15);
#pragma unroll
        for (int ks = 0; ks < 2; ks++) {
            int kc = ks * 16 + (lane >> 4) * 8;
            u32 ao = row * 64 + ((((kc >> 3) ^ ((row >> 1) & 3)) & 3) << 4);
            ldsm4(qh[ks], sb + ao);
        }
    }

    float oacc[4][4];
#pragma unroll
    for (int i = 0; i < 4; i++)
#pragma unroll
        for (int j = 0; j < 4; j++) oacc[i][j] = 0.f;
    float mx0 = -1e30f, mx1 = -1e30f, l0 = 0.f, l1 = 0.f;

    for (int kt = 0; kt < 8; kt++) {
        if (kt == 7) { CPA_WAIT0(); } else { CPA_WAIT1(); }
        __syncthreads();
        if (kt + 2 < 8) { fill_kv(kt + 2, (kt + 2) % 3); CPA_COMMIT(); }
        u32 base = sb + 8192 + (kt % 3) * ASTG;

        // ---- S = Q K^T (log2-domain; Q pre-scaled)
        float sacc[8][4];
#pragma unroll
        for (int i = 0; i < 8; i++)
#pragma unroll
            for (int j = 0; j < 4; j++) sacc[i][j] = 0.f;
#pragma unroll
        for (int ks = 0; ks < 2; ks++) {
            int kd = ks * 16 + ((lane >> 3) & 1) * 8 + (lane & 7);
            u32 krb = kd * 128;
#pragma unroll
            for (int pp = 0; pp < 4; pp++) {
                int nb = pp * 16 + (lane >> 4) * 8;
                u32 off = krb + ((((nb >> 3) ^ (kd & 7))) << 4);
                u32 kbh[4];
                ldsm4t(kbh, base + AK + off);
#pragma unroll
                for (int s = 0; s < 2; s++)
                    mma16816(sacc[pp * 2 + s], qh[ks], kbh + s * 2);
            }
        }

        // ---- online softmax (base-2)
        float rm0 = -1e30f, rm1 = -1e30f;
#pragma unroll
        for (int j = 0; j < 8; j++) {
            rm0 = fmaxf(rm0, fmaxf(sacc[j][0], sacc[j][1]));
            rm1 = fmaxf(rm1, fmaxf(sacc[j][2], sacc[j][3]));
        }
        rm0 = fmaxf(rm0, __shfl_xor_sync(0xffffffffu, rm0, 1));
        rm0 = fmaxf(rm0, __shfl_xor_sync(0xffffffffu, rm0, 2));
        rm1 = fmaxf(rm1, __shfl_xor_sync(0xffffffffu, rm1, 1));
        rm1 = fmaxf(rm1, __shfl_xor_sync(0xffffffffu, rm1, 2));
        float nm0 = fmaxf(mx0, rm0), nm1 = fmaxf(mx1, rm1);
        float c0 = ex2f(mx0 - nm0), c1 = ex2f(mx1 - nm1);
        mx0 = nm0; mx1 = nm1;
#pragma unroll
        for (int df = 0; df < 4; df++) {
            oacc[df][0] *= c0; oacc[df][1] *= c0;
            oacc[df][2] *= c1; oacc[df][3] *= c1;
        }

        float rs0 = 0.f, rs1 = 0.f;
        u32 aph[4][4];
#pragma unroll
        for (int j = 0; j < 8; j++) {
            float p0 = ex2f(sacc[j][0] - nm0);
            float p1 = ex2f(sacc[j][1] - nm0);
            float p2 = ex2f(sacc[j][2] - nm1);
            float p3 = ex2f(sacc[j][3] - nm1);
            rs0 += p0 + p1; rs1 += p2 + p3;
            int ks = j >> 1, half = (j & 1) * 2;
            aph[ks][half]     = pk_h(__float2half(p0), __float2half(p1));
            aph[ks][half + 1] = pk_h(__float2half(p2), __float2half(p3));
        }
        rs0 += __shfl_xor_sync(0xffffffffu, rs0, 1);
        rs0 += __shfl_xor_sync(0xffffffffu, rs0, 2);
        rs1 += __shfl_xor_sync(0xffffffffu, rs1, 1);
        rs1 += __shfl_xor_sync(0xffffffffu, rs1, 2);
        l0 = l0 * c0 + rs0;
        l1 = l1 * c1 + rs1;

        // ---- O += P V  (V in [d][key], NON-trans ldsm)
#pragma unroll
        for (int ks = 0; ks < 4; ks++) {
            int kk = ks * 16 + ((lane >> 3) & 1) * 8;
#pragma unroll
            for (int dg = 0; dg < 2; dg++) {
                int dn = dg * 16 + (lane >> 4) * 8 + (lane & 7);
                u32 off = dn * 128 + ((((kk >> 3) ^ (dn & 7))) << 4);
                u32 vbh[4];
                ldsm4(vbh, base + AV + off);
#pragma unroll
                for (int s = 0; s < 2; s++)
                    mma16816(oacc[dg * 2 + s], aph[ks], vbh + s * 2);
            }
        }
    }

    // ---- epilogue: normalize, stage f32 to smem [128][34], store f16
    float inv0 = 1.f / l0, inv1 = 1.f / l1;
    __syncthreads();
    {
        int r = wid * 16 + (lane >> 2);
#pragma unroll
        for (int df = 0; df < 4; df++) {
            int dc = df * 8 + (lane & 3) * 2;
            *reinterpret_cast<float2*>(&Os[r * 34 + dc]) =
                make_float2(oacc[df][0] * inv0, oacc[df][1] * inv0);
            *reinterpret_cast<float2*>(&Os[(r + 8) * 34 + dc]) =
                make_float2(oacc[df][2] * inv1, oacc[df][3] * inv1);
        }
    }
    __syncthreads();
    {
        int d = t >> 3, qg = (t & 7) * 16;
        f16* dh_ = gatt + ((size_t)b * CC + hh * HD + d) * NN + nqbase + qg;
#pragma unroll
        for (int qq = 0; qq < 16; qq += 2) {
            *reinterpret_cast<u32*>(dh_ + qq) =
                pk_h(__float2half(Os[(qg + qq) * 34 + d]),
                     __float2half(Os[(qg + qq + 1) * 34 + d]));
        }
    }
}

// ---------------------------------------------------------------------------
extern "C" void kernel_launch(void* const* d_in, const int* in_sizes, int n_in,
                              void* d_out, int out_size) {
    const float* x      = (const float*)d_in[0];
    const float* w_qkv  = (const float*)d_in[1];
    const float* w_proj = (const float*)d_in[2];
    const float* b_proj = (const float*)d_in[3];
    float* out = (float*)d_out;

    cudaFuncSetAttribute(qkv_gemm_kernel, cudaFuncAttributeMaxDynamicSharedMemorySize, SMEM_GEMM);
    cudaFuncSetAttribute(proj_gemm_kernel, cudaFuncAttributeMaxDynamicSharedMemorySize, SMEM_GEMM);
    cudaFuncSetAttribute(attn_kernel, cudaFuncAttributeMaxDynamicSharedMemorySize, SMEM_ATT);

    split_all_kernel<<<(N4X + N4Q + N4P + 255) / 256, 256>>>(x, w_qkv, w_proj);

    dim3 g1(NN / 128, OC3 / 128, BB);
    qkv_gemm_kernel<<<g1, 256, SMEM_GEMM>>>();

    dim3 g2(MSEQ / 128, BB * GG * NH);
    attn_kernel<<<g2, 256, SMEM_ATT>>>();

    dim3 g3(NN / 128, CC / 128, BB);
    proj_gemm_kernel<<<g3, 256, SMEM_GEMM>>>(b_proj, out);
}

// round 13
// speedup vs baseline: 8.4383x; 1.0260x over previous
#include <cuda_runtime.h>
#include <cuda_fp16.h>

#define BB   4
#define CC   256
#define NN   4096
#define GG   8
#define NH   8
#define HD   32
#define MSEQ 512
#define OC3  768
// 1/sqrt(32) * log2(e): Q pre-scale so softmax runs in log2 domain (ex2)
#define Q2SCALE (0.17677669529663687f * 1.4426950408889634f)

typedef unsigned long long u64;
typedef unsigned int u32;
typedef __half f16;

// ---------------------------------------------------------------- helpers
__device__ __forceinline__ u32 smem_u32(const void* p) {
    u32 a; asm("{.reg .u64 t; cvta.to.shared.u64 t,%1; cvt.u32.u64 %0,t;}" : "=r"(a) : "l"(p));
    return a;
}
__device__ __forceinline__ void cpa16(u32 dst, const void* src) {
    asm volatile("cp.async.cg.shared.global [%0],[%1],16;" :: "r"(dst), "l"(src));
}
#define CPA_COMMIT() asm volatile("cp.async.commit_group;" ::: "memory")
#define CPA_WAIT1()  asm volatile("cp.async.wait_group 1;" ::: "memory")
#define CPA_WAIT0()  asm volatile("cp.async.wait_group 0;" ::: "memory")
__device__ __forceinline__ float ex2f(float x) {
    float r; asm("ex2.approx.f32 %0,%1;" : "=f"(r) : "f"(x)); return r;
}
// pack (lo, hi) f32 -> f16x2 in one cvt
__device__ __forceinline__ u32 cvtf16x2(float hi, float lo) {
    u32 r; asm("cvt.rn.f16x2.f32 %0,%1,%2;" : "=r"(r) : "f"(hi), "f"(lo)); return r;
}
__device__ __forceinline__ u32 ex2h2(u32 x) {
    u32 r; asm("ex2.approx.f16x2 %0,%1;" : "=r"(r) : "r"(x)); return r;
}
__device__ __forceinline__ void ldsm4(u32* r, u32 addr) {
    asm volatile("ldmatrix.sync.aligned.m8n8.x4.shared.b16 {%0,%1,%2,%3},[%4];"
                 : "=r"(r[0]), "=r"(r[1]), "=r"(r[2]), "=r"(r[3]) : "r"(addr));
}
__device__ __forceinline__ void ldsm4t(u32* r, u32 addr) {
    asm volatile("ldmatrix.sync.aligned.m8n8.x4.trans.shared.b16 {%0,%1,%2,%3},[%4];"
                 : "=r"(r[0]), "=r"(r[1]), "=r"(r[2]), "=r"(r[3]) : "r"(addr));
}
__device__ __forceinline__ void mma16816(float* d, const u32* a, const u32* b) {
    asm volatile("mma.sync.aligned.m16n8k16.row.col.f32.f16.f16.f32 "
                 "{%0,%1,%2,%3},{%4,%5,%6,%7},{%8,%9},{%0,%1,%2,%3};"
                 : "+f"(d[0]), "+f"(d[1]), "+f"(d[2]), "+f"(d[3])
                 : "r"(a[0]), "r"(a[1]), "r"(a[2]), "r"(a[3]), "r"(b[0]), "r"(b[1]));
}
__device__ __forceinline__ u32 pk_h(f16 a, f16 b) {
    __half2 t; t.x = a; t.y = b;
    return *reinterpret_cast<u32*>(&t);
}
__device__ __forceinline__ void st_h2(char* base, u32 off, f16 a, f16 b) {
    __half2 t; t.x = a; t.y = b;
    *reinterpret_cast<__half2*>(base + off) = t;
}

// A tile [m][32 k] f16: 64B rows, 4-chunk swizzle
__device__ __forceinline__ u32 a32_off(int m, int k8) {
    return m * 64 + ((((k8 >> 3) ^ ((m >> 1) & 3)) & 3) << 4);
}
// B tile [32 k][128 n] f16: 256B rows, 8-chunk swizzle
__device__ __forceinline__ u32 b32_off(int k, int n8) {
    return k * 256 + ((((n8 >> 3) ^ (k & 7))) << 4);
}

#define ST_A    0
#define ST_B    8192
#define STAGE_SZ 16384
#define SMEM_GEMM (3 * STAGE_SZ)        // 49152, 3-stage

// ---------------- persistent f16 buffers (plain fp16, fp32 accum in mma)
__device__ __align__(128) f16 gx[(size_t)BB * CC * NN];
__device__ __align__(128) f16 gwq[OC3 * CC];
__device__ __align__(128) f16 gwp[CC * CC];
__device__ __align__(128) f16 gqkv[(size_t)BB * OC3 * NN];   // Q rows pre-scaled by Q2SCALE
__device__ __align__(128) f16 gatt[(size_t)BB * CC * NN];

// ---------------------------------------------------------------------------
// Fused prepass: f32 -> f16 for x, w_qkv, w_proj in one launch.
// ---------------------------------------------------------------------------
#define N4X (BB * CC * NN / 4)
#define N4Q (OC3 * CC / 4)
#define N4P (CC * CC / 4)

__global__ __launch_bounds__(256) void split_all_kernel(const float* __restrict__ x,
                                                        const float* __restrict__ wq,
                                                        const float* __restrict__ wp) {
    int i = blockIdx.x * blockDim.x + threadIdx.x;
    const float* src;
    f16* hi;
    int j;
    if (i < N4X)                  { src = x;  hi = gx;  j = i; }
    else if (i < N4X + N4Q)       { src = wq; hi = gwq; j = i - N4X; }
    else if (i < N4X + N4Q + N4P) { src = wp; hi = gwp; j = i - N4X - N4Q; }
    else return;
    float4 v = reinterpret_cast<const float4*>(src)[j];
    reinterpret_cast<uint2*>(hi)[j] =
        make_uint2(cvtf16x2(v.y, v.x), cvtf16x2(v.w, v.z));
}

// ---------------------------------------------------------------------------
// GEMM mainloop: 3-stage cp.async, K-chunks of 32, plain fp16 operands.
// ---------------------------------------------------------------------------
template<int KDIM>
__device__ __forceinline__ void gemm_main(const f16* __restrict__ Ah,
                                          const f16* __restrict__ Bh,
                                          size_t ldb, int m0, char* smem,
                                          float (&acc)[2][8][4]) {
    const u32 sb = smem_u32(smem);
    const int t = threadIdx.x;
    const int wid = t >> 5, lane = t & 31;
    const int wm = (wid & 3) * 32;
    const int wn = (wid >> 2) * 64;
    constexpr int NCH = KDIM / 32;

#pragma unroll
    for (int i = 0; i < 2; i++)
#pragma unroll
        for (int j = 0; j < 8; j++)
#pragma unroll
            for (int c = 0; c < 4; c++) acc[i][j][c] = 0.f;

    const int am0 = t >> 2,         ak8 = (t & 3) * 8;
    const int am1 = (256 + t) >> 2, bk0 = t >> 4;
    const int bn8 = (t & 15) * 8,   bk1 = (256 + t) >> 4;

    auto fill = [&](int c0, int buf) {
        u32 base = sb + buf * STAGE_SZ;
        cpa16(base + ST_A + a32_off(am0, ak8), Ah + (size_t)(m0 + am0) * KDIM + c0 + ak8);
        cpa16(base + ST_A + a32_off(am1, ak8), Ah + (size_t)(m0 + am1) * KDIM + c0 + ak8);
        cpa16(base + ST_B + b32_off(bk0, bn8), Bh + (size_t)(c0 + bk0) * ldb + bn8);
        cpa16(base + ST_B + b32_off(bk1, bn8), Bh + (size_t)(c0 + bk1) * ldb + bn8);
    };

    fill(0, 0);  CPA_COMMIT();
    fill(32, 1); CPA_COMMIT();

    for (int ch = 0; ch < NCH; ch++) {
        if (ch == NCH - 1) { CPA_WAIT0(); } else { CPA_WAIT1(); }
        __syncthreads();
        if (ch + 2 < NCH) { fill((ch + 2) * 32, (ch + 2) % 3); CPA_COMMIT(); }
        u32 base = sb + (ch % 3) * STAGE_SZ;

#pragma unroll
        for (int ks = 0; ks < 2; ks++) {
            u32 ah[2][4];
#pragma unroll
            for (int i = 0; i < 2; i++) {
                int row = wm + i * 16 + (lane & 15);
                int kc  = ks * 16 + (lane >> 4) * 8;
                u32 ao = row * 64 + ((((kc >> 3) ^ ((row >> 1) & 3)) & 3) << 4);
                ldsm4(ah[i], base + ST_A + ao);
            }
#pragma unroll
            for (int nh = 0; nh < 2; nh++) {
                u32 bh[2][4];
#pragma unroll
                for (int pp = 0; pp < 2; pp++) {
                    int k = ks * 16 + ((lane >> 3) & 1) * 8 + (lane & 7);
                    int nb = wn + nh * 32 + pp * 16 + (lane >> 4) * 8;
                    u32 bo = k * 256 + ((((nb >> 3) ^ (k & 7))) << 4);
                    ldsm4t(bh[pp], base + ST_B + bo);
                }
#pragma unroll
                for (int i = 0; i < 2; i++)
#pragma unroll
                    for (int pp = 0; pp < 2; pp++)
#pragma unroll
                        for (int s = 0; s < 2; s++)
                            mma16816(acc[i][nh * 4 + pp * 2 + s], ah[i], bh[pp] + s * 2);
            }
        }
    }
}

// Kernel 1: qkv GEMM -> f16, Q rows pre-scaled by Q2SCALE
__global__ __launch_bounds__(256, 2) void qkv_gemm_kernel() {
    extern __shared__ char smem[];
    const int b = blockIdx.z;
    const int n0 = blockIdx.x * 128;
    const int m0 = blockIdx.y * 128;
    float acc[2][8][4];
    gemm_main<CC>(gwq, gx + (size_t)b * CC * NN + n0, NN, m0, smem, acc);

    const int t = threadIdx.x, wid = t >> 5, lane = t & 31;
    const int wm = (wid & 3) * 32, wn = (wid >> 2) * 64;
    f16* oh = gqkv + ((size_t)b * OC3 + m0) * NN + n0;
#pragma unroll
    for (int i = 0; i < 2; i++) {
        int r0 = wm + i * 16 + (lane >> 2);
        float s0 = (m0 + r0 < CC) ? Q2SCALE : 1.f;
        float s8 = (m0 + r0 + 8 < CC) ? Q2SCALE : 1.f;
#pragma unroll
        for (int nt = 0; nt < 8; nt++) {
            int n = wn + nt * 8 + (lane & 3) * 2;
            *reinterpret_cast<u32*>(oh + (size_t)r0 * NN + n) =
                cvtf16x2(acc[i][nt][1] * s0, acc[i][nt][0] * s0);
            *reinterpret_cast<u32*>(oh + (size_t)(r0 + 8) * NN + n) =
                cvtf16x2(acc[i][nt][3] * s8, acc[i][nt][2] * s8);
        }
    }
}

// Kernel 3: proj GEMM + bias -> f32 out
__global__ __launch_bounds__(256, 2) void proj_gemm_kernel(const float* __restrict__ bias,
                                                           float* __restrict__ out) {
    extern __shared__ char smem[];
    const int b = blockIdx.z;
    const int n0 = blockIdx.x * 128;
    const int m0 = blockIdx.y * 128;
    float acc[2][8][4];
    gemm_main<CC>(gwp, gatt + (size_t)b * CC * NN + n0, NN, m0, smem, acc);

    const int t = threadIdx.x, wid = t >> 5, lane = t & 31;
    const int wm = (wid & 3) * 32, wn = (wid >> 2) * 64;
    float* outp = out + ((size_t)b * CC + m0) * NN + n0;
#pragma unroll
    for (int i = 0; i < 2; i++) {
        int r0 = wm + i * 16 + (lane >> 2);
        float b0 = bias[m0 + r0], b8 = bias[m0 + r0 + 8];
#pragma unroll
        for (int nt = 0; nt < 8; nt++) {
            int n = wn + nt * 8 + (lane & 3) * 2;
            float* d0 = outp + (size_t)r0 * NN + n;
            *reinterpret_cast<float2*>(d0) =
                make_float2(acc[i][nt][0] + b0, acc[i][nt][1] + b0);
            *reinterpret_cast<float2*>(d0 + 8 * NN) =
                make_float2(acc[i][nt][2] + b8, acc[i][nt][3] + b8);
        }
    }
}

// ---------------------------------------------------------------------------
// Kernel 2: grouped MHA, plain fp16. 128 queries/block, 8 warps.
// P computed via ex2.approx.f16x2 (halved MUFU); row-sum l via ones-MMA.
// dyn smem: Qs 8KB @0 | stages @8192 + s*8192 (K 4KB, V 4KB). Os overlays.
// ---------------------------------------------------------------------------
#define AK 0
#define AV 4096
#define ASTG 8192
#define SMEM_ATT (8192 + 3 * ASTG)      // 32768

__global__ __launch_bounds__(256) void attn_kernel() {
    extern __shared__ char sm[];
    char* Qs = sm;
    float* Os = reinterpret_cast<float*>(sm + 8192);
    const u32 sb = smem_u32(sm);

    const int t = threadIdx.x, lane = t & 31, wid = t >> 5;
    const int head = blockIdx.y;
    const int b = head >> 6, g = (head >> 3) & 7, hh = head & 7;
    const int nqbase = g * MSEQ + blockIdx.x * 128;
    const size_t qoff = ((size_t)b * OC3 + hh * HD) * NN;
    const f16* qp = gqkv + qoff;
    const f16* kp = qp + (size_t)CC * NN;
    const f16* vp = qp + (size_t)(2 * CC) * NN;

    // K/V fill: 256 threads, 1 16B chunk per tile per thread
    const int fd = t >> 3, fk8 = (t & 7) * 8;
    const u32 fo = fd * 128 + ((((fk8 >> 3) ^ (fd & 7))) << 4);

    auto fill_kv = [&](int kt, int buf) {
        const int nk = g * MSEQ + kt * 64;
        u32 base = sb + 8192 + buf * ASTG;
        size_t s = (size_t)fd * NN + nk + fk8;
        cpa16(base + AK + fo, kp + s);
        cpa16(base + AV + fo, vp + s);
    };

    fill_kv(0, 0); CPA_COMMIT();
    fill_kv(1, 1); CPA_COMMIT();

    // ---- Q fill: transpose [d][n] -> smem [q][d] (64B rows, 4-chunk swizzle)
    {
        int q = t & 127, dh = (t >> 7) * 16;
        const f16* ph = qp + nqbase + q;
#pragma unroll
        for (int dd = 0; dd < 16; dd += 2) {
            int d = dh + dd;
            u32 off = q * 64 + ((((d >> 3) ^ ((q >> 1) & 3)) & 3) << 4) + (d & 7) * 2;
            st_h2(Qs, off, ph[(size_t)d * NN], ph[(size_t)(d + 1) * NN]);
        }
    }
    __syncthreads();

    u32 qh[2][4];
    {
        int row = wid * 16 + (lane & 15);
#pragma unroll
        for (int ks = 0; ks < 2; ks++) {
            int kc = ks * 16 + (lane >> 4) * 8;
            u32 ao = row * 64 + ((((kc >> 3) ^ ((row >> 1) & 3)) & 3) << 4);
            ldsm4(qh[ks], sb + ao);
        }
    }

    float oacc[4][4];
    float oaccl[4];                       // l accumulator (ones-MMA)
#pragma unroll
    for (int i = 0; i < 4; i++) {
        oaccl[i] = 0.f;
#pragma unroll
        for (int j = 0; j < 4; j++) oacc[i][j] = 0.f;
    }
    const u32 ones2[2] = {0x3C003C00u, 0x3C003C00u};   // f16x2 {1,1}
    float mx0 = -1e30f, mx1 = -1e30f;

    for (int kt = 0; kt < 8; kt++) {
        if (kt == 7) { CPA_WAIT0(); } else { CPA_WAIT1(); }
        __syncthreads();
        if (kt + 2 < 8) { fill_kv(kt + 2, (kt + 2) % 3); CPA_COMMIT(); }
        u32 base = sb + 8192 + (kt % 3) * ASTG;

        // ---- S = Q K^T (log2-domain; Q pre-scaled)
        float sacc[8][4];
#pragma unroll
        for (int i = 0; i < 8; i++)
#pragma unroll
            for (int j = 0; j < 4; j++) sacc[i][j] = 0.f;
#pragma unroll
        for (int ks = 0; ks < 2; ks++) {
            int kd = ks * 16 + ((lane >> 3) & 1) * 8 + (lane & 7);
            u32 krb = kd * 128;
#pragma unroll
            for (int pp = 0; pp < 4; pp++) {
                int nb = pp * 16 + (lane >> 4) * 8;
                u32 off = krb + ((((nb >> 3) ^ (kd & 7))) << 4);
                u32 kbh[4];
                ldsm4t(kbh, base + AK + off);
#pragma unroll
                for (int s = 0; s < 2; s++)
                    mma16816(sacc[pp * 2 + s], qh[ks], kbh + s * 2);
            }
        }

        // ---- online softmax (base-2), P in f16x2 via ex2.approx.f16x2
        float rm0 = -1e30f, rm1 = -1e30f;
#pragma unroll
        for (int j = 0; j < 8; j++) {
            rm0 = fmaxf(rm0, fmaxf(sacc[j][0], sacc[j][1]));
            rm1 = fmaxf(rm1, fmaxf(sacc[j][2], sacc[j][3]));
        }
        rm0 = fmaxf(rm0, __shfl_xor_sync(0xffffffffu, rm0, 1));
        rm0 = fmaxf(rm0, __shfl_xor_sync(0xffffffffu, rm0, 2));
        rm1 = fmaxf(rm1, __shfl_xor_sync(0xffffffffu, rm1, 1));
        rm1 = fmaxf(rm1, __shfl_xor_sync(0xffffffffu, rm1, 2));
        float nm0 = fmaxf(mx0, rm0), nm1 = fmaxf(mx1, rm1);
        float c0 = ex2f(mx0 - nm0), c1 = ex2f(mx1 - nm1);
        mx0 = nm0; mx1 = nm1;
#pragma unroll
        for (int df = 0; df < 4; df++) {
            oacc[df][0] *= c0; oacc[df][1] *= c0;
            oacc[df][2] *= c1; oacc[df][3] *= c1;
        }
        oaccl[0] *= c0; oaccl[1] *= c0;
        oaccl[2] *= c1; oaccl[3] *= c1;

        u32 aph[4][4];
#pragma unroll
        for (int j = 0; j < 8; j++) {
            int ks = j >> 1, half = (j & 1) * 2;
            aph[ks][half] =
                ex2h2(cvtf16x2(sacc[j][1] - nm0, sacc[j][0] - nm0));
            aph[ks][half + 1] =
                ex2h2(cvtf16x2(sacc[j][3] - nm1, sacc[j][2] - nm1));
        }

        // ---- row-sum l via ones-MMA (replaces scalar sum + shfl)
#pragma unroll
        for (int ks = 0; ks < 4; ks++)
            mma16816(oaccl, aph[ks], ones2);

        // ---- O += P V  (V in [d][key], NON-trans ldsm)
#pragma unroll
        for (int ks = 0; ks < 4; ks++) {
            int kk = ks * 16 + ((lane >> 3) & 1) * 8;
#pragma unroll
            for (int dg = 0; dg < 2; dg++) {
                int dn = dg * 16 + (lane >> 4) * 8 + (lane & 7);
                u32 off = dn * 128 + ((((kk >> 3) ^ (dn & 7))) << 4);
                u32 vbh[4];
                ldsm4(vbh, base + AV + off);
#pragma unroll
                for (int s = 0; s < 2; s++)
                    mma16816(oacc[dg * 2 + s], aph[ks], vbh + s * 2);
            }
        }
    }

    // ---- epilogue: normalize (l from ones-MMA accumulator), stage, store f16
    float inv0 = 1.f / oaccl[0], inv1 = 1.f / oaccl[2];
    __syncthreads();
    {
        int r = wid * 16 + (lane >> 2);
#pragma unroll
        for (int df = 0; df < 4; df++) {
            int dc = df * 8 + (lane & 3) * 2;
            *reinterpret_cast<float2*>(&Os[r * 34 + dc]) =
                make_float2(oacc[df][0] * inv0, oacc[df][1] * inv0);
            *reinterpret_cast<float2*>(&Os[(r + 8) * 34 + dc]) =
                make_float2(oacc[df][2] * inv1, oacc[df][3] * inv1);
        }
    }
    __syncthreads();
    {
        int d = t >> 3, qg = (t & 7) * 16;
        f16* dh_ = gatt + ((size_t)b * CC + hh * HD + d) * NN + nqbase + qg;
#pragma unroll
        for (int qq = 0; qq < 16; qq += 2) {
            *reinterpret_cast<u32*>(dh_ + qq) =
                cvtf16x2(Os[(qg + qq + 1) * 34 + d], Os[(qg + qq) * 34 + d]);
        }
    }
}

// ---------------------------------------------------------------------------
extern "C" void kernel_launch(void* const* d_in, const int* in_sizes, int n_in,
                              void* d_out, int out_size) {
    const float* x      = (const float*)d_in[0];
    const float* w_qkv  = (const float*)d_in[1];
    const float* w_proj = (const float*)d_in[2];
    const float* b_proj = (const float*)d_in[3];
    float* out = (float*)d_out;

    cudaFuncSetAttribute(qkv_gemm_kernel, cudaFuncAttributeMaxDynamicSharedMemorySize, SMEM_GEMM);
    cudaFuncSetAttribute(proj_gemm_kernel, cudaFuncAttributeMaxDynamicSharedMemorySize, SMEM_GEMM);
    cudaFuncSetAttribute(attn_kernel, cudaFuncAttributeMaxDynamicSharedMemorySize, SMEM_ATT);

    split_all_kernel<<<(N4X + N4Q + N4P + 255) / 256, 256>>>(x, w_qkv, w_proj);

    dim3 g1(NN / 128, OC3 / 128, BB);
    qkv_gemm_kernel<<<g1, 256, SMEM_GEMM>>>();

    dim3 g2(MSEQ / 128, BB * GG * NH);
    attn_kernel<<<g2, 256, SMEM_ATT>>>();

    dim3 g3(NN / 128, CC / 128, BB);
    proj_gemm_kernel<<<g3, 256, SMEM_GEMM>>>(b_proj, out);
}